// round 6
// baseline (speedup 1.0000x reference)
#include <cuda_runtime.h>
#include <math.h>
#include <stdint.h>

#define B_    4
#define L_    2048
#define DM    2048
#define DI    4096
#define DST   64
#define HN    64
#define HP    64
#define CONVD 4224
#define DIP   8448
#define BL    (B_*L_)          // 8192
#define NCLS  4

// ---------------- scratch (static device globals; no allocation) ----------------
__device__ float g_zx[BL * DIP];
__device__ float g_xh[BL * DI];
__device__ float g_Bm[BL * DST];
__device__ float g_Cm[BL * DST];
__device__ float g_dt[BL * HN];
__device__ float g_dA[BL * HN];
__device__ float g_y [BL * DI];
__device__ float g_oh[BL * DM];

// ---------------- helpers ----------------
__device__ __forceinline__ uint32_t smem_u32(const void* p) {
    uint32_t a;
    asm("{ .reg .u64 t; cvta.to.shared.u64 t, %1; cvt.u32.u64 %0, t; }" : "=r"(a) : "l"(p));
    return a;
}
__device__ __forceinline__ void cp16(uint32_t saddr, const void* gptr) {
    asm volatile("cp.async.ca.shared.global [%0], [%1], 16;" :: "r"(saddr), "l"(gptr) : "memory");
}
__device__ __forceinline__ void cp_commit() {
    asm volatile("cp.async.commit_group;" ::: "memory");
}
__device__ __forceinline__ void cp_wait2() {
    asm volatile("cp.async.wait_group 2;" ::: "memory");
}
// pack two fp32 (k, k+1) into f16x2: lo = v.x (k), hi = v.y (k+1)
__device__ __forceinline__ unsigned packh2(float2 v) {
    unsigned r;
    asm("cvt.rn.f16x2.f32 %0, %1, %2;" : "=r"(r) : "f"(v.y), "f"(v.x));
    return r;
}
__device__ __forceinline__ void mma_f16(float c[4], const unsigned a[4], const unsigned b[2]) {
    asm volatile(
        "mma.sync.aligned.m16n8k16.row.col.f32.f16.f16.f32 "
        "{%0,%1,%2,%3}, {%4,%5,%6,%7}, {%8,%9}, {%0,%1,%2,%3};"
        : "+f"(c[0]), "+f"(c[1]), "+f"(c[2]), "+f"(c[3])
        : "r"(a[0]), "r"(a[1]), "r"(a[2]), "r"(a[3]),
          "r"(b[0]), "r"(b[1]));
}

// smem: 4 stages x (A[128][20] + B[128][20]) fp32; row stride 20 floats = 80 B
#define ROWSTR   20
#define STAGE_A_BYTES (128 * 80)            // 10240
#define STAGE_BYTES   (2 * STAGE_A_BYTES)   // 20480
#define NSTAGE   4
#define SMEM_BYTES (NSTAGE * STAGE_BYTES)   // 81920

// ---------------- FP16 mma.sync GEMM (fp32 in/out/accum), cp.async 4-stage ----------------
// C[M,N] = A[M,K] * W[N,K]^T. 128x128 tile, BK=16, 256 threads (8 warps 2x4),
// warp tile 64x32 via m16n8k16 (one MMA covers the full BK=16).
__global__ __launch_bounds__(256, 2)
void gemm_f16_ca(const float* __restrict__ A, const float* __restrict__ W,
                 float* __restrict__ C, int M, int N, int K)
{
    extern __shared__ __align__(16) char smem[];
    const uint32_t sb = smem_u32(smem);
    const float* Sf = (const float*)smem;

    const int tid  = threadIdx.x;
    const int warp = tid >> 5;
    const int lane = tid & 31;
    const int wm = warp & 1;
    const int wn = warp >> 1;
    const int g  = lane >> 2;
    const int t  = lane & 3;
    const int bm = blockIdx.y << 7;
    const int bn = blockIdx.x << 7;

    // producer mapping: thread handles rows r0, r0+64 at 16B chunk k4, for A and B
    const int r0 = tid >> 2;          // 0..63
    const int k4 = tid & 3;           // 16B chunk within BK=16 row

    const float* Ag0 = A + (size_t)(bm + r0) * K + k4 * 4;
    const float* Wg0 = W + (size_t)(bn + r0) * K + k4 * 4;
    const size_t rows64 = (size_t)64 * K;
    const uint32_t sA0 = sb + (uint32_t)(r0 * 80 + k4 * 16);

    float acc[4][4][4];
    #pragma unroll
    for (int i = 0; i < 4; i++)
        #pragma unroll
        for (int j = 0; j < 4; j++)
            #pragma unroll
            for (int c = 0; c < 4; c++) acc[i][j][c] = 0.f;

    const int KT = K >> 4;

    auto issue_stage = [&](int kt, int s) {
        const float* Ag = Ag0 + kt * 16;
        const float* Wg = Wg0 + kt * 16;
        const uint32_t sA = sA0 + s * STAGE_BYTES;
        const uint32_t sB = sA + STAGE_A_BYTES;
        cp16(sA,            Ag);
        cp16(sA + 64 * 80,  Ag + rows64);
        cp16(sB,            Wg);
        cp16(sB + 64 * 80,  Wg + rows64);
    };

    issue_stage(0, 0); cp_commit();
    issue_stage(1, 1); cp_commit();
    issue_stage(2, 2); cp_commit();
    cp_wait2();
    __syncthreads();

    const int k0 = 2 * t;             // fragment k base (0,2,4,6)

    for (int kt = 0; kt < KT; kt++) {
        const int s = kt & 3;
        const float* Af = Sf + s * (STAGE_BYTES / 4);
        const float* Bf = Af + (STAGE_A_BYTES / 4);

        unsigned a[4][4], b[4][2];
        #pragma unroll
        for (int mt = 0; mt < 4; mt++) {
            const int r = wm * 64 + mt * 16 + g;
            a[mt][0] = packh2(*(const float2*)&Af[r * ROWSTR + k0]);
            a[mt][1] = packh2(*(const float2*)&Af[(r + 8) * ROWSTR + k0]);
            a[mt][2] = packh2(*(const float2*)&Af[r * ROWSTR + k0 + 8]);
            a[mt][3] = packh2(*(const float2*)&Af[(r + 8) * ROWSTR + k0 + 8]);
        }
        #pragma unroll
        for (int nt = 0; nt < 4; nt++) {
            const int c = wn * 32 + nt * 8 + g;
            b[nt][0] = packh2(*(const float2*)&Bf[c * ROWSTR + k0]);
            b[nt][1] = packh2(*(const float2*)&Bf[c * ROWSTR + k0 + 8]);
        }
        #pragma unroll
        for (int mt = 0; mt < 4; mt++)
            #pragma unroll
            for (int nt = 0; nt < 4; nt++)
                mma_f16(acc[mt][nt], a[mt], b[nt]);

        if (kt + 3 < KT) issue_stage(kt + 3, (kt + 3) & 3);
        cp_commit();
        if (kt + 1 < KT) {
            cp_wait2();
            __syncthreads();
        }
    }

    #pragma unroll
    for (int mt = 0; mt < 4; mt++) {
        #pragma unroll
        for (int nt = 0; nt < 4; nt++) {
            const int rr = bm + wm * 64 + mt * 16 + g;
            const int c0 = bn + wn * 32 + nt * 8 + 2 * t;
            *(float2*)&C[(size_t)rr * N + c0]       = make_float2(acc[mt][nt][0], acc[mt][nt][1]);
            *(float2*)&C[(size_t)(rr + 8) * N + c0] = make_float2(acc[mt][nt][2], acc[mt][nt][3]);
        }
    }
}

// ---------------- exact fp32 dt path: dt_raw = x . W_dt^T, then softplus/exp ----------------
__global__ __launch_bounds__(256)
void dt_exact_kernel(const float* __restrict__ x, const float* __restrict__ in_proj_w,
                     const float* __restrict__ dt_bias, const float* __restrict__ A_log)
{
    __shared__ float As[16][132];
    __shared__ float Ws[16][68];
    const int tid = threadIdx.x;
    const int bt0 = blockIdx.x << 7;
    const int tm = tid >> 3;
    const int tn = tid & 7;
    const float* Wdt = in_proj_w + (size_t)(DI + CONVD) * DM;

    float acc[4][8];
    #pragma unroll
    for (int i = 0; i < 4; i++)
        #pragma unroll
        for (int j = 0; j < 8; j++) acc[i][j] = 0.f;

    for (int k0 = 0; k0 < DM; k0 += 16) {
        #pragma unroll
        for (int i = 0; i < 2; i++) {
            const int lin = tid + (i << 8);
            const int r = lin >> 2;
            const int kk = (lin & 3) << 2;
            float4 v = *(const float4*)(x + (size_t)(bt0 + r) * DM + k0 + kk);
            As[kk + 0][r] = v.x; As[kk + 1][r] = v.y;
            As[kk + 2][r] = v.z; As[kk + 3][r] = v.w;
        }
        {
            const int r = tid >> 2;
            const int kk = (tid & 3) << 2;
            float4 w = *(const float4*)(Wdt + (size_t)r * DM + k0 + kk);
            Ws[kk + 0][r] = w.x; Ws[kk + 1][r] = w.y;
            Ws[kk + 2][r] = w.z; Ws[kk + 3][r] = w.w;
        }
        __syncthreads();
        #pragma unroll
        for (int k = 0; k < 16; k++) {
            float a[4], b[8];
            #pragma unroll
            for (int i = 0; i < 4; i++) a[i] = As[k][tm + i * 32];
            #pragma unroll
            for (int j = 0; j < 8; j++) b[j] = Ws[k][tn + j * 8];
            #pragma unroll
            for (int i = 0; i < 4; i++)
                #pragma unroll
                for (int j = 0; j < 8; j++)
                    acc[i][j] = fmaf(a[i], b[j], acc[i][j]);
        }
        __syncthreads();
    }
    #pragma unroll
    for (int i = 0; i < 4; i++) {
        #pragma unroll
        for (int j = 0; j < 8; j++) {
            const int bt = bt0 + tm + i * 32;
            const int h  = tn + j * 8;
            float dtr = acc[i][j] + __ldg(dt_bias + h);
            float dts = (dtr > 20.f) ? dtr : log1pf(expf(dtr));
            g_dt[bt * HN + h] = dts;
            g_dA[bt * HN + h] = expf(-expf(__ldg(A_log + h)) * dts);
        }
    }
}

// ---------------- conv1d(depthwise, width 4) + SiLU ----------------
__global__ void conv_prep_kernel(const float* __restrict__ conv_w,
                                 const float* __restrict__ conv_b)
{
    const int bt = blockIdx.x;
    const int b  = bt / L_;
    const int t  = bt % L_;

    for (int c = threadIdx.x; c < CONVD; c += blockDim.x) {
        float4 wv = *(const float4*)(conv_w + c * 4);
        float s = conv_b[c];
        const float wk[4] = {wv.x, wv.y, wv.z, wv.w};
        #pragma unroll
        for (int k = 0; k < 4; k++) {
            int tt = t - 3 + k;
            float xv = (tt >= 0) ? g_zx[(size_t)(b * L_ + tt) * DIP + DI + c] : 0.f;
            s = fmaf(xv, wk[k], s);
        }
        float sil = s / (1.f + expf(-s));
        if (c < DI)            g_xh[(size_t)bt * DI + c]       = sil;
        else if (c < DI + DST) g_Bm[bt * DST + (c - DI)]        = sil;
        else                   g_Cm[bt * DST + (c - DI - DST)]  = sil;
    }
}

// ---------------- sequential selective scan + D*x + silu(z) gating ----------------
__global__ __launch_bounds__(64)
void scan_kernel(const float* __restrict__ Dp)
{
    const int b = blockIdx.x >> 6;
    const int h = blockIdx.x & 63;
    const int p = threadIdx.x;
    const float Dh = __ldg(Dp + h);

    float hs[DST];
    #pragma unroll
    for (int n = 0; n < DST; n++) hs[n] = 0.f;

    for (int t = 0; t < L_; t++) {
        const int bt = b * L_ + t;
        const float dA = __ldg(&g_dA[bt * HN + h]);
        const float dt = __ldg(&g_dt[bt * HN + h]);
        const float xv = g_xh[(size_t)bt * DI + h * HP + p];
        const float u  = dt * xv;
        const float4* Bv = (const float4*)(g_Bm + bt * DST);
        const float4* Cv = (const float4*)(g_Cm + bt * DST);
        float ac0 = 0.f, ac1 = 0.f, ac2 = 0.f, ac3 = 0.f;   // 4 chains: break serial dep
        #pragma unroll
        for (int j = 0; j < 16; j++) {
            float4 Bq = __ldg(&Bv[j]);
            float4 Cq = __ldg(&Cv[j]);
            hs[4*j+0] = fmaf(hs[4*j+0], dA, u * Bq.x); ac0 = fmaf(hs[4*j+0], Cq.x, ac0);
            hs[4*j+1] = fmaf(hs[4*j+1], dA, u * Bq.y); ac1 = fmaf(hs[4*j+1], Cq.y, ac1);
            hs[4*j+2] = fmaf(hs[4*j+2], dA, u * Bq.z); ac2 = fmaf(hs[4*j+2], Cq.z, ac2);
            hs[4*j+3] = fmaf(hs[4*j+3], dA, u * Bq.w); ac3 = fmaf(hs[4*j+3], Cq.w, ac3);
        }
        const float acc = (ac0 + ac1) + (ac2 + ac3);
        const float z = g_zx[(size_t)bt * DIP + h * HP + p];
        const float gate = z / (1.f + expf(-z));
        g_y[(size_t)bt * DI + h * HP + p] = (acc + Dh * xv) * gate;
    }
}

// ---------------- RMS norm over D_INNER, in place ----------------
__global__ __launch_bounds__(256)
void rmsnorm_kernel(const float* __restrict__ norm_w)
{
    const int bt = blockIdx.x;
    float* row = g_y + (size_t)bt * DI;
    float v[16];
    float ss = 0.f;
    #pragma unroll
    for (int i = 0; i < 16; i++) {
        v[i] = row[threadIdx.x + i * 256];
        ss = fmaf(v[i], v[i], ss);
    }
    #pragma unroll
    for (int o = 16; o > 0; o >>= 1) ss += __shfl_xor_sync(0xffffffffu, ss, o);
    __shared__ float sred[8];
    const int lane = threadIdx.x & 31, warp = threadIdx.x >> 5;
    if (lane == 0) sred[warp] = ss;
    __syncthreads();
    float tot = 0.f;
    #pragma unroll
    for (int w = 0; w < 8; w++) tot += sred[w];
    const float scale = rsqrtf(tot * (1.f / DI) + 1e-5f);
    #pragma unroll
    for (int i = 0; i < 16; i++)
        row[threadIdx.x + i * 256] = v[i] * scale * norm_w[threadIdx.x + i * 256];
}

// ---------------- classifier head ----------------
__global__ __launch_bounds__(256)
void cls_kernel(const float* __restrict__ cls_w, const float* __restrict__ cls_b,
                float* __restrict__ out)
{
    const int bt = blockIdx.x;
    const float* row = g_oh + (size_t)bt * DM;
    float a0 = 0.f, a1 = 0.f, a2 = 0.f, a3 = 0.f;
    for (int k = threadIdx.x; k < DM; k += 256) {
        float xv = row[k];
        a0 = fmaf(xv, __ldg(cls_w + k),          a0);
        a1 = fmaf(xv, __ldg(cls_w + DM + k),     a1);
        a2 = fmaf(xv, __ldg(cls_w + 2 * DM + k), a2);
        a3 = fmaf(xv, __ldg(cls_w + 3 * DM + k), a3);
    }
    #pragma unroll
    for (int o = 16; o > 0; o >>= 1) {
        a0 += __shfl_xor_sync(0xffffffffu, a0, o);
        a1 += __shfl_xor_sync(0xffffffffu, a1, o);
        a2 += __shfl_xor_sync(0xffffffffu, a2, o);
        a3 += __shfl_xor_sync(0xffffffffu, a3, o);
    }
    __shared__ float sred[8][4];
    const int lane = threadIdx.x & 31, warp = threadIdx.x >> 5;
    if (lane == 0) { sred[warp][0] = a0; sred[warp][1] = a1; sred[warp][2] = a2; sred[warp][3] = a3; }
    __syncthreads();
    if (threadIdx.x < 4) {
        float s = cls_b[threadIdx.x];
        #pragma unroll
        for (int w = 0; w < 8; w++) s += sred[w][threadIdx.x];
        out[bt * NCLS + threadIdx.x] = s;
    }
}

// ---------------- launcher ----------------
extern "C" void kernel_launch(void* const* d_in, const int* in_sizes, int n_in,
                              void* d_out, int out_size)
{
    (void)in_sizes; (void)n_in; (void)out_size;
    const float* x          = (const float*)d_in[0];
    const float* in_proj_w  = (const float*)d_in[1];
    const float* conv_w     = (const float*)d_in[2];
    const float* conv_b     = (const float*)d_in[3];
    const float* dt_bias    = (const float*)d_in[4];
    const float* A_log      = (const float*)d_in[5];
    const float* Dp         = (const float*)d_in[6];
    const float* norm_w     = (const float*)d_in[7];
    const float* out_proj_w = (const float*)d_in[8];
    const float* cls_w      = (const float*)d_in[9];
    const float* cls_b      = (const float*)d_in[10];
    float* out = (float*)d_out;

    float *zx, *y, *oh;
    cudaGetSymbolAddress((void**)&zx, g_zx);
    cudaGetSymbolAddress((void**)&y,  g_y);
    cudaGetSymbolAddress((void**)&oh, g_oh);

    cudaFuncSetAttribute(gemm_f16_ca, cudaFuncAttributeMaxDynamicSharedMemorySize, SMEM_BYTES);

    // 1) in_proj GEMM (fp16 mma.sync, fp32 accum): (8192,2048) x (8448,2048)^T
    {
        dim3 grid(DIP / 128, BL / 128);
        gemm_f16_ca<<<grid, 256, SMEM_BYTES>>>(x, in_proj_w, zx, BL, DIP, DM);
    }
    // 2) exact fp32 dt path
    dt_exact_kernel<<<BL / 128, 256>>>(x, in_proj_w, dt_bias, A_log);
    // 3) conv + silu
    conv_prep_kernel<<<BL, 256>>>(conv_w, conv_b);
    // 4) selective scan (+ D*x, silu(z) gate)
    scan_kernel<<<B_ * HN, 64>>>(Dp);
    // 5) RMS norm in place
    rmsnorm_kernel<<<BL, 256>>>(norm_w);
    // 6) out_proj GEMM: (8192,4096) x (2048,4096)^T
    {
        dim3 grid(DM / 128, BL / 128);
        gemm_f16_ca<<<grid, 256, SMEM_BYTES>>>(y, out_proj_w, oh, BL, DM, DI);
    }
    // 7) classifier head
    cls_kernel<<<BL, 256>>>(cls_w, cls_b, out);
}

// round 7
// speedup vs baseline: 1.2353x; 1.2353x over previous
#include <cuda_runtime.h>
#include <cuda_fp16.h>
#include <math.h>
#include <stdint.h>

#define B_    4
#define L_    2048
#define DM    2048
#define DI    4096
#define DST   64
#define HN    64
#define HP    64
#define CONVD 4224
#define DIP   8448
#define BL    (B_*L_)          // 8192
#define NCLS  4

// ---------------- scratch (static device globals; no allocation) ----------------
__device__ float  g_zx[BL * DIP];
__device__ float  g_xh[BL * DI];
__device__ float  g_Bm[BL * DST];
__device__ float  g_Cm[BL * DST];
__device__ float  g_dt[BL * HN];
__device__ float  g_dA[BL * HN];
__device__ float  g_y [BL * DI];
__device__ float  g_oh[BL * DM];
__device__ __half g_x16 [BL * DM];      // half(x)
__device__ __half g_w1h [DIP * DM];     // half(in_proj_w)
__device__ __half g_w2h [DM * DI];      // half(out_proj_w)
__device__ __half g_y16 [BL * DI];      // half(normed y)

// ---------------- helpers ----------------
__device__ __forceinline__ uint32_t smem_u32(const void* p) {
    uint32_t a;
    asm("{ .reg .u64 t; cvta.to.shared.u64 t, %1; cvt.u32.u64 %0, t; }" : "=r"(a) : "l"(p));
    return a;
}
__device__ __forceinline__ void cp16(uint32_t saddr, const void* gptr) {
    asm volatile("cp.async.ca.shared.global [%0], [%1], 16;" :: "r"(saddr), "l"(gptr) : "memory");
}
__device__ __forceinline__ void cp_commit() {
    asm volatile("cp.async.commit_group;" ::: "memory");
}
__device__ __forceinline__ void cp_wait2() {
    asm volatile("cp.async.wait_group 2;" ::: "memory");
}
__device__ __forceinline__ void ldsm4(unsigned& r0, unsigned& r1, unsigned& r2, unsigned& r3,
                                      uint32_t addr) {
    asm volatile("ldmatrix.sync.aligned.m8n8.x4.shared.b16 {%0,%1,%2,%3}, [%4];"
                 : "=r"(r0), "=r"(r1), "=r"(r2), "=r"(r3) : "r"(addr));
}
__device__ __forceinline__ void mma_f16(float c[4], const unsigned a[4], const unsigned b[2]) {
    asm volatile(
        "mma.sync.aligned.m16n8k16.row.col.f32.f16.f16.f32 "
        "{%0,%1,%2,%3}, {%4,%5,%6,%7}, {%8,%9}, {%0,%1,%2,%3};"
        : "+f"(c[0]), "+f"(c[1]), "+f"(c[2]), "+f"(c[3])
        : "r"(a[0]), "r"(a[1]), "r"(a[2]), "r"(a[3]),
          "r"(b[0]), "r"(b[1]));
}

// smem: 4 stages x (A[128 rows][32 halfs] + B[128][32]) = 4 x 16384 B
#define STAGE_BYTES 16384
#define SMEM_BYTES  (4 * STAGE_BYTES)   // 65536

// ---------------- FP16-operand GEMM (fp32 accum/out), ldmatrix + cp.async 4-stage ----
// C[M,N] = A[M,K] * W[N,K]^T, A/W half row-major (K contiguous).
// 128x128 tile, BK=32, 256 threads (8 warps 2x4), warp tile 64x32 via m16n8k16.
// smem chunk swizzle: (row, k8chunk) -> row*64 + ((k8 ^ ((row>>1)&3))<<4). Conflict-free LDSM.
__global__ __launch_bounds__(256, 2)
void gemm_h(const __half* __restrict__ A, const __half* __restrict__ W,
            float* __restrict__ C, int M, int N, int K)
{
    extern __shared__ __align__(16) char smem[];
    const uint32_t sb = smem_u32(smem);

    const int tid  = threadIdx.x;
    const int warp = tid >> 5;
    const int lane = tid & 31;
    const int wm = warp & 1;
    const int wn = warp >> 1;
    const int g  = lane >> 2;
    const int t  = lane & 3;
    const int bm = blockIdx.y << 7;
    const int bn = blockIdx.x << 7;

    // producer: thread handles chunks c0, c0+1 (of 512) for both A and B
    uint32_t pOff[2];
    const __half* AgP[2];
    const __half* WgP[2];
    #pragma unroll
    for (int j = 0; j < 2; j++) {
        const int c   = tid * 2 + j;
        const int pr  = c >> 2;           // row 0..127
        const int pk8 = c & 3;            // 16B chunk in row
        pOff[j] = (uint32_t)(pr * 64 + ((pk8 ^ ((pr >> 1) & 3)) << 4));
        AgP[j] = A + (size_t)(bm + pr) * K + pk8 * 8;
        WgP[j] = W + (size_t)(bn + pr) * K + pk8 * 8;
    }

    // consumer ldmatrix static offsets
    uint32_t offA[4], swA[4];
    #pragma unroll
    for (int mt = 0; mt < 4; mt++) {
        const int r = wm * 64 + mt * 16 + (lane & 7) + ((lane >> 3) & 1) * 8;
        offA[mt] = (uint32_t)(r * 64);
        swA[mt]  = (uint32_t)((r >> 1) & 3);
    }
    uint32_t offB[2], swB[2], cB;
    #pragma unroll
    for (int h = 0; h < 2; h++) {
        const int r = wn * 32 + h * 16 + (lane & 7) + ((lane >> 4) & 1) * 8;
        offB[h] = (uint32_t)(r * 64);
        swB[h]  = (uint32_t)((r >> 1) & 3);
    }
    cB = (uint32_t)((lane >> 3) & 1);     // chunk low bit for B
    const uint32_t cA = (uint32_t)(lane >> 4);  // chunk low bit for A

    float acc[4][4][4];
    #pragma unroll
    for (int i = 0; i < 4; i++)
        #pragma unroll
        for (int j = 0; j < 4; j++)
            #pragma unroll
            for (int c = 0; c < 4; c++) acc[i][j][c] = 0.f;

    const int KT = K >> 5;

    auto issue_stage = [&](int kt, int s) {
        const uint32_t sA = sb + s * STAGE_BYTES;
        #pragma unroll
        for (int j = 0; j < 2; j++) {
            cp16(sA + pOff[j],        AgP[j] + kt * 32);
            cp16(sA + 8192 + pOff[j], WgP[j] + kt * 32);
        }
    };

    issue_stage(0, 0); cp_commit();
    issue_stage(1, 1); cp_commit();
    issue_stage(2, 2); cp_commit();
    cp_wait2();
    __syncthreads();

    for (int kt = 0; kt < KT; kt++) {
        const int s = kt & 3;
        const uint32_t sA = sb + s * STAGE_BYTES;
        const uint32_t sBq = sA + 8192;

        #pragma unroll
        for (int kk = 0; kk < 2; kk++) {
            unsigned a[4][4], b[4][2];
            #pragma unroll
            for (int mt = 0; mt < 4; mt++) {
                const uint32_t ch = (uint32_t)(2 * kk) + cA;
                ldsm4(a[mt][0], a[mt][1], a[mt][2], a[mt][3],
                      sA + offA[mt] + ((ch ^ swA[mt]) << 4));
            }
            #pragma unroll
            for (int h = 0; h < 2; h++) {
                const uint32_t ch = (uint32_t)(2 * kk) + cB;
                ldsm4(b[2*h][0], b[2*h][1], b[2*h+1][0], b[2*h+1][1],
                      sBq + offB[h] + ((ch ^ swB[h]) << 4));
            }
            #pragma unroll
            for (int mt = 0; mt < 4; mt++)
                #pragma unroll
                for (int nt = 0; nt < 4; nt++)
                    mma_f16(acc[mt][nt], a[mt], b[nt]);
        }

        if (kt + 3 < KT) issue_stage(kt + 3, (kt + 3) & 3);
        cp_commit();
        if (kt + 1 < KT) {
            cp_wait2();
            __syncthreads();
        }
    }

    #pragma unroll
    for (int mt = 0; mt < 4; mt++) {
        #pragma unroll
        for (int nt = 0; nt < 4; nt++) {
            const int rr = bm + wm * 64 + mt * 16 + g;
            const int c0 = bn + wn * 32 + nt * 8 + 2 * t;
            *(float2*)&C[(size_t)rr * N + c0]       = make_float2(acc[mt][nt][0], acc[mt][nt][1]);
            *(float2*)&C[(size_t)(rr + 8) * N + c0] = make_float2(acc[mt][nt][2], acc[mt][nt][3]);
        }
    }
}

// ---------------- f32 -> f16 conversion (vectorized) ----------------
__global__ __launch_bounds__(256)
void cvt_f16_kernel(const float* __restrict__ src, __half* __restrict__ dst, int n4)
{
    int i = blockIdx.x * 256 + threadIdx.x;
    const int stride = gridDim.x * 256;
    for (; i < n4; i += stride) {
        float4 v = *(const float4*)(src + (size_t)i * 4);
        __half2 lo = __floats2half2_rn(v.x, v.y);
        __half2 hi = __floats2half2_rn(v.z, v.w);
        *(__half2*)(dst + (size_t)i * 4)     = lo;
        *(__half2*)(dst + (size_t)i * 4 + 2) = hi;
    }
}

// ---------------- exact fp32 dt path: dt_raw = x . W_dt^T, then softplus/exp ----------------
__global__ __launch_bounds__(256)
void dt_exact_kernel(const float* __restrict__ x, const float* __restrict__ in_proj_w,
                     const float* __restrict__ dt_bias, const float* __restrict__ A_log)
{
    __shared__ float As[16][132];
    __shared__ float Ws[16][68];
    const int tid = threadIdx.x;
    const int bt0 = blockIdx.x << 7;
    const int tm = tid >> 3;
    const int tn = tid & 7;
    const float* Wdt = in_proj_w + (size_t)(DI + CONVD) * DM;

    float acc[4][8];
    #pragma unroll
    for (int i = 0; i < 4; i++)
        #pragma unroll
        for (int j = 0; j < 8; j++) acc[i][j] = 0.f;

    for (int k0 = 0; k0 < DM; k0 += 16) {
        #pragma unroll
        for (int i = 0; i < 2; i++) {
            const int lin = tid + (i << 8);
            const int r = lin >> 2;
            const int kk = (lin & 3) << 2;
            float4 v = *(const float4*)(x + (size_t)(bt0 + r) * DM + k0 + kk);
            As[kk + 0][r] = v.x; As[kk + 1][r] = v.y;
            As[kk + 2][r] = v.z; As[kk + 3][r] = v.w;
        }
        {
            const int r = tid >> 2;
            const int kk = (tid & 3) << 2;
            float4 w = *(const float4*)(Wdt + (size_t)r * DM + k0 + kk);
            Ws[kk + 0][r] = w.x; Ws[kk + 1][r] = w.y;
            Ws[kk + 2][r] = w.z; Ws[kk + 3][r] = w.w;
        }
        __syncthreads();
        #pragma unroll
        for (int k = 0; k < 16; k++) {
            float a[4], b[8];
            #pragma unroll
            for (int i = 0; i < 4; i++) a[i] = As[k][tm + i * 32];
            #pragma unroll
            for (int j = 0; j < 8; j++) b[j] = Ws[k][tn + j * 8];
            #pragma unroll
            for (int i = 0; i < 4; i++)
                #pragma unroll
                for (int j = 0; j < 8; j++)
                    acc[i][j] = fmaf(a[i], b[j], acc[i][j]);
        }
        __syncthreads();
    }
    #pragma unroll
    for (int i = 0; i < 4; i++) {
        #pragma unroll
        for (int j = 0; j < 8; j++) {
            const int bt = bt0 + tm + i * 32;
            const int h  = tn + j * 8;
            float dtr = acc[i][j] + __ldg(dt_bias + h);
            float dts = (dtr > 20.f) ? dtr : log1pf(expf(dtr));
            g_dt[bt * HN + h] = dts;
            g_dA[bt * HN + h] = expf(-expf(__ldg(A_log + h)) * dts);
        }
    }
}

// ---------------- conv1d(depthwise, width 4) + SiLU ----------------
__global__ void conv_prep_kernel(const float* __restrict__ conv_w,
                                 const float* __restrict__ conv_b)
{
    const int bt = blockIdx.x;
    const int b  = bt / L_;
    const int t  = bt % L_;

    for (int c = threadIdx.x; c < CONVD; c += blockDim.x) {
        float4 wv = *(const float4*)(conv_w + c * 4);
        float s = conv_b[c];
        const float wk[4] = {wv.x, wv.y, wv.z, wv.w};
        #pragma unroll
        for (int k = 0; k < 4; k++) {
            int tt = t - 3 + k;
            float xv = (tt >= 0) ? g_zx[(size_t)(b * L_ + tt) * DIP + DI + c] : 0.f;
            s = fmaf(xv, wk[k], s);
        }
        float sil = s / (1.f + expf(-s));
        if (c < DI)            g_xh[(size_t)bt * DI + c]       = sil;
        else if (c < DI + DST) g_Bm[bt * DST + (c - DI)]        = sil;
        else                   g_Cm[bt * DST + (c - DI - DST)]  = sil;
    }
}

// ---------------- sequential selective scan + D*x + silu(z) gating ----------------
__global__ __launch_bounds__(64)
void scan_kernel(const float* __restrict__ Dp)
{
    const int b = blockIdx.x >> 6;
    const int h = blockIdx.x & 63;
    const int p = threadIdx.x;
    const float Dh = __ldg(Dp + h);

    float hs[DST];
    #pragma unroll
    for (int n = 0; n < DST; n++) hs[n] = 0.f;

    for (int t = 0; t < L_; t++) {
        const int bt = b * L_ + t;
        const float dA = __ldg(&g_dA[bt * HN + h]);
        const float dt = __ldg(&g_dt[bt * HN + h]);
        const float xv = g_xh[(size_t)bt * DI + h * HP + p];
        const float u  = dt * xv;
        const float4* Bv = (const float4*)(g_Bm + bt * DST);
        const float4* Cv = (const float4*)(g_Cm + bt * DST);
        float ac0 = 0.f, ac1 = 0.f, ac2 = 0.f, ac3 = 0.f;
        #pragma unroll
        for (int j = 0; j < 16; j++) {
            float4 Bq = __ldg(&Bv[j]);
            float4 Cq = __ldg(&Cv[j]);
            hs[4*j+0] = fmaf(hs[4*j+0], dA, u * Bq.x); ac0 = fmaf(hs[4*j+0], Cq.x, ac0);
            hs[4*j+1] = fmaf(hs[4*j+1], dA, u * Bq.y); ac1 = fmaf(hs[4*j+1], Cq.y, ac1);
            hs[4*j+2] = fmaf(hs[4*j+2], dA, u * Bq.z); ac2 = fmaf(hs[4*j+2], Cq.z, ac2);
            hs[4*j+3] = fmaf(hs[4*j+3], dA, u * Bq.w); ac3 = fmaf(hs[4*j+3], Cq.w, ac3);
        }
        const float acc = (ac0 + ac1) + (ac2 + ac3);
        const float z = g_zx[(size_t)bt * DIP + h * HP + p];
        const float gate = z / (1.f + expf(-z));
        g_y[(size_t)bt * DI + h * HP + p] = (acc + Dh * xv) * gate;
    }
}

// ---------------- RMS norm over D_INNER, writes half output for gemm2 ----------------
__global__ __launch_bounds__(256)
void rmsnorm_kernel(const float* __restrict__ norm_w)
{
    const int bt = blockIdx.x;
    const float* row = g_y + (size_t)bt * DI;
    __half* rowh = g_y16 + (size_t)bt * DI;
    float v[16];
    float ss = 0.f;
    #pragma unroll
    for (int i = 0; i < 16; i++) {
        v[i] = row[threadIdx.x + i * 256];
        ss = fmaf(v[i], v[i], ss);
    }
    #pragma unroll
    for (int o = 16; o > 0; o >>= 1) ss += __shfl_xor_sync(0xffffffffu, ss, o);
    __shared__ float sred[8];
    const int lane = threadIdx.x & 31, warp = threadIdx.x >> 5;
    if (lane == 0) sred[warp] = ss;
    __syncthreads();
    float tot = 0.f;
    #pragma unroll
    for (int w = 0; w < 8; w++) tot += sred[w];
    const float scale = rsqrtf(tot * (1.f / DI) + 1e-5f);
    #pragma unroll
    for (int i = 0; i < 16; i++) {
        const int c = threadIdx.x + i * 256;
        rowh[c] = __float2half_rn(v[i] * scale * norm_w[c]);
    }
}

// ---------------- classifier head ----------------
__global__ __launch_bounds__(256)
void cls_kernel(const float* __restrict__ cls_w, const float* __restrict__ cls_b,
                float* __restrict__ out)
{
    const int bt = blockIdx.x;
    const float* row = g_oh + (size_t)bt * DM;
    float a0 = 0.f, a1 = 0.f, a2 = 0.f, a3 = 0.f;
    for (int k = threadIdx.x; k < DM; k += 256) {
        float xv = row[k];
        a0 = fmaf(xv, __ldg(cls_w + k),          a0);
        a1 = fmaf(xv, __ldg(cls_w + DM + k),     a1);
        a2 = fmaf(xv, __ldg(cls_w + 2 * DM + k), a2);
        a3 = fmaf(xv, __ldg(cls_w + 3 * DM + k), a3);
    }
    #pragma unroll
    for (int o = 16; o > 0; o >>= 1) {
        a0 += __shfl_xor_sync(0xffffffffu, a0, o);
        a1 += __shfl_xor_sync(0xffffffffu, a1, o);
        a2 += __shfl_xor_sync(0xffffffffu, a2, o);
        a3 += __shfl_xor_sync(0xffffffffu, a3, o);
    }
    __shared__ float sred[8][4];
    const int lane = threadIdx.x & 31, warp = threadIdx.x >> 5;
    if (lane == 0) { sred[warp][0] = a0; sred[warp][1] = a1; sred[warp][2] = a2; sred[warp][3] = a3; }
    __syncthreads();
    if (threadIdx.x < 4) {
        float s = cls_b[threadIdx.x];
        #pragma unroll
        for (int w = 0; w < 8; w++) s += sred[w][threadIdx.x];
        out[bt * NCLS + threadIdx.x] = s;
    }
}

// ---------------- launcher ----------------
extern "C" void kernel_launch(void* const* d_in, const int* in_sizes, int n_in,
                              void* d_out, int out_size)
{
    (void)in_sizes; (void)n_in; (void)out_size;
    const float* x          = (const float*)d_in[0];
    const float* in_proj_w  = (const float*)d_in[1];
    const float* conv_w     = (const float*)d_in[2];
    const float* conv_b     = (const float*)d_in[3];
    const float* dt_bias    = (const float*)d_in[4];
    const float* A_log      = (const float*)d_in[5];
    const float* Dp         = (const float*)d_in[6];
    const float* norm_w     = (const float*)d_in[7];
    const float* out_proj_w = (const float*)d_in[8];
    const float* cls_w      = (const float*)d_in[9];
    const float* cls_b      = (const float*)d_in[10];
    float* out = (float*)d_out;

    float *zx, *oh;
    __half *x16, *w1h, *w2h, *y16;
    cudaGetSymbolAddress((void**)&zx,  g_zx);
    cudaGetSymbolAddress((void**)&oh,  g_oh);
    cudaGetSymbolAddress((void**)&x16, g_x16);
    cudaGetSymbolAddress((void**)&w1h, g_w1h);
    cudaGetSymbolAddress((void**)&w2h, g_w2h);
    cudaGetSymbolAddress((void**)&y16, g_y16);

    cudaFuncSetAttribute(gemm_h, cudaFuncAttributeMaxDynamicSharedMemorySize, SMEM_BYTES);

    // 0) convert GEMM operands to fp16
    cvt_f16_kernel<<<2048, 256>>>(x,          x16, BL * DM / 4);
    cvt_f16_kernel<<<2048, 256>>>(in_proj_w,  w1h, DIP * DM / 4);
    cvt_f16_kernel<<<2048, 256>>>(out_proj_w, w2h, DM * DI / 4);
    // 1) exact fp32 dt path (independent of gemm1)
    dt_exact_kernel<<<BL / 128, 256>>>(x, in_proj_w, dt_bias, A_log);
    // 2) in_proj GEMM: (8192,2048) x (8448,2048)^T, half operands
    {
        dim3 grid(DIP / 128, BL / 128);
        gemm_h<<<grid, 256, SMEM_BYTES>>>(x16, w1h, zx, BL, DIP, DM);
    }
    // 3) conv + silu
    conv_prep_kernel<<<BL, 256>>>(conv_w, conv_b);
    // 4) selective scan (+ D*x, silu(z) gate)
    scan_kernel<<<B_ * HN, 64>>>(Dp);
    // 5) RMS norm, writes half
    rmsnorm_kernel<<<BL, 256>>>(norm_w);
    // 6) out_proj GEMM: (8192,4096) x (2048,4096)^T, half operands
    {
        dim3 grid(DM / 128, BL / 128);
        gemm_h<<<grid, 256, SMEM_BYTES>>>(y16, w2h, oh, BL, DM, DI);
    }
    // 7) classifier head
    cls_kernel<<<BL, 256>>>(cls_w, cls_b, out);
}

// round 8
// speedup vs baseline: 1.2504x; 1.0122x over previous
#include <cuda_runtime.h>
#include <cuda_fp16.h>
#include <math.h>
#include <stdint.h>

#define B_    4
#define L_    2048
#define DM    2048
#define DI    4096
#define DST   64
#define HN    64
#define HP    64
#define CONVD 4224
#define DIP   8448
#define BL    (B_*L_)          // 8192
#define NCLS  4

// ---------------- scratch (static device globals; no allocation) ----------------
__device__ float  g_zx[BL * DIP];
__device__ float  g_xh[BL * DI];
__device__ float  g_Bm[BL * DST];
__device__ float  g_Cm[BL * DST];
__device__ float  g_dt[BL * HN];
__device__ float  g_dA[BL * HN];
__device__ float  g_y [BL * DI];
__device__ float  g_M [NCLS * DI];      // folded cls_w @ out_proj  (4 x 4096)
__device__ __half g_x16[BL * DM];       // half(x)
__device__ __half g_w1h[DIP * DM];      // half(in_proj_w)

// ---------------- helpers ----------------
__device__ __forceinline__ uint32_t smem_u32(const void* p) {
    uint32_t a;
    asm("{ .reg .u64 t; cvta.to.shared.u64 t, %1; cvt.u32.u64 %0, t; }" : "=r"(a) : "l"(p));
    return a;
}
__device__ __forceinline__ void cp16(uint32_t saddr, const void* gptr) {
    asm volatile("cp.async.ca.shared.global [%0], [%1], 16;" :: "r"(saddr), "l"(gptr) : "memory");
}
__device__ __forceinline__ void cp_commit() {
    asm volatile("cp.async.commit_group;" ::: "memory");
}
__device__ __forceinline__ void cp_wait2() {
    asm volatile("cp.async.wait_group 2;" ::: "memory");
}
__device__ __forceinline__ void ldsm4(unsigned& r0, unsigned& r1, unsigned& r2, unsigned& r3,
                                      uint32_t addr) {
    asm volatile("ldmatrix.sync.aligned.m8n8.x4.shared.b16 {%0,%1,%2,%3}, [%4];"
                 : "=r"(r0), "=r"(r1), "=r"(r2), "=r"(r3) : "r"(addr));
}
__device__ __forceinline__ void mma_f16(float c[4], const unsigned a[4], const unsigned b[2]) {
    asm volatile(
        "mma.sync.aligned.m16n8k16.row.col.f32.f16.f16.f32 "
        "{%0,%1,%2,%3}, {%4,%5,%6,%7}, {%8,%9}, {%0,%1,%2,%3};"
        : "+f"(c[0]), "+f"(c[1]), "+f"(c[2]), "+f"(c[3])
        : "r"(a[0]), "r"(a[1]), "r"(a[2]), "r"(a[3]),
          "r"(b[0]), "r"(b[1]));
}

// smem: 4 stages x (A[128 rows][32 halfs] + B[128][32]) = 4 x 16384 B
#define STAGE_BYTES 16384
#define SMEM_BYTES  (4 * STAGE_BYTES)   // 65536

// ---------------- FP16-operand GEMM (fp32 accum/out), ldmatrix + cp.async 4-stage ----
__global__ __launch_bounds__(256, 2)
void gemm_h(const __half* __restrict__ A, const __half* __restrict__ W,
            float* __restrict__ C, int M, int N, int K)
{
    extern __shared__ __align__(16) char smem[];
    const uint32_t sb = smem_u32(smem);

    const int tid  = threadIdx.x;
    const int warp = tid >> 5;
    const int lane = tid & 31;
    const int wm = warp & 1;
    const int wn = warp >> 1;
    const int g  = lane >> 2;
    const int t  = lane & 3;
    const int bm = blockIdx.y << 7;
    const int bn = blockIdx.x << 7;

    uint32_t pOff[2];
    const __half* AgP[2];
    const __half* WgP[2];
    #pragma unroll
    for (int j = 0; j < 2; j++) {
        const int c   = tid * 2 + j;
        const int pr  = c >> 2;
        const int pk8 = c & 3;
        pOff[j] = (uint32_t)(pr * 64 + ((pk8 ^ ((pr >> 1) & 3)) << 4));
        AgP[j] = A + (size_t)(bm + pr) * K + pk8 * 8;
        WgP[j] = W + (size_t)(bn + pr) * K + pk8 * 8;
    }

    uint32_t offA[4], swA[4];
    #pragma unroll
    for (int mt = 0; mt < 4; mt++) {
        const int r = wm * 64 + mt * 16 + (lane & 7) + ((lane >> 3) & 1) * 8;
        offA[mt] = (uint32_t)(r * 64);
        swA[mt]  = (uint32_t)((r >> 1) & 3);
    }
    uint32_t offB[2], swB[2], cB;
    #pragma unroll
    for (int h = 0; h < 2; h++) {
        const int r = wn * 32 + h * 16 + (lane & 7) + ((lane >> 4) & 1) * 8;
        offB[h] = (uint32_t)(r * 64);
        swB[h]  = (uint32_t)((r >> 1) & 3);
    }
    cB = (uint32_t)((lane >> 3) & 1);
    const uint32_t cA = (uint32_t)(lane >> 4);

    float acc[4][4][4];
    #pragma unroll
    for (int i = 0; i < 4; i++)
        #pragma unroll
        for (int j = 0; j < 4; j++)
            #pragma unroll
            for (int c = 0; c < 4; c++) acc[i][j][c] = 0.f;

    const int KT = K >> 5;

    auto issue_stage = [&](int kt, int s) {
        const uint32_t sA = sb + s * STAGE_BYTES;
        #pragma unroll
        for (int j = 0; j < 2; j++) {
            cp16(sA + pOff[j],        AgP[j] + kt * 32);
            cp16(sA + 8192 + pOff[j], WgP[j] + kt * 32);
        }
    };

    issue_stage(0, 0); cp_commit();
    issue_stage(1, 1); cp_commit();
    issue_stage(2, 2); cp_commit();
    cp_wait2();
    __syncthreads();

    for (int kt = 0; kt < KT; kt++) {
        const int s = kt & 3;
        const uint32_t sA = sb + s * STAGE_BYTES;
        const uint32_t sBq = sA + 8192;

        #pragma unroll
        for (int kk = 0; kk < 2; kk++) {
            unsigned a[4][4], b[4][2];
            #pragma unroll
            for (int mt = 0; mt < 4; mt++) {
                const uint32_t ch = (uint32_t)(2 * kk) + cA;
                ldsm4(a[mt][0], a[mt][1], a[mt][2], a[mt][3],
                      sA + offA[mt] + ((ch ^ swA[mt]) << 4));
            }
            #pragma unroll
            for (int h = 0; h < 2; h++) {
                const uint32_t ch = (uint32_t)(2 * kk) + cB;
                ldsm4(b[2*h][0], b[2*h][1], b[2*h+1][0], b[2*h+1][1],
                      sBq + offB[h] + ((ch ^ swB[h]) << 4));
            }
            #pragma unroll
            for (int mt = 0; mt < 4; mt++)
                #pragma unroll
                for (int nt = 0; nt < 4; nt++)
                    mma_f16(acc[mt][nt], a[mt], b[nt]);
        }

        if (kt + 3 < KT) issue_stage(kt + 3, (kt + 3) & 3);
        cp_commit();
        if (kt + 1 < KT) {
            cp_wait2();
            __syncthreads();
        }
    }

    #pragma unroll
    for (int mt = 0; mt < 4; mt++) {
        #pragma unroll
        for (int nt = 0; nt < 4; nt++) {
            const int rr = bm + wm * 64 + mt * 16 + g;
            const int c0 = bn + wn * 32 + nt * 8 + 2 * t;
            *(float2*)&C[(size_t)rr * N + c0]       = make_float2(acc[mt][nt][0], acc[mt][nt][1]);
            *(float2*)&C[(size_t)(rr + 8) * N + c0] = make_float2(acc[mt][nt][2], acc[mt][nt][3]);
        }
    }
}

// ---------------- f32 -> f16 conversion (vectorized) ----------------
__global__ __launch_bounds__(256)
void cvt_f16_kernel(const float* __restrict__ src, __half* __restrict__ dst, int n4)
{
    int i = blockIdx.x * 256 + threadIdx.x;
    const int stride = gridDim.x * 256;
    for (; i < n4; i += stride) {
        float4 v = *(const float4*)(src + (size_t)i * 4);
        *(__half2*)(dst + (size_t)i * 4)     = __floats2half2_rn(v.x, v.y);
        *(__half2*)(dst + (size_t)i * 4 + 2) = __floats2half2_rn(v.z, v.w);
    }
}

// ---------------- fold M = cls_w @ out_proj  (4 x 4096), exact fp32 ----------------
// thread per output column e; coalesced out_proj_w[d*DI + e] reads.
__global__ __launch_bounds__(256)
void mbuild_kernel(const float* __restrict__ out_proj_w, const float* __restrict__ cls_w)
{
    const int e = blockIdx.x * 256 + threadIdx.x;   // 0..4095
    float a0 = 0.f, a1 = 0.f, a2 = 0.f, a3 = 0.f;
    for (int d = 0; d < DM; d++) {
        const float w = __ldg(out_proj_w + (size_t)d * DI + e);
        a0 = fmaf(w, __ldg(cls_w + d),          a0);
        a1 = fmaf(w, __ldg(cls_w + DM + d),     a1);
        a2 = fmaf(w, __ldg(cls_w + 2 * DM + d), a2);
        a3 = fmaf(w, __ldg(cls_w + 3 * DM + d), a3);
    }
    g_M[e]          = a0;
    g_M[DI + e]     = a1;
    g_M[2 * DI + e] = a2;
    g_M[3 * DI + e] = a3;
}

// ---------------- exact fp32 dt path (64 rows/block, grid 128) ----------------
__global__ __launch_bounds__(256)
void dt_exact_kernel(const float* __restrict__ x, const float* __restrict__ in_proj_w,
                     const float* __restrict__ dt_bias, const float* __restrict__ A_log)
{
    __shared__ float As[16][68];
    __shared__ float Ws[16][68];
    const int tid = threadIdx.x;
    const int bt0 = blockIdx.x << 6;       // 64 rows per block
    const int tm = tid >> 3;               // 0..31 -> rows tm + i*32, i<2
    const int tn = tid & 7;                // 0..7  -> cols tn + j*8
    const float* Wdt = in_proj_w + (size_t)(DI + CONVD) * DM;

    float acc[2][8];
    #pragma unroll
    for (int i = 0; i < 2; i++)
        #pragma unroll
        for (int j = 0; j < 8; j++) acc[i][j] = 0.f;

    for (int k0 = 0; k0 < DM; k0 += 16) {
        {
            const int r = tid >> 2;            // 0..63
            const int kk = (tid & 3) << 2;
            float4 v = *(const float4*)(x + (size_t)(bt0 + r) * DM + k0 + kk);
            As[kk + 0][r] = v.x; As[kk + 1][r] = v.y;
            As[kk + 2][r] = v.z; As[kk + 3][r] = v.w;
            float4 w = *(const float4*)(Wdt + (size_t)r * DM + k0 + kk);
            Ws[kk + 0][r] = w.x; Ws[kk + 1][r] = w.y;
            Ws[kk + 2][r] = w.z; Ws[kk + 3][r] = w.w;
        }
        __syncthreads();
        #pragma unroll
        for (int k = 0; k < 16; k++) {
            float a[2], b[8];
            #pragma unroll
            for (int i = 0; i < 2; i++) a[i] = As[k][tm + i * 32];
            #pragma unroll
            for (int j = 0; j < 8; j++) b[j] = Ws[k][tn + j * 8];
            #pragma unroll
            for (int i = 0; i < 2; i++)
                #pragma unroll
                for (int j = 0; j < 8; j++)
                    acc[i][j] = fmaf(a[i], b[j], acc[i][j]);
        }
        __syncthreads();
    }
    #pragma unroll
    for (int i = 0; i < 2; i++) {
        #pragma unroll
        for (int j = 0; j < 8; j++) {
            const int bt = bt0 + tm + i * 32;
            const int h  = tn + j * 8;
            float dtr = acc[i][j] + __ldg(dt_bias + h);
            float dts = (dtr > 20.f) ? dtr : log1pf(expf(dtr));
            g_dt[bt * HN + h] = dts;
            g_dA[bt * HN + h] = expf(-expf(__ldg(A_log + h)) * dts);
        }
    }
}

// ---------------- conv1d(depthwise, width 4) + SiLU ----------------
__global__ void conv_prep_kernel(const float* __restrict__ conv_w,
                                 const float* __restrict__ conv_b)
{
    const int bt = blockIdx.x;
    const int b  = bt / L_;
    const int t  = bt % L_;

    for (int c = threadIdx.x; c < CONVD; c += blockDim.x) {
        float4 wv = *(const float4*)(conv_w + c * 4);
        float s = conv_b[c];
        const float wk[4] = {wv.x, wv.y, wv.z, wv.w};
        #pragma unroll
        for (int k = 0; k < 4; k++) {
            int tt = t - 3 + k;
            float xv = (tt >= 0) ? g_zx[(size_t)(b * L_ + tt) * DIP + DI + c] : 0.f;
            s = fmaf(xv, wk[k], s);
        }
        float sil = s / (1.f + expf(-s));
        if (c < DI)            g_xh[(size_t)bt * DI + c]       = sil;
        else if (c < DI + DST) g_Bm[bt * DST + (c - DI)]        = sil;
        else                   g_Cm[bt * DST + (c - DI - DST)]  = sil;
    }
}

// ---------------- sequential selective scan + D*x + silu(z) gating ----------------
__global__ __launch_bounds__(64)
void scan_kernel(const float* __restrict__ Dp)
{
    const int b = blockIdx.x >> 6;
    const int h = blockIdx.x & 63;
    const int p = threadIdx.x;
    const float Dh = __ldg(Dp + h);

    float hs[DST];
    #pragma unroll
    for (int n = 0; n < DST; n++) hs[n] = 0.f;

    for (int t = 0; t < L_; t++) {
        const int bt = b * L_ + t;
        const float dA = __ldg(&g_dA[bt * HN + h]);
        const float dt = __ldg(&g_dt[bt * HN + h]);
        const float xv = g_xh[(size_t)bt * DI + h * HP + p];
        const float u  = dt * xv;
        const float4* Bv = (const float4*)(g_Bm + bt * DST);
        const float4* Cv = (const float4*)(g_Cm + bt * DST);
        float ac[8];
        #pragma unroll
        for (int i = 0; i < 8; i++) ac[i] = 0.f;
        #pragma unroll
        for (int j = 0; j < 16; j++) {
            float4 Bq = __ldg(&Bv[j]);
            float4 Cq = __ldg(&Cv[j]);
            const int o = (j & 1) << 2;   // alternate accumulator banks
            hs[4*j+0] = fmaf(hs[4*j+0], dA, u * Bq.x); ac[o+0] = fmaf(hs[4*j+0], Cq.x, ac[o+0]);
            hs[4*j+1] = fmaf(hs[4*j+1], dA, u * Bq.y); ac[o+1] = fmaf(hs[4*j+1], Cq.y, ac[o+1]);
            hs[4*j+2] = fmaf(hs[4*j+2], dA, u * Bq.z); ac[o+2] = fmaf(hs[4*j+2], Cq.z, ac[o+2]);
            hs[4*j+3] = fmaf(hs[4*j+3], dA, u * Bq.w); ac[o+3] = fmaf(hs[4*j+3], Cq.w, ac[o+3]);
        }
        const float acc = ((ac[0] + ac[4]) + (ac[1] + ac[5])) + ((ac[2] + ac[6]) + (ac[3] + ac[7]));
        const float z = g_zx[(size_t)bt * DIP + h * HP + p];
        const float gate = z / (1.f + expf(-z));
        g_y[(size_t)bt * DI + h * HP + p] = (acc + Dh * xv) * gate;
    }
}

// ---------------- RMS norm + folded (out_proj ∘ classifier):  out[bt,c] = Σ_e ynorm[e] M[c,e] + b[c]
__global__ __launch_bounds__(256)
void rmsnorm_cls_kernel(const float* __restrict__ norm_w,
                        const float* __restrict__ cls_b, float* __restrict__ out)
{
    const int bt = blockIdx.x;
    const float* row = g_y + (size_t)bt * DI;
    float v[16];
    float ss = 0.f;
    #pragma unroll
    for (int i = 0; i < 16; i++) {
        v[i] = row[threadIdx.x + i * 256];
        ss = fmaf(v[i], v[i], ss);
    }
    #pragma unroll
    for (int o = 16; o > 0; o >>= 1) ss += __shfl_xor_sync(0xffffffffu, ss, o);
    __shared__ float sred[8];
    const int lane = threadIdx.x & 31, warp = threadIdx.x >> 5;
    if (lane == 0) sred[warp] = ss;
    __syncthreads();
    float tot = 0.f;
    #pragma unroll
    for (int w = 0; w < 8; w++) tot += sred[w];
    const float scale = rsqrtf(tot * (1.f / DI) + 1e-5f);

    float a0 = 0.f, a1 = 0.f, a2 = 0.f, a3 = 0.f;
    #pragma unroll
    for (int i = 0; i < 16; i++) {
        const int c = threadIdx.x + i * 256;
        const float yn = v[i] * scale * __ldg(norm_w + c);
        a0 = fmaf(yn, __ldg(&g_M[c]),          a0);
        a1 = fmaf(yn, __ldg(&g_M[DI + c]),     a1);
        a2 = fmaf(yn, __ldg(&g_M[2 * DI + c]), a2);
        a3 = fmaf(yn, __ldg(&g_M[3 * DI + c]), a3);
    }
    #pragma unroll
    for (int o = 16; o > 0; o >>= 1) {
        a0 += __shfl_xor_sync(0xffffffffu, a0, o);
        a1 += __shfl_xor_sync(0xffffffffu, a1, o);
        a2 += __shfl_xor_sync(0xffffffffu, a2, o);
        a3 += __shfl_xor_sync(0xffffffffu, a3, o);
    }
    __shared__ float s4[8][4];
    if (lane == 0) { s4[warp][0] = a0; s4[warp][1] = a1; s4[warp][2] = a2; s4[warp][3] = a3; }
    __syncthreads();
    if (threadIdx.x < 4) {
        float s = __ldg(cls_b + threadIdx.x);
        #pragma unroll
        for (int w = 0; w < 8; w++) s += s4[w][threadIdx.x];
        out[bt * NCLS + threadIdx.x] = s;
    }
}

// ---------------- launcher ----------------
extern "C" void kernel_launch(void* const* d_in, const int* in_sizes, int n_in,
                              void* d_out, int out_size)
{
    (void)in_sizes; (void)n_in; (void)out_size;
    const float* x          = (const float*)d_in[0];
    const float* in_proj_w  = (const float*)d_in[1];
    const float* conv_w     = (const float*)d_in[2];
    const float* conv_b     = (const float*)d_in[3];
    const float* dt_bias    = (const float*)d_in[4];
    const float* A_log      = (const float*)d_in[5];
    const float* Dp         = (const float*)d_in[6];
    const float* norm_w     = (const float*)d_in[7];
    const float* out_proj_w = (const float*)d_in[8];
    const float* cls_w      = (const float*)d_in[9];
    const float* cls_b      = (const float*)d_in[10];
    float* out = (float*)d_out;

    float* zx;
    __half *x16, *w1h;
    cudaGetSymbolAddress((void**)&zx,  g_zx);
    cudaGetSymbolAddress((void**)&x16, g_x16);
    cudaGetSymbolAddress((void**)&w1h, g_w1h);

    cudaFuncSetAttribute(gemm_h, cudaFuncAttributeMaxDynamicSharedMemorySize, SMEM_BYTES);

    // 0) convert gemm1 operands to fp16; build folded M
    cvt_f16_kernel<<<2048, 256>>>(x,         x16, BL * DM / 4);
    cvt_f16_kernel<<<2048, 256>>>(in_proj_w, w1h, DIP * DM / 4);
    mbuild_kernel<<<DI / 256, 256>>>(out_proj_w, cls_w);
    // 1) exact fp32 dt path
    dt_exact_kernel<<<BL / 64, 256>>>(x, in_proj_w, dt_bias, A_log);
    // 2) in_proj GEMM: (8192,2048) x (8448,2048)^T, half operands
    {
        dim3 grid(DIP / 128, BL / 128);
        gemm_h<<<grid, 256, SMEM_BYTES>>>(x16, w1h, zx, BL, DIP, DM);
    }
    // 3) conv + silu
    conv_prep_kernel<<<BL, 256>>>(conv_w, conv_b);
    // 4) selective scan (+ D*x, silu(z) gate)
    scan_kernel<<<B_ * HN, 64>>>(Dp);
    // 5) RMS norm fused with folded out_proj+classifier
    rmsnorm_cls_kernel<<<BL, 256>>>(norm_w, cls_b, out);
}

// round 9
// speedup vs baseline: 1.2991x; 1.0389x over previous
#include <cuda_runtime.h>
#include <cuda_fp16.h>
#include <math.h>
#include <stdint.h>

#define B_    4
#define L_    2048
#define DM    2048
#define DI    4096
#define DST   64
#define HN    64
#define HP    64
#define CONVD 4224
#define DIP   8448
#define NOUT  8320             // gemm1 columns actually consumed (z + xBC)
#define BL    (B_*L_)          // 8192
#define NCLS  4

// ---------------- scratch (static device globals; no allocation) ----------------
__device__ float  g_zx[BL * DIP];
__device__ float  g_xh[BL * DI];
__device__ float  g_Bm[BL * DST];
__device__ float  g_Cm[BL * DST];
__device__ float  g_dt[BL * HN];
__device__ float  g_dA[BL * HN];
__device__ float  g_y [BL * DI];
__device__ float  g_M [NCLS * DI];      // folded cls_w @ out_proj  (4 x 4096)
__device__ __half g_x16[BL * DM];       // half(x)
__device__ __half g_w1h[DIP * DM];      // half(in_proj_w)

// ---------------- helpers ----------------
__device__ __forceinline__ uint32_t smem_u32(const void* p) {
    uint32_t a;
    asm("{ .reg .u64 t; cvta.to.shared.u64 t, %1; cvt.u32.u64 %0, t; }" : "=r"(a) : "l"(p));
    return a;
}
__device__ __forceinline__ void cp16(uint32_t saddr, const void* gptr) {
    asm volatile("cp.async.ca.shared.global [%0], [%1], 16;" :: "r"(saddr), "l"(gptr) : "memory");
}
__device__ __forceinline__ void cp_commit() {
    asm volatile("cp.async.commit_group;" ::: "memory");
}
__device__ __forceinline__ void cp_wait2() {
    asm volatile("cp.async.wait_group 2;" ::: "memory");
}
__device__ __forceinline__ void ldsm4(unsigned& r0, unsigned& r1, unsigned& r2, unsigned& r3,
                                      uint32_t addr) {
    asm volatile("ldmatrix.sync.aligned.m8n8.x4.shared.b16 {%0,%1,%2,%3}, [%4];"
                 : "=r"(r0), "=r"(r1), "=r"(r2), "=r"(r3) : "r"(addr));
}
__device__ __forceinline__ void mma_f16(float c[4], const unsigned a[4], const unsigned b[2]) {
    asm volatile(
        "mma.sync.aligned.m16n8k16.row.col.f32.f16.f16.f32 "
        "{%0,%1,%2,%3}, {%4,%5,%6,%7}, {%8,%9}, {%0,%1,%2,%3};"
        : "+f"(c[0]), "+f"(c[1]), "+f"(c[2]), "+f"(c[3])
        : "r"(a[0]), "r"(a[1]), "r"(a[2]), "r"(a[3]),
          "r"(b[0]), "r"(b[1]));
}

// smem: 4 stages x (A[256 rows][32 halfs]=16KB + B[128][32]=8KB) = 4 x 24576 B
#define STAGE_BYTES 24576
#define STAGE_BOFF  16384
#define SMEM_BYTES  (4 * STAGE_BYTES)   // 98304

// ---------------- FP16-operand GEMM, 256x128 CTA tile, 64x64 warp tile -------------
// C[M,Ncols] = A[M,K] * W[Ncols,K]^T (half, K contiguous), C fp32 with row stride ldc.
// 256 threads = 8 warps (4m x 2n). BK=32, 4-stage cp.async, ldmatrix.x4 everywhere.
__global__ __launch_bounds__(256, 1)
void gemm_h256(const __half* __restrict__ A, const __half* __restrict__ W,
               float* __restrict__ C, int M, int K, int ldc)
{
    extern __shared__ __align__(16) char smem[];
    const uint32_t sb = smem_u32(smem);

    const int tid  = threadIdx.x;
    const int warp = tid >> 5;
    const int lane = tid & 31;
    const int wm = warp >> 1;        // 0..3
    const int wn = warp & 1;         // 0..1
    const int g  = lane >> 2;
    const int t  = lane & 3;
    const int bm = blockIdx.y << 8;  // 256 rows
    const int bn = blockIdx.x << 7;  // 128 cols

    // producer: 6 chunks per thread per stage (1024 A-chunks + 512 B-chunks)
    uint32_t pOff[6];
    const __half* Gp[6];
    #pragma unroll
    for (int j = 0; j < 6; j++) {
        const int c = tid + (j << 8);
        if (c < 1024) {
            const int pr = c >> 2, k8 = c & 3;
            pOff[j] = (uint32_t)(pr * 64 + ((k8 ^ ((pr >> 1) & 3)) << 4));
            Gp[j]   = A + (size_t)(bm + pr) * K + k8 * 8;
        } else {
            const int cb = c - 1024;
            const int pr = cb >> 2, k8 = cb & 3;
            pOff[j] = (uint32_t)(STAGE_BOFF + pr * 64 + ((k8 ^ ((pr >> 1) & 3)) << 4));
            Gp[j]   = W + (size_t)(bn + pr) * K + k8 * 8;
        }
    }

    // consumer ldmatrix offsets
    uint32_t offA[4], swA[4];
    #pragma unroll
    for (int mt = 0; mt < 4; mt++) {
        const int r = wm * 64 + mt * 16 + (lane & 7) + ((lane >> 3) & 1) * 8;
        offA[mt] = (uint32_t)(r * 64);
        swA[mt]  = (uint32_t)((r >> 1) & 3);
    }
    uint32_t offB[4], swB[4];
    #pragma unroll
    for (int h = 0; h < 4; h++) {
        const int r = wn * 64 + h * 16 + (lane & 7) + ((lane >> 4) & 1) * 8;
        offB[h] = (uint32_t)(STAGE_BOFF + r * 64);
        swB[h]  = (uint32_t)((r >> 1) & 3);
    }
    const uint32_t cA = (uint32_t)(lane >> 4);
    const uint32_t cB = (uint32_t)((lane >> 3) & 1);

    float acc[4][8][4];
    #pragma unroll
    for (int i = 0; i < 4; i++)
        #pragma unroll
        for (int j = 0; j < 8; j++)
            #pragma unroll
            for (int c = 0; c < 4; c++) acc[i][j][c] = 0.f;

    const int KT = K >> 5;

    auto issue_stage = [&](int kt, int s) {
        const uint32_t base = sb + s * STAGE_BYTES;
        #pragma unroll
        for (int j = 0; j < 6; j++)
            cp16(base + pOff[j], Gp[j] + kt * 32);
    };

    issue_stage(0, 0); cp_commit();
    issue_stage(1, 1); cp_commit();
    issue_stage(2, 2); cp_commit();
    cp_wait2();
    __syncthreads();

    for (int kt = 0; kt < KT; kt++) {
        const int s = kt & 3;
        const uint32_t base = sb + s * STAGE_BYTES;

        #pragma unroll
        for (int kk = 0; kk < 2; kk++) {
            unsigned a[4][4], b[8][2];
            #pragma unroll
            for (int mt = 0; mt < 4; mt++) {
                const uint32_t ch = (uint32_t)(2 * kk) + cA;
                ldsm4(a[mt][0], a[mt][1], a[mt][2], a[mt][3],
                      base + offA[mt] + ((ch ^ swA[mt]) << 4));
            }
            #pragma unroll
            for (int h = 0; h < 4; h++) {
                const uint32_t ch = (uint32_t)(2 * kk) + cB;
                ldsm4(b[2*h][0], b[2*h][1], b[2*h+1][0], b[2*h+1][1],
                      base + offB[h] + ((ch ^ swB[h]) << 4));
            }
            #pragma unroll
            for (int mt = 0; mt < 4; mt++)
                #pragma unroll
                for (int nt = 0; nt < 8; nt++)
                    mma_f16(acc[mt][nt], a[mt], b[nt]);
        }

        if (kt + 3 < KT) issue_stage(kt + 3, (kt + 3) & 3);
        cp_commit();
        if (kt + 1 < KT) {
            cp_wait2();
            __syncthreads();
        }
    }

    #pragma unroll
    for (int mt = 0; mt < 4; mt++) {
        #pragma unroll
        for (int nt = 0; nt < 8; nt++) {
            const int rr = bm + wm * 64 + mt * 16 + g;
            const int c0 = bn + wn * 64 + nt * 8 + 2 * t;
            *(float2*)&C[(size_t)rr * ldc + c0]       = make_float2(acc[mt][nt][0], acc[mt][nt][1]);
            *(float2*)&C[(size_t)(rr + 8) * ldc + c0] = make_float2(acc[mt][nt][2], acc[mt][nt][3]);
        }
    }
}

// ---------------- f32 -> f16 conversion (vectorized) ----------------
__global__ __launch_bounds__(256)
void cvt_f16_kernel(const float* __restrict__ src, __half* __restrict__ dst, int n4)
{
    int i = blockIdx.x * 256 + threadIdx.x;
    const int stride = gridDim.x * 256;
    for (; i < n4; i += stride) {
        float4 v = *(const float4*)(src + (size_t)i * 4);
        *(__half2*)(dst + (size_t)i * 4)     = __floats2half2_rn(v.x, v.y);
        *(__half2*)(dst + (size_t)i * 4 + 2) = __floats2half2_rn(v.z, v.w);
    }
}

// ---------------- fold M = cls_w @ out_proj  (4 x 4096), exact fp32 ----------------
__global__ __launch_bounds__(256)
void mbuild_kernel(const float* __restrict__ out_proj_w, const float* __restrict__ cls_w)
{
    const int e = blockIdx.x * 256 + threadIdx.x;   // 0..4095
    float a0 = 0.f, a1 = 0.f, a2 = 0.f, a3 = 0.f;
    for (int d = 0; d < DM; d++) {
        const float w = __ldg(out_proj_w + (size_t)d * DI + e);
        a0 = fmaf(w, __ldg(cls_w + d),          a0);
        a1 = fmaf(w, __ldg(cls_w + DM + d),     a1);
        a2 = fmaf(w, __ldg(cls_w + 2 * DM + d), a2);
        a3 = fmaf(w, __ldg(cls_w + 3 * DM + d), a3);
    }
    g_M[e]          = a0;
    g_M[DI + e]     = a1;
    g_M[2 * DI + e] = a2;
    g_M[3 * DI + e] = a3;
}

// ---------------- exact fp32 dt path (32 rows/block, grid 256) ----------------
__global__ __launch_bounds__(256)
void dt_exact_kernel(const float* __restrict__ x, const float* __restrict__ in_proj_w,
                     const float* __restrict__ dt_bias, const float* __restrict__ A_log)
{
    __shared__ float As[16][36];
    __shared__ float Ws[16][68];
    const int tid = threadIdx.x;
    const int bt0 = blockIdx.x << 5;       // 32 rows per block
    const int tm = tid >> 3;               // 0..31 -> row
    const int tn = tid & 7;                // 0..7  -> cols tn + j*8
    const float* Wdt = in_proj_w + (size_t)(DI + CONVD) * DM;

    float acc[8];
    #pragma unroll
    for (int j = 0; j < 8; j++) acc[j] = 0.f;

    for (int k0 = 0; k0 < DM; k0 += 16) {
        if (tid < 128) {
            const int r = tid >> 2;            // 0..31
            const int kk = (tid & 3) << 2;
            float4 v = *(const float4*)(x + (size_t)(bt0 + r) * DM + k0 + kk);
            As[kk + 0][r] = v.x; As[kk + 1][r] = v.y;
            As[kk + 2][r] = v.z; As[kk + 3][r] = v.w;
        }
        {
            const int r = tid >> 2;            // 0..63
            const int kk = (tid & 3) << 2;
            float4 w = *(const float4*)(Wdt + (size_t)r * DM + k0 + kk);
            Ws[kk + 0][r] = w.x; Ws[kk + 1][r] = w.y;
            Ws[kk + 2][r] = w.z; Ws[kk + 3][r] = w.w;
        }
        __syncthreads();
        #pragma unroll
        for (int k = 0; k < 16; k++) {
            const float a = As[k][tm];
            #pragma unroll
            for (int j = 0; j < 8; j++)
                acc[j] = fmaf(a, Ws[k][tn + j * 8], acc[j]);
        }
        __syncthreads();
    }
    #pragma unroll
    for (int j = 0; j < 8; j++) {
        const int bt = bt0 + tm;
        const int h  = tn + j * 8;
        float dtr = acc[j] + __ldg(dt_bias + h);
        float dts = (dtr > 20.f) ? dtr : log1pf(expf(dtr));
        g_dt[bt * HN + h] = dts;
        g_dA[bt * HN + h] = expf(-expf(__ldg(A_log + h)) * dts);
    }
}

// ---------------- conv1d(depthwise, width 4) + SiLU ----------------
__global__ void conv_prep_kernel(const float* __restrict__ conv_w,
                                 const float* __restrict__ conv_b)
{
    const int bt = blockIdx.x;
    const int b  = bt / L_;
    const int t  = bt % L_;

    for (int c = threadIdx.x; c < CONVD; c += blockDim.x) {
        float4 wv = *(const float4*)(conv_w + c * 4);
        float s = conv_b[c];
        const float wk[4] = {wv.x, wv.y, wv.z, wv.w};
        #pragma unroll
        for (int k = 0; k < 4; k++) {
            int tt = t - 3 + k;
            float xv = (tt >= 0) ? g_zx[(size_t)(b * L_ + tt) * DIP + DI + c] : 0.f;
            s = fmaf(xv, wk[k], s);
        }
        float sil = s / (1.f + expf(-s));
        if (c < DI)            g_xh[(size_t)bt * DI + c]       = sil;
        else if (c < DI + DST) g_Bm[bt * DST + (c - DI)]        = sil;
        else                   g_Cm[bt * DST + (c - DI - DST)]  = sil;
    }
}

// ---------------- sequential selective scan + D*x + silu(z) gating ----------------
__global__ __launch_bounds__(64)
void scan_kernel(const float* __restrict__ Dp)
{
    const int b = blockIdx.x >> 6;
    const int h = blockIdx.x & 63;
    const int p = threadIdx.x;
    const float Dh = __ldg(Dp + h);

    float hs[DST];
    #pragma unroll
    for (int n = 0; n < DST; n++) hs[n] = 0.f;

    for (int t = 0; t < L_; t++) {
        const int bt = b * L_ + t;
        const float dA = __ldg(&g_dA[bt * HN + h]);
        const float dt = __ldg(&g_dt[bt * HN + h]);
        const float xv = g_xh[(size_t)bt * DI + h * HP + p];
        const float u  = dt * xv;
        const float4* Bv = (const float4*)(g_Bm + bt * DST);
        const float4* Cv = (const float4*)(g_Cm + bt * DST);
        float ac[8];
        #pragma unroll
        for (int i = 0; i < 8; i++) ac[i] = 0.f;
        #pragma unroll
        for (int j = 0; j < 16; j++) {
            float4 Bq = __ldg(&Bv[j]);
            float4 Cq = __ldg(&Cv[j]);
            const int o = (j & 1) << 2;
            hs[4*j+0] = fmaf(hs[4*j+0], dA, u * Bq.x); ac[o+0] = fmaf(hs[4*j+0], Cq.x, ac[o+0]);
            hs[4*j+1] = fmaf(hs[4*j+1], dA, u * Bq.y); ac[o+1] = fmaf(hs[4*j+1], Cq.y, ac[o+1]);
            hs[4*j+2] = fmaf(hs[4*j+2], dA, u * Bq.z); ac[o+2] = fmaf(hs[4*j+2], Cq.z, ac[o+2]);
            hs[4*j+3] = fmaf(hs[4*j+3], dA, u * Bq.w); ac[o+3] = fmaf(hs[4*j+3], Cq.w, ac[o+3]);
        }
        const float acc = ((ac[0] + ac[4]) + (ac[1] + ac[5])) + ((ac[2] + ac[6]) + (ac[3] + ac[7]));
        const float z = g_zx[(size_t)bt * DIP + h * HP + p];
        const float gate = z / (1.f + expf(-z));
        g_y[(size_t)bt * DI + h * HP + p] = (acc + Dh * xv) * gate;
    }
}

// ---------------- RMS norm + folded (out_proj ∘ classifier) ----------------
__global__ __launch_bounds__(256)
void rmsnorm_cls_kernel(const float* __restrict__ norm_w,
                        const float* __restrict__ cls_b, float* __restrict__ out)
{
    const int bt = blockIdx.x;
    const float* row = g_y + (size_t)bt * DI;
    float v[16];
    float ss = 0.f;
    #pragma unroll
    for (int i = 0; i < 16; i++) {
        v[i] = row[threadIdx.x + i * 256];
        ss = fmaf(v[i], v[i], ss);
    }
    #pragma unroll
    for (int o = 16; o > 0; o >>= 1) ss += __shfl_xor_sync(0xffffffffu, ss, o);
    __shared__ float sred[8];
    const int lane = threadIdx.x & 31, warp = threadIdx.x >> 5;
    if (lane == 0) sred[warp] = ss;
    __syncthreads();
    float tot = 0.f;
    #pragma unroll
    for (int w = 0; w < 8; w++) tot += sred[w];
    const float scale = rsqrtf(tot * (1.f / DI) + 1e-5f);

    float a0 = 0.f, a1 = 0.f, a2 = 0.f, a3 = 0.f;
    #pragma unroll
    for (int i = 0; i < 16; i++) {
        const int c = threadIdx.x + i * 256;
        const float yn = v[i] * scale * __ldg(norm_w + c);
        a0 = fmaf(yn, __ldg(&g_M[c]),          a0);
        a1 = fmaf(yn, __ldg(&g_M[DI + c]),     a1);
        a2 = fmaf(yn, __ldg(&g_M[2 * DI + c]), a2);
        a3 = fmaf(yn, __ldg(&g_M[3 * DI + c]), a3);
    }
    #pragma unroll
    for (int o = 16; o > 0; o >>= 1) {
        a0 += __shfl_xor_sync(0xffffffffu, a0, o);
        a1 += __shfl_xor_sync(0xffffffffu, a1, o);
        a2 += __shfl_xor_sync(0xffffffffu, a2, o);
        a3 += __shfl_xor_sync(0xffffffffu, a3, o);
    }
    __shared__ float s4[8][4];
    if (lane == 0) { s4[warp][0] = a0; s4[warp][1] = a1; s4[warp][2] = a2; s4[warp][3] = a3; }
    __syncthreads();
    if (threadIdx.x < 4) {
        float s = __ldg(cls_b + threadIdx.x);
        #pragma unroll
        for (int w = 0; w < 8; w++) s += s4[w][threadIdx.x];
        out[bt * NCLS + threadIdx.x] = s;
    }
}

// ---------------- launcher ----------------
extern "C" void kernel_launch(void* const* d_in, const int* in_sizes, int n_in,
                              void* d_out, int out_size)
{
    (void)in_sizes; (void)n_in; (void)out_size;
    const float* x          = (const float*)d_in[0];
    const float* in_proj_w  = (const float*)d_in[1];
    const float* conv_w     = (const float*)d_in[2];
    const float* conv_b     = (const float*)d_in[3];
    const float* dt_bias    = (const float*)d_in[4];
    const float* A_log      = (const float*)d_in[5];
    const float* Dp         = (const float*)d_in[6];
    const float* norm_w     = (const float*)d_in[7];
    const float* out_proj_w = (const float*)d_in[8];
    const float* cls_w      = (const float*)d_in[9];
    const float* cls_b      = (const float*)d_in[10];
    float* out = (float*)d_out;

    float* zx;
    __half *x16, *w1h;
    cudaGetSymbolAddress((void**)&zx,  g_zx);
    cudaGetSymbolAddress((void**)&x16, g_x16);
    cudaGetSymbolAddress((void**)&w1h, g_w1h);

    cudaFuncSetAttribute(gemm_h256, cudaFuncAttributeMaxDynamicSharedMemorySize, SMEM_BYTES);

    // 0) convert gemm1 operands to fp16; build folded M
    cvt_f16_kernel<<<2048, 256>>>(x,         x16, BL * DM / 4);
    cvt_f16_kernel<<<2048, 256>>>(in_proj_w, w1h, DIP * DM / 4);
    mbuild_kernel<<<DI / 256, 256>>>(out_proj_w, cls_w);
    // 1) exact fp32 dt path
    dt_exact_kernel<<<BL / 32, 256>>>(x, in_proj_w, dt_bias, A_log);
    // 2) in_proj GEMM: (8192,2048) x (8320,2048)^T, half operands, ldc=8448
    {
        dim3 grid(NOUT / 128, BL / 256);
        gemm_h256<<<grid, 256, SMEM_BYTES>>>(x16, w1h, zx, BL, DM, DIP);
    }
    // 3) conv + silu
    conv_prep_kernel<<<BL, 256>>>(conv_w, conv_b);
    // 4) selective scan (+ D*x, silu(z) gate)
    scan_kernel<<<B_ * HN, 64>>>(Dp);
    // 5) RMS norm fused with folded out_proj+classifier
    rmsnorm_cls_kernel<<<BL, 256>>>(norm_w, cls_b, out);
}

// round 10
// speedup vs baseline: 2.4801x; 1.9091x over previous
#include <cuda_runtime.h>
#include <cuda_fp16.h>
#include <math.h>
#include <stdint.h>

#define B_    4
#define L_    2048
#define DM    2048
#define DI    4096
#define DST   64
#define HN    64
#define HP    64
#define CONVD 4224
#define DIP   8448
#define NOUT  8320             // gemm1 columns actually consumed (z + xBC)
#define BL    (B_*L_)          // 8192
#define NCLS  4
#define NSEG  16
#define SEGL  (L_/NSEG)        // 128

// ---------------- scratch (static device globals; no allocation) ----------------
__device__ float  g_zx[BL * DIP];
__device__ float  g_xh[BL * DI];
__device__ float  g_Bm[BL * DST];
__device__ float  g_Cm[BL * DST];
__device__ float  g_dt[BL * HN];
__device__ float  g_dA[BL * HN];
__device__ float  g_y [BL * DI];
__device__ float  g_M [NCLS * DI];
__device__ float  g_cp[BL * HN];                       // within-segment cumprod of dA
__device__ float  g_hend[B_ * HN * NSEG * HP * DST];   // segment-end local states (67MB)
__device__ float  g_h0  [B_ * HN * NSEG * HP * DST];   // segment start states    (67MB)
__device__ __half g_x16[BL * DM];
__device__ __half g_w1h[DIP * DM];

__device__ __forceinline__ size_t sidx(int b, int h, int seg, int p) {
    return ((((size_t)(b * HN + h) * NSEG + seg) * HP) + p) * DST;
}

// ---------------- helpers ----------------
__device__ __forceinline__ uint32_t smem_u32(const void* p) {
    uint32_t a;
    asm("{ .reg .u64 t; cvta.to.shared.u64 t, %1; cvt.u32.u64 %0, t; }" : "=r"(a) : "l"(p));
    return a;
}
__device__ __forceinline__ void cp16(uint32_t saddr, const void* gptr) {
    asm volatile("cp.async.ca.shared.global [%0], [%1], 16;" :: "r"(saddr), "l"(gptr) : "memory");
}
__device__ __forceinline__ void cp_commit() {
    asm volatile("cp.async.commit_group;" ::: "memory");
}
__device__ __forceinline__ void cp_wait2() {
    asm volatile("cp.async.wait_group 2;" ::: "memory");
}
__device__ __forceinline__ void ldsm4(unsigned& r0, unsigned& r1, unsigned& r2, unsigned& r3,
                                      uint32_t addr) {
    asm volatile("ldmatrix.sync.aligned.m8n8.x4.shared.b16 {%0,%1,%2,%3}, [%4];"
                 : "=r"(r0), "=r"(r1), "=r"(r2), "=r"(r3) : "r"(addr));
}
__device__ __forceinline__ void mma_f16(float c[4], const unsigned a[4], const unsigned b[2]) {
    asm volatile(
        "mma.sync.aligned.m16n8k16.row.col.f32.f16.f16.f32 "
        "{%0,%1,%2,%3}, {%4,%5,%6,%7}, {%8,%9}, {%0,%1,%2,%3};"
        : "+f"(c[0]), "+f"(c[1]), "+f"(c[2]), "+f"(c[3])
        : "r"(a[0]), "r"(a[1]), "r"(a[2]), "r"(a[3]),
          "r"(b[0]), "r"(b[1]));
}

#define STAGE_BYTES 24576
#define STAGE_BOFF  16384
#define SMEM_BYTES  (4 * STAGE_BYTES)   // 98304

// ---------------- FP16-operand GEMM, 256x128 CTA tile (unchanged from R9) ----------
__global__ __launch_bounds__(256, 1)
void gemm_h256(const __half* __restrict__ A, const __half* __restrict__ W,
               float* __restrict__ C, int M, int K, int ldc)
{
    extern __shared__ __align__(16) char smem[];
    const uint32_t sb = smem_u32(smem);

    const int tid  = threadIdx.x;
    const int warp = tid >> 5;
    const int lane = tid & 31;
    const int wm = warp >> 1;
    const int wn = warp & 1;
    const int g  = lane >> 2;
    const int t  = lane & 3;
    const int bm = blockIdx.y << 8;
    const int bn = blockIdx.x << 7;

    uint32_t pOff[6];
    const __half* Gp[6];
    #pragma unroll
    for (int j = 0; j < 6; j++) {
        const int c = tid + (j << 8);
        if (c < 1024) {
            const int pr = c >> 2, k8 = c & 3;
            pOff[j] = (uint32_t)(pr * 64 + ((k8 ^ ((pr >> 1) & 3)) << 4));
            Gp[j]   = A + (size_t)(bm + pr) * K + k8 * 8;
        } else {
            const int cb = c - 1024;
            const int pr = cb >> 2, k8 = cb & 3;
            pOff[j] = (uint32_t)(STAGE_BOFF + pr * 64 + ((k8 ^ ((pr >> 1) & 3)) << 4));
            Gp[j]   = W + (size_t)(bn + pr) * K + k8 * 8;
        }
    }

    uint32_t offA[4], swA[4];
    #pragma unroll
    for (int mt = 0; mt < 4; mt++) {
        const int r = wm * 64 + mt * 16 + (lane & 7) + ((lane >> 3) & 1) * 8;
        offA[mt] = (uint32_t)(r * 64);
        swA[mt]  = (uint32_t)((r >> 1) & 3);
    }
    uint32_t offB[4], swB[4];
    #pragma unroll
    for (int h = 0; h < 4; h++) {
        const int r = wn * 64 + h * 16 + (lane & 7) + ((lane >> 4) & 1) * 8;
        offB[h] = (uint32_t)(STAGE_BOFF + r * 64);
        swB[h]  = (uint32_t)((r >> 1) & 3);
    }
    const uint32_t cA = (uint32_t)(lane >> 4);
    const uint32_t cB = (uint32_t)((lane >> 3) & 1);

    float acc[4][8][4];
    #pragma unroll
    for (int i = 0; i < 4; i++)
        #pragma unroll
        for (int j = 0; j < 8; j++)
            #pragma unroll
            for (int c = 0; c < 4; c++) acc[i][j][c] = 0.f;

    const int KT = K >> 5;

    auto issue_stage = [&](int kt, int s) {
        const uint32_t base = sb + s * STAGE_BYTES;
        #pragma unroll
        for (int j = 0; j < 6; j++)
            cp16(base + pOff[j], Gp[j] + kt * 32);
    };

    issue_stage(0, 0); cp_commit();
    issue_stage(1, 1); cp_commit();
    issue_stage(2, 2); cp_commit();
    cp_wait2();
    __syncthreads();

    for (int kt = 0; kt < KT; kt++) {
        const int s = kt & 3;
        const uint32_t base = sb + s * STAGE_BYTES;

        #pragma unroll
        for (int kk = 0; kk < 2; kk++) {
            unsigned a[4][4], b[8][2];
            #pragma unroll
            for (int mt = 0; mt < 4; mt++) {
                const uint32_t ch = (uint32_t)(2 * kk) + cA;
                ldsm4(a[mt][0], a[mt][1], a[mt][2], a[mt][3],
                      base + offA[mt] + ((ch ^ swA[mt]) << 4));
            }
            #pragma unroll
            for (int h = 0; h < 4; h++) {
                const uint32_t ch = (uint32_t)(2 * kk) + cB;
                ldsm4(b[2*h][0], b[2*h][1], b[2*h+1][0], b[2*h+1][1],
                      base + offB[h] + ((ch ^ swB[h]) << 4));
            }
            #pragma unroll
            for (int mt = 0; mt < 4; mt++)
                #pragma unroll
                for (int nt = 0; nt < 8; nt++)
                    mma_f16(acc[mt][nt], a[mt], b[nt]);
        }

        if (kt + 3 < KT) issue_stage(kt + 3, (kt + 3) & 3);
        cp_commit();
        if (kt + 1 < KT) {
            cp_wait2();
            __syncthreads();
        }
    }

    #pragma unroll
    for (int mt = 0; mt < 4; mt++) {
        #pragma unroll
        for (int nt = 0; nt < 8; nt++) {
            const int rr = bm + wm * 64 + mt * 16 + g;
            const int c0 = bn + wn * 64 + nt * 8 + 2 * t;
            *(float2*)&C[(size_t)rr * ldc + c0]       = make_float2(acc[mt][nt][0], acc[mt][nt][1]);
            *(float2*)&C[(size_t)(rr + 8) * ldc + c0] = make_float2(acc[mt][nt][2], acc[mt][nt][3]);
        }
    }
}

// ---------------- f32 -> f16 conversion ----------------
__global__ __launch_bounds__(256)
void cvt_f16_kernel(const float* __restrict__ src, __half* __restrict__ dst, int n4)
{
    int i = blockIdx.x * 256 + threadIdx.x;
    const int stride = gridDim.x * 256;
    for (; i < n4; i += stride) {
        float4 v = *(const float4*)(src + (size_t)i * 4);
        *(__half2*)(dst + (size_t)i * 4)     = __floats2half2_rn(v.x, v.y);
        *(__half2*)(dst + (size_t)i * 4 + 2) = __floats2half2_rn(v.z, v.w);
    }
}

// ---------------- fold M = cls_w @ out_proj ----------------
__global__ __launch_bounds__(256)
void mbuild_kernel(const float* __restrict__ out_proj_w, const float* __restrict__ cls_w)
{
    const int e = blockIdx.x * 256 + threadIdx.x;
    float a0 = 0.f, a1 = 0.f, a2 = 0.f, a3 = 0.f;
    for (int d = 0; d < DM; d++) {
        const float w = __ldg(out_proj_w + (size_t)d * DI + e);
        a0 = fmaf(w, __ldg(cls_w + d),          a0);
        a1 = fmaf(w, __ldg(cls_w + DM + d),     a1);
        a2 = fmaf(w, __ldg(cls_w + 2 * DM + d), a2);
        a3 = fmaf(w, __ldg(cls_w + 3 * DM + d), a3);
    }
    g_M[e]          = a0;
    g_M[DI + e]     = a1;
    g_M[2 * DI + e] = a2;
    g_M[3 * DI + e] = a3;
}

// ---------------- exact fp32 dt path ----------------
__global__ __launch_bounds__(256)
void dt_exact_kernel(const float* __restrict__ x, const float* __restrict__ in_proj_w,
                     const float* __restrict__ dt_bias, const float* __restrict__ A_log)
{
    __shared__ float As[16][36];
    __shared__ float Ws[16][68];
    const int tid = threadIdx.x;
    const int bt0 = blockIdx.x << 5;
    const int tm = tid >> 3;
    const int tn = tid & 7;
    const float* Wdt = in_proj_w + (size_t)(DI + CONVD) * DM;

    float acc[8];
    #pragma unroll
    for (int j = 0; j < 8; j++) acc[j] = 0.f;

    for (int k0 = 0; k0 < DM; k0 += 16) {
        if (tid < 128) {
            const int r = tid >> 2;
            const int kk = (tid & 3) << 2;
            float4 v = *(const float4*)(x + (size_t)(bt0 + r) * DM + k0 + kk);
            As[kk + 0][r] = v.x; As[kk + 1][r] = v.y;
            As[kk + 2][r] = v.z; As[kk + 3][r] = v.w;
        }
        {
            const int r = tid >> 2;
            const int kk = (tid & 3) << 2;
            float4 w = *(const float4*)(Wdt + (size_t)r * DM + k0 + kk);
            Ws[kk + 0][r] = w.x; Ws[kk + 1][r] = w.y;
            Ws[kk + 2][r] = w.z; Ws[kk + 3][r] = w.w;
        }
        __syncthreads();
        #pragma unroll
        for (int k = 0; k < 16; k++) {
            const float a = As[k][tm];
            #pragma unroll
            for (int j = 0; j < 8; j++)
                acc[j] = fmaf(a, Ws[k][tn + j * 8], acc[j]);
        }
        __syncthreads();
    }
    #pragma unroll
    for (int j = 0; j < 8; j++) {
        const int bt = bt0 + tm;
        const int h  = tn + j * 8;
        float dtr = acc[j] + __ldg(dt_bias + h);
        float dts = (dtr > 20.f) ? dtr : log1pf(expf(dtr));
        g_dt[bt * HN + h] = dts;
        g_dA[bt * HN + h] = expf(-expf(__ldg(A_log + h)) * dts);
    }
}

// ---------------- conv1d(depthwise, width 4) + SiLU ----------------
__global__ void conv_prep_kernel(const float* __restrict__ conv_w,
                                 const float* __restrict__ conv_b)
{
    const int bt = blockIdx.x;
    const int b  = bt / L_;
    const int t  = bt % L_;

    for (int c = threadIdx.x; c < CONVD; c += blockDim.x) {
        float4 wv = *(const float4*)(conv_w + c * 4);
        float s = conv_b[c];
        const float wk[4] = {wv.x, wv.y, wv.z, wv.w};
        #pragma unroll
        for (int k = 0; k < 4; k++) {
            int tt = t - 3 + k;
            float xv = (tt >= 0) ? g_zx[(size_t)(b * L_ + tt) * DIP + DI + c] : 0.f;
            s = fmaf(xv, wk[k], s);
        }
        float sil = s / (1.f + expf(-s));
        if (c < DI)            g_xh[(size_t)bt * DI + c]       = sil;
        else if (c < DI + DST) g_Bm[bt * DST + (c - DI)]        = sil;
        else                   g_Cm[bt * DST + (c - DI - DST)]  = sil;
    }
}

// ---------------- chunked scan: pass A — local scans with h0 = 0 ----------------
// grid = b*h*NSEG (seg fastest), 64 threads = p. Writes local y, cumP, segment-end state.
__global__ __launch_bounds__(64)
void scan_local_kernel()
{
    const int seg = blockIdx.x & (NSEG - 1);
    const int bh  = blockIdx.x >> 4;
    const int b = bh >> 6;
    const int h = bh & 63;
    const int p = threadIdx.x;

    float hs[DST];
    #pragma unroll
    for (int n = 0; n < DST; n++) hs[n] = 0.f;
    float cum = 1.f;

    const int t0 = seg * SEGL;
    for (int t = t0; t < t0 + SEGL; t++) {
        const int bt = b * L_ + t;
        const float dA = __ldg(&g_dA[bt * HN + h]);
        const float dt = __ldg(&g_dt[bt * HN + h]);
        const float xv = g_xh[(size_t)bt * DI + h * HP + p];
        const float u  = dt * xv;
        cum *= dA;
        const float4* Bv = (const float4*)(g_Bm + bt * DST);
        const float4* Cv = (const float4*)(g_Cm + bt * DST);
        float ac[8];
        #pragma unroll
        for (int i = 0; i < 8; i++) ac[i] = 0.f;
        #pragma unroll
        for (int j = 0; j < 16; j++) {
            float4 Bq = __ldg(&Bv[j]);
            float4 Cq = __ldg(&Cv[j]);
            const int o = (j & 1) << 2;
            hs[4*j+0] = fmaf(hs[4*j+0], dA, u * Bq.x); ac[o+0] = fmaf(hs[4*j+0], Cq.x, ac[o+0]);
            hs[4*j+1] = fmaf(hs[4*j+1], dA, u * Bq.y); ac[o+1] = fmaf(hs[4*j+1], Cq.y, ac[o+1]);
            hs[4*j+2] = fmaf(hs[4*j+2], dA, u * Bq.z); ac[o+2] = fmaf(hs[4*j+2], Cq.z, ac[o+2]);
            hs[4*j+3] = fmaf(hs[4*j+3], dA, u * Bq.w); ac[o+3] = fmaf(hs[4*j+3], Cq.w, ac[o+3]);
        }
        g_y[(size_t)bt * DI + h * HP + p] =
            ((ac[0] + ac[4]) + (ac[1] + ac[5])) + ((ac[2] + ac[6]) + (ac[3] + ac[7]));
        if (p == 0) g_cp[bt * HN + h] = cum;
    }
    float4* He = (float4*)&g_hend[sidx(b, h, seg, p)];
    #pragma unroll
    for (int j = 0; j < 16; j++)
        He[j] = make_float4(hs[4*j], hs[4*j+1], hs[4*j+2], hs[4*j+3]);
}

// ---------------- chunked scan: pass B — stitch segment start states ----------------
// grid = b*h = 256, 64 threads = p.
__global__ __launch_bounds__(64)
void scan_combine_kernel()
{
    const int b = blockIdx.x >> 6;
    const int h = blockIdx.x & 63;
    const int p = threadIdx.x;

    float h0[DST];
    #pragma unroll
    for (int n = 0; n < DST; n++) h0[n] = 0.f;

    for (int k = 0; k < NSEG; k++) {
        float4* H0 = (float4*)&g_h0[sidx(b, h, k, p)];
        #pragma unroll
        for (int j = 0; j < 16; j++)
            H0[j] = make_float4(h0[4*j], h0[4*j+1], h0[4*j+2], h0[4*j+3]);
        const float Pend = __ldg(&g_cp[(b * L_ + k * SEGL + SEGL - 1) * HN + h]);
        const float4* He = (const float4*)&g_hend[sidx(b, h, k, p)];
        #pragma unroll
        for (int j = 0; j < 16; j++) {
            float4 e = __ldg(&He[j]);
            h0[4*j+0] = fmaf(h0[4*j+0], Pend, e.x);
            h0[4*j+1] = fmaf(h0[4*j+1], Pend, e.y);
            h0[4*j+2] = fmaf(h0[4*j+2], Pend, e.z);
            h0[4*j+3] = fmaf(h0[4*j+3], Pend, e.w);
        }
    }
}

// ---------------- chunked scan: pass C — correction + D*x + silu(z) gate ----------------
// grid = b*h*NSEG, 64 threads = p.
__global__ __launch_bounds__(64)
void scan_fix_kernel(const float* __restrict__ Dp)
{
    const int seg = blockIdx.x & (NSEG - 1);
    const int bh  = blockIdx.x >> 4;
    const int b = bh >> 6;
    const int h = bh & 63;
    const int p = threadIdx.x;
    const float Dh = __ldg(Dp + h);

    float h0[DST];
    {
        const float4* H0 = (const float4*)&g_h0[sidx(b, h, seg, p)];
        #pragma unroll
        for (int j = 0; j < 16; j++) {
            float4 v = __ldg(&H0[j]);
            h0[4*j] = v.x; h0[4*j+1] = v.y; h0[4*j+2] = v.z; h0[4*j+3] = v.w;
        }
    }

    const int t0 = seg * SEGL;
    for (int t = t0; t < t0 + SEGL; t++) {
        const int bt = b * L_ + t;
        const float cum = __ldg(&g_cp[bt * HN + h]);
        const float xv  = g_xh[(size_t)bt * DI + h * HP + p];
        const float z   = g_zx[(size_t)bt * DIP + h * HP + p];
        const float yl  = g_y[(size_t)bt * DI + h * HP + p];
        const float4* Cv = (const float4*)(g_Cm + bt * DST);
        float ac[8];
        #pragma unroll
        for (int i = 0; i < 8; i++) ac[i] = 0.f;
        #pragma unroll
        for (int j = 0; j < 16; j++) {
            float4 Cq = __ldg(&Cv[j]);
            const int o = (j & 1) << 2;
            ac[o+0] = fmaf(h0[4*j+0], Cq.x, ac[o+0]);
            ac[o+1] = fmaf(h0[4*j+1], Cq.y, ac[o+1]);
            ac[o+2] = fmaf(h0[4*j+2], Cq.z, ac[o+2]);
            ac[o+3] = fmaf(h0[4*j+3], Cq.w, ac[o+3]);
        }
        const float dotC = ((ac[0] + ac[4]) + (ac[1] + ac[5])) + ((ac[2] + ac[6]) + (ac[3] + ac[7]));
        const float y = yl + cum * dotC + Dh * xv;
        const float gate = z / (1.f + expf(-z));
        g_y[(size_t)bt * DI + h * HP + p] = y * gate;
    }
}

// ---------------- RMS norm + folded (out_proj ∘ classifier) ----------------
__global__ __launch_bounds__(256)
void rmsnorm_cls_kernel(const float* __restrict__ norm_w,
                        const float* __restrict__ cls_b, float* __restrict__ out)
{
    const int bt = blockIdx.x;
    const float* row = g_y + (size_t)bt * DI;
    float v[16];
    float ss = 0.f;
    #pragma unroll
    for (int i = 0; i < 16; i++) {
        v[i] = row[threadIdx.x + i * 256];
        ss = fmaf(v[i], v[i], ss);
    }
    #pragma unroll
    for (int o = 16; o > 0; o >>= 1) ss += __shfl_xor_sync(0xffffffffu, ss, o);
    __shared__ float sred[8];
    const int lane = threadIdx.x & 31, warp = threadIdx.x >> 5;
    if (lane == 0) sred[warp] = ss;
    __syncthreads();
    float tot = 0.f;
    #pragma unroll
    for (int w = 0; w < 8; w++) tot += sred[w];
    const float scale = rsqrtf(tot * (1.f / DI) + 1e-5f);

    float a0 = 0.f, a1 = 0.f, a2 = 0.f, a3 = 0.f;
    #pragma unroll
    for (int i = 0; i < 16; i++) {
        const int c = threadIdx.x + i * 256;
        const float yn = v[i] * scale * __ldg(norm_w + c);
        a0 = fmaf(yn, __ldg(&g_M[c]),          a0);
        a1 = fmaf(yn, __ldg(&g_M[DI + c]),     a1);
        a2 = fmaf(yn, __ldg(&g_M[2 * DI + c]), a2);
        a3 = fmaf(yn, __ldg(&g_M[3 * DI + c]), a3);
    }
    #pragma unroll
    for (int o = 16; o > 0; o >>= 1) {
        a0 += __shfl_xor_sync(0xffffffffu, a0, o);
        a1 += __shfl_xor_sync(0xffffffffu, a1, o);
        a2 += __shfl_xor_sync(0xffffffffu, a2, o);
        a3 += __shfl_xor_sync(0xffffffffu, a3, o);
    }
    __shared__ float s4[8][4];
    if (lane == 0) { s4[warp][0] = a0; s4[warp][1] = a1; s4[warp][2] = a2; s4[warp][3] = a3; }
    __syncthreads();
    if (threadIdx.x < 4) {
        float s = __ldg(cls_b + threadIdx.x);
        #pragma unroll
        for (int w = 0; w < 8; w++) s += s4[w][threadIdx.x];
        out[bt * NCLS + threadIdx.x] = s;
    }
}

// ---------------- launcher ----------------
extern "C" void kernel_launch(void* const* d_in, const int* in_sizes, int n_in,
                              void* d_out, int out_size)
{
    (void)in_sizes; (void)n_in; (void)out_size;
    const float* x          = (const float*)d_in[0];
    const float* in_proj_w  = (const float*)d_in[1];
    const float* conv_w     = (const float*)d_in[2];
    const float* conv_b     = (const float*)d_in[3];
    const float* dt_bias    = (const float*)d_in[4];
    const float* A_log      = (const float*)d_in[5];
    const float* Dp         = (const float*)d_in[6];
    const float* norm_w     = (const float*)d_in[7];
    const float* out_proj_w = (const float*)d_in[8];
    const float* cls_w      = (const float*)d_in[9];
    const float* cls_b      = (const float*)d_in[10];
    float* out = (float*)d_out;

    float* zx;
    __half *x16, *w1h;
    cudaGetSymbolAddress((void**)&zx,  g_zx);
    cudaGetSymbolAddress((void**)&x16, g_x16);
    cudaGetSymbolAddress((void**)&w1h, g_w1h);

    cudaFuncSetAttribute(gemm_h256, cudaFuncAttributeMaxDynamicSharedMemorySize, SMEM_BYTES);

    // 1-2) convert gemm1 operands to fp16
    cvt_f16_kernel<<<2048, 256>>>(x,         x16, BL * DM / 4);
    cvt_f16_kernel<<<2048, 256>>>(in_proj_w, w1h, DIP * DM / 4);
    // 3) build folded M
    mbuild_kernel<<<DI / 256, 256>>>(out_proj_w, cls_w);
    // 4) in_proj GEMM  (4th launch — ncu capture target)
    {
        dim3 grid(NOUT / 128, BL / 256);
        gemm_h256<<<grid, 256, SMEM_BYTES>>>(x16, w1h, zx, BL, DM, DIP);
    }
    // 5) exact fp32 dt path
    dt_exact_kernel<<<BL / 32, 256>>>(x, in_proj_w, dt_bias, A_log);
    // 6) conv + silu
    conv_prep_kernel<<<BL, 256>>>(conv_w, conv_b);
    // 7-9) chunked selective scan
    scan_local_kernel<<<B_ * HN * NSEG, 64>>>();
    scan_combine_kernel<<<B_ * HN, 64>>>();
    scan_fix_kernel<<<B_ * HN * NSEG, 64>>>(Dp);
    // 10) RMS norm fused with folded out_proj+classifier
    rmsnorm_cls_kernel<<<BL, 256>>>(norm_w, cls_b, out);
}

// round 11
// speedup vs baseline: 4.1467x; 1.6720x over previous
#include <cuda_runtime.h>
#include <cuda_fp16.h>
#include <math.h>
#include <stdint.h>

#define B_    4
#define L_    2048
#define DM    2048
#define DI    4096
#define DST   64
#define HN    64
#define HP    64
#define CONVD 4224
#define DIP   8448
#define NOUT  8320
#define BL    (B_*L_)          // 8192
#define NCLS  4
#define TC    64               // segment length
#define NSEG  (L_/TC)          // 32
#define SROW  76               // smem row stride (floats)

// ---------------- scratch (static device globals; no allocation) ----------------
__device__ float  g_zx[BL * DIP];
__device__ float  g_xh[BL * DI];
__device__ float  g_Bm[BL * DST];
__device__ float  g_Cm[BL * DST];
__device__ float  g_dt[BL * HN];
__device__ float  g_a [BL * HN];                       // log dA = -exp(A_log)*dt
__device__ float  g_y [BL * DI];
__device__ float  g_M [NCLS * DI];
__device__ float  g_cp[BL * HN];                       // exp(cumsum a) within segment
__device__ float  g_hend[(size_t)B_ * HN * NSEG * HP * DST];  // [n][p] per (b,h,seg)
__device__ float  g_h0  [(size_t)B_ * HN * NSEG * HP * DST];
__device__ __half g_x16[BL * DM];
__device__ __half g_w1h[DIP * DM];

// ---------------- helpers ----------------
__device__ __forceinline__ uint32_t smem_u32(const void* p) {
    uint32_t a;
    asm("{ .reg .u64 t; cvta.to.shared.u64 t, %1; cvt.u32.u64 %0, t; }" : "=r"(a) : "l"(p));
    return a;
}
__device__ __forceinline__ void cp16(uint32_t saddr, const void* gptr) {
    asm volatile("cp.async.ca.shared.global [%0], [%1], 16;" :: "r"(saddr), "l"(gptr) : "memory");
}
__device__ __forceinline__ void cp_commit() {
    asm volatile("cp.async.commit_group;" ::: "memory");
}
__device__ __forceinline__ void cp_wait2() {
    asm volatile("cp.async.wait_group 2;" ::: "memory");
}
__device__ __forceinline__ void ldsm4(unsigned& r0, unsigned& r1, unsigned& r2, unsigned& r3,
                                      uint32_t addr) {
    asm volatile("ldmatrix.sync.aligned.m8n8.x4.shared.b16 {%0,%1,%2,%3}, [%4];"
                 : "=r"(r0), "=r"(r1), "=r"(r2), "=r"(r3) : "r"(addr));
}
__device__ __forceinline__ void mma_f16(float c[4], const unsigned a[4], const unsigned b[2]) {
    asm volatile(
        "mma.sync.aligned.m16n8k16.row.col.f32.f16.f16.f32 "
        "{%0,%1,%2,%3}, {%4,%5,%6,%7}, {%8,%9}, {%0,%1,%2,%3};"
        : "+f"(c[0]), "+f"(c[1]), "+f"(c[2]), "+f"(c[3])
        : "r"(a[0]), "r"(a[1]), "r"(a[2]), "r"(a[3]),
          "r"(b[0]), "r"(b[1]));
}

#define STAGE_BYTES 24576
#define STAGE_BOFF  16384
#define SMEM_BYTES  (4 * STAGE_BYTES)   // 98304
#define SSD_SMEM    (4 * 64 * SROW * 4 + 4 * 64 * 4)   // 78848+1024

// ---------------- FP16-operand GEMM, 256x128 CTA tile (unchanged) ----------------
__global__ __launch_bounds__(256, 1)
void gemm_h256(const __half* __restrict__ A, const __half* __restrict__ W,
               float* __restrict__ C, int M, int K, int ldc)
{
    extern __shared__ __align__(16) char smem[];
    const uint32_t sb = smem_u32(smem);

    const int tid  = threadIdx.x;
    const int warp = tid >> 5;
    const int lane = tid & 31;
    const int wm = warp >> 1;
    const int wn = warp & 1;
    const int g  = lane >> 2;
    const int t  = lane & 3;
    const int bm = blockIdx.y << 8;
    const int bn = blockIdx.x << 7;

    uint32_t pOff[6];
    const __half* Gp[6];
    #pragma unroll
    for (int j = 0; j < 6; j++) {
        const int c = tid + (j << 8);
        if (c < 1024) {
            const int pr = c >> 2, k8 = c & 3;
            pOff[j] = (uint32_t)(pr * 64 + ((k8 ^ ((pr >> 1) & 3)) << 4));
            Gp[j]   = A + (size_t)(bm + pr) * K + k8 * 8;
        } else {
            const int cb = c - 1024;
            const int pr = cb >> 2, k8 = cb & 3;
            pOff[j] = (uint32_t)(STAGE_BOFF + pr * 64 + ((k8 ^ ((pr >> 1) & 3)) << 4));
            Gp[j]   = W + (size_t)(bn + pr) * K + k8 * 8;
        }
    }

    uint32_t offA[4], swA[4];
    #pragma unroll
    for (int mt = 0; mt < 4; mt++) {
        const int r = wm * 64 + mt * 16 + (lane & 7) + ((lane >> 3) & 1) * 8;
        offA[mt] = (uint32_t)(r * 64);
        swA[mt]  = (uint32_t)((r >> 1) & 3);
    }
    uint32_t offB[4], swB[4];
    #pragma unroll
    for (int h = 0; h < 4; h++) {
        const int r = wn * 64 + h * 16 + (lane & 7) + ((lane >> 4) & 1) * 8;
        offB[h] = (uint32_t)(STAGE_BOFF + r * 64);
        swB[h]  = (uint32_t)((r >> 1) & 3);
    }
    const uint32_t cA = (uint32_t)(lane >> 4);
    const uint32_t cB = (uint32_t)((lane >> 3) & 1);

    float acc[4][8][4];
    #pragma unroll
    for (int i = 0; i < 4; i++)
        #pragma unroll
        for (int j = 0; j < 8; j++)
            #pragma unroll
            for (int c = 0; c < 4; c++) acc[i][j][c] = 0.f;

    const int KT = K >> 5;

    auto issue_stage = [&](int kt, int s) {
        const uint32_t base = sb + s * STAGE_BYTES;
        #pragma unroll
        for (int j = 0; j < 6; j++)
            cp16(base + pOff[j], Gp[j] + kt * 32);
    };

    issue_stage(0, 0); cp_commit();
    issue_stage(1, 1); cp_commit();
    issue_stage(2, 2); cp_commit();
    cp_wait2();
    __syncthreads();

    for (int kt = 0; kt < KT; kt++) {
        const int s = kt & 3;
        const uint32_t base = sb + s * STAGE_BYTES;

        #pragma unroll
        for (int kk = 0; kk < 2; kk++) {
            unsigned a[4][4], b[8][2];
            #pragma unroll
            for (int mt = 0; mt < 4; mt++) {
                const uint32_t ch = (uint32_t)(2 * kk) + cA;
                ldsm4(a[mt][0], a[mt][1], a[mt][2], a[mt][3],
                      base + offA[mt] + ((ch ^ swA[mt]) << 4));
            }
            #pragma unroll
            for (int h = 0; h < 4; h++) {
                const uint32_t ch = (uint32_t)(2 * kk) + cB;
                ldsm4(b[2*h][0], b[2*h][1], b[2*h+1][0], b[2*h+1][1],
                      base + offB[h] + ((ch ^ swB[h]) << 4));
            }
            #pragma unroll
            for (int mt = 0; mt < 4; mt++)
                #pragma unroll
                for (int nt = 0; nt < 8; nt++)
                    mma_f16(acc[mt][nt], a[mt], b[nt]);
        }

        if (kt + 3 < KT) issue_stage(kt + 3, (kt + 3) & 3);
        cp_commit();
        if (kt + 1 < KT) {
            cp_wait2();
            __syncthreads();
        }
    }

    #pragma unroll
    for (int mt = 0; mt < 4; mt++) {
        #pragma unroll
        for (int nt = 0; nt < 8; nt++) {
            const int rr = bm + wm * 64 + mt * 16 + g;
            const int c0 = bn + wn * 64 + nt * 8 + 2 * t;
            *(float2*)&C[(size_t)rr * ldc + c0]       = make_float2(acc[mt][nt][0], acc[mt][nt][1]);
            *(float2*)&C[(size_t)(rr + 8) * ldc + c0] = make_float2(acc[mt][nt][2], acc[mt][nt][3]);
        }
    }
}

// ---------------- f32 -> f16 conversion ----------------
__global__ __launch_bounds__(256)
void cvt_f16_kernel(const float* __restrict__ src, __half* __restrict__ dst, int n4)
{
    int i = blockIdx.x * 256 + threadIdx.x;
    const int stride = gridDim.x * 256;
    for (; i < n4; i += stride) {
        float4 v = *(const float4*)(src + (size_t)i * 4);
        *(__half2*)(dst + (size_t)i * 4)     = __floats2half2_rn(v.x, v.y);
        *(__half2*)(dst + (size_t)i * 4 + 2) = __floats2half2_rn(v.z, v.w);
    }
}

// ---------------- fold M = cls_w @ out_proj ----------------
__global__ __launch_bounds__(256)
void mbuild_kernel(const float* __restrict__ out_proj_w, const float* __restrict__ cls_w)
{
    const int e = blockIdx.x * 256 + threadIdx.x;
    float a0 = 0.f, a1 = 0.f, a2 = 0.f, a3 = 0.f;
    for (int d = 0; d < DM; d++) {
        const float w = __ldg(out_proj_w + (size_t)d * DI + e);
        a0 = fmaf(w, __ldg(cls_w + d),          a0);
        a1 = fmaf(w, __ldg(cls_w + DM + d),     a1);
        a2 = fmaf(w, __ldg(cls_w + 2 * DM + d), a2);
        a3 = fmaf(w, __ldg(cls_w + 3 * DM + d), a3);
    }
    g_M[e]          = a0;
    g_M[DI + e]     = a1;
    g_M[2 * DI + e] = a2;
    g_M[3 * DI + e] = a3;
}

// ---------------- exact fp32 dt path (also writes log-dA) ----------------
__global__ __launch_bounds__(256)
void dt_exact_kernel(const float* __restrict__ x, const float* __restrict__ in_proj_w,
                     const float* __restrict__ dt_bias, const float* __restrict__ A_log)
{
    __shared__ float As[16][36];
    __shared__ float Ws[16][68];
    const int tid = threadIdx.x;
    const int bt0 = blockIdx.x << 5;
    const int tm = tid >> 3;
    const int tn = tid & 7;
    const float* Wdt = in_proj_w + (size_t)(DI + CONVD) * DM;

    float acc[8];
    #pragma unroll
    for (int j = 0; j < 8; j++) acc[j] = 0.f;

    for (int k0 = 0; k0 < DM; k0 += 16) {
        if (tid < 128) {
            const int r = tid >> 2;
            const int kk = (tid & 3) << 2;
            float4 v = *(const float4*)(x + (size_t)(bt0 + r) * DM + k0 + kk);
            As[kk + 0][r] = v.x; As[kk + 1][r] = v.y;
            As[kk + 2][r] = v.z; As[kk + 3][r] = v.w;
        }
        {
            const int r = tid >> 2;
            const int kk = (tid & 3) << 2;
            float4 w = *(const float4*)(Wdt + (size_t)r * DM + k0 + kk);
            Ws[kk + 0][r] = w.x; Ws[kk + 1][r] = w.y;
            Ws[kk + 2][r] = w.z; Ws[kk + 3][r] = w.w;
        }
        __syncthreads();
        #pragma unroll
        for (int k = 0; k < 16; k++) {
            const float a = As[k][tm];
            #pragma unroll
            for (int j = 0; j < 8; j++)
                acc[j] = fmaf(a, Ws[k][tn + j * 8], acc[j]);
        }
        __syncthreads();
    }
    #pragma unroll
    for (int j = 0; j < 8; j++) {
        const int bt = bt0 + tm;
        const int h  = tn + j * 8;
        float dtr = acc[j] + __ldg(dt_bias + h);
        float dts = (dtr > 20.f) ? dtr : log1pf(expf(dtr));
        g_dt[bt * HN + h] = dts;
        g_a [bt * HN + h] = -expf(__ldg(A_log + h)) * dts;
    }
}

// ---------------- conv1d(depthwise, width 4) + SiLU ----------------
__global__ void conv_prep_kernel(const float* __restrict__ conv_w,
                                 const float* __restrict__ conv_b)
{
    const int bt = blockIdx.x;
    const int b  = bt / L_;
    const int t  = bt % L_;

    for (int c = threadIdx.x; c < CONVD; c += blockDim.x) {
        float4 wv = *(const float4*)(conv_w + c * 4);
        float s = conv_b[c];
        const float wk[4] = {wv.x, wv.y, wv.z, wv.w};
        #pragma unroll
        for (int k = 0; k < 4; k++) {
            int tt = t - 3 + k;
            float xv = (tt >= 0) ? g_zx[(size_t)(b * L_ + tt) * DIP + DI + c] : 0.f;
            s = fmaf(xv, wk[k], s);
        }
        float sil = s / (1.f + expf(-s));
        if (c < DI)            g_xh[(size_t)bt * DI + c]       = sil;
        else if (c < DI + DST) g_Bm[bt * DST + (c - DI)]        = sil;
        else                   g_Cm[bt * DST + (c - DI - DST)]  = sil;
    }
}

// ---------------- SSD segment kernel: local Y + segment-end state ----------------
// block per (b,h,seg), 256 threads. Tc=64.
__global__ __launch_bounds__(256)
void seg_ssd_kernel()
{
    extern __shared__ __align__(16) float sm[];
    float* Ct  = sm;                 // [64][SROW] C rows (t, cols n)
    float* Bsm = sm + 64 * SROW;     // [64][SROW] B rows (s, cols n)
    float* Xs  = sm + 2 * 64 * SROW; // [64][SROW] x rows (s, cols p)
    float* Ms  = sm + 3 * 64 * SROW; // [64][SROW] M[s][t]
    float* Acs = sm + 4 * 64 * SROW; // [64]
    float* dtss = Acs + 64;
    float* cums = Acs + 128;
    float* wss  = Acs + 192;

    const int tid = threadIdx.x;
    const int seg = blockIdx.x & (NSEG - 1);
    const int bh  = blockIdx.x >> 5;          // NSEG == 32
    const int b = bh >> 6, h = bh & 63;
    const int btbase = b * L_ + seg * TC;

    // cooperative tile loads (each thread: one row quarter = 4 float4)
    {
        const int lr = tid >> 2;
        const int lc = (tid & 3) << 4;
        const float* gB = g_Bm + (size_t)(btbase + lr) * DST + lc;
        const float* gC = g_Cm + (size_t)(btbase + lr) * DST + lc;
        const float* gX = g_xh + (size_t)(btbase + lr) * DI + h * HP + lc;
        #pragma unroll
        for (int q = 0; q < 4; q++) {
            *(float4*)&Bsm[lr * SROW + lc + q * 4] = *(const float4*)(gB + q * 4);
            *(float4*)&Ct [lr * SROW + lc + q * 4] = *(const float4*)(gC + q * 4);
            *(float4*)&Xs [lr * SROW + lc + q * 4] = *(const float4*)(gX + q * 4);
        }
    }
    if (tid < 64) {
        dtss[tid] = g_dt[(btbase + tid) * HN + h];
        Acs[tid]  = g_a [(btbase + tid) * HN + h];
    }
    __syncthreads();
    // inclusive cumsum of Acs (Hillis-Steele)
    #pragma unroll
    for (int off = 1; off < 64; off <<= 1) {
        float v = 0.f;
        if (tid < 64 && tid >= off) v = Acs[tid - off];
        __syncthreads();
        if (tid < 64) Acs[tid] += v;
        __syncthreads();
    }
    if (tid < 64) {
        cums[tid] = __expf(Acs[tid]);
        wss[tid]  = __expf(Acs[63] - Acs[tid]) * dtss[tid];
        g_cp[(btbase + tid) * HN + h] = cums[tid];
    }
    __syncthreads();

    const int it = tid >> 4;          // 0..15
    const int jp = tid & 15;          // 0..15
    const int t0 = it << 2;
    const int j0 = jp << 2;           // s0 / p0 / n0

    // GEMM1: S[t][s] = sum_n C[t][n] * B[s][n]   (skip fully-upper tiles)
    float S[4][4];
    #pragma unroll
    for (int i = 0; i < 4; i++)
        #pragma unroll
        for (int j = 0; j < 4; j++) S[i][j] = 0.f;
    if (j0 <= t0 + 3) {
        for (int n = 0; n < 64; n += 4) {
            float4 cv[4], bv[4];
            #pragma unroll
            for (int i = 0; i < 4; i++) cv[i] = *(const float4*)&Ct[(t0 + i) * SROW + n];
            #pragma unroll
            for (int j = 0; j < 4; j++) bv[j] = *(const float4*)&Bsm[(j0 + j) * SROW + n];
            #pragma unroll
            for (int i = 0; i < 4; i++)
                #pragma unroll
                for (int j = 0; j < 4; j++)
                    S[i][j] += cv[i].x * bv[j].x + cv[i].y * bv[j].y
                             + cv[i].z * bv[j].z + cv[i].w * bv[j].w;
        }
    }
    // mask + decay weight, store transposed M[s][t]
    #pragma unroll
    for (int i = 0; i < 4; i++)
        #pragma unroll
        for (int j = 0; j < 4; j++) {
            const int t = t0 + i, s = j0 + j;
            const float m = (s <= t) ? __expf(Acs[t] - Acs[s]) * dtss[s] : 0.f;
            Ms[s * SROW + t] = S[i][j] * m;
        }
    __syncthreads();

    // GEMM2 (Y[t][p] = sum_s M[t][s] X[s][p]) + GEMM3 (Hend[n][p] = sum_s B[s][n] w_s X[s][p])
    float Y[4][4], Hn[4][4];
    #pragma unroll
    for (int i = 0; i < 4; i++)
        #pragma unroll
        for (int j = 0; j < 4; j++) { Y[i][j] = 0.f; Hn[i][j] = 0.f; }
    for (int s = 0; s < 64; s++) {
        const float4 xv = *(const float4*)&Xs[s * SROW + j0];
        const float4 mv = *(const float4*)&Ms[s * SROW + t0];
        const float4 bv = *(const float4*)&Bsm[s * SROW + t0];
        const float w = wss[s];
        const float xa[4] = {xv.x, xv.y, xv.z, xv.w};
        const float wx[4] = {xv.x * w, xv.y * w, xv.z * w, xv.w * w};
        const float ma[4] = {mv.x, mv.y, mv.z, mv.w};
        const float ba[4] = {bv.x, bv.y, bv.z, bv.w};
        #pragma unroll
        for (int i = 0; i < 4; i++)
            #pragma unroll
            for (int j = 0; j < 4; j++) {
                Y[i][j]  = fmaf(ma[i], xa[j], Y[i][j]);
                Hn[i][j] = fmaf(ba[i], wx[j], Hn[i][j]);
            }
    }
    #pragma unroll
    for (int i = 0; i < 4; i++)
        *(float4*)&g_y[(size_t)(btbase + t0 + i) * DI + h * HP + j0] =
            make_float4(Y[i][0], Y[i][1], Y[i][2], Y[i][3]);
    const size_t hb = ((size_t)bh * NSEG + seg) * (DST * HP);
    #pragma unroll
    for (int i = 0; i < 4; i++)
        *(float4*)&g_hend[hb + (size_t)(t0 + i) * HP + j0] =
            make_float4(Hn[i][0], Hn[i][1], Hn[i][2], Hn[i][3]);
}

// ---------------- combine: elementwise stitch of segment states ----------------
__global__ __launch_bounds__(256)
void scan_combine_kernel()
{
    const int bh  = blockIdx.x;       // 0..255
    const int tid = threadIdx.x;
    const int b = bh >> 6, h = bh & 63;
    float4 st[4];
    #pragma unroll
    for (int q = 0; q < 4; q++) st[q] = make_float4(0.f, 0.f, 0.f, 0.f);
    const size_t base0 = (size_t)bh * NSEG * (DST * HP);
    for (int k = 0; k < NSEG; k++) {
        const size_t off = base0 + (size_t)k * (DST * HP) + (size_t)tid * 16;
        #pragma unroll
        for (int q = 0; q < 4; q++) *(float4*)&g_h0[off + q * 4] = st[q];
        const float Pend = __ldg(&g_cp[(b * L_ + k * TC + TC - 1) * HN + h]);
        #pragma unroll
        for (int q = 0; q < 4; q++) {
            float4 e = __ldg((const float4*)&g_hend[off + q * 4]);
            st[q].x = fmaf(st[q].x, Pend, e.x);
            st[q].y = fmaf(st[q].y, Pend, e.y);
            st[q].z = fmaf(st[q].z, Pend, e.z);
            st[q].w = fmaf(st[q].w, Pend, e.w);
        }
    }
}

// ---------------- fix: y += cum_t * (C_t · h0) + D*x, then silu(z) gate ----------------
__global__ __launch_bounds__(256)
void scan_fix_kernel(const float* __restrict__ Dp)
{
    __shared__ float Ctf[64 * SROW];
    __shared__ float H0s[64 * SROW];     // [n][p]
    __shared__ float cumf[64];

    const int tid = threadIdx.x;
    const int seg = blockIdx.x & (NSEG - 1);
    const int bh  = blockIdx.x >> 5;
    const int b = bh >> 6, h = bh & 63;
    const int btbase = b * L_ + seg * TC;

    {
        const int lr = tid >> 2;
        const int lc = (tid & 3) << 4;
        const float* gC = g_Cm + (size_t)(btbase + lr) * DST + lc;
        const size_t hb = ((size_t)bh * NSEG + seg) * (DST * HP);
        const float* gH = g_h0 + hb + (size_t)lr * HP + lc;
        #pragma unroll
        for (int q = 0; q < 4; q++) {
            *(float4*)&Ctf[lr * SROW + lc + q * 4] = *(const float4*)(gC + q * 4);
            *(float4*)&H0s[lr * SROW + lc + q * 4] = *(const float4*)(gH + q * 4);
        }
    }
    if (tid < 64) cumf[tid] = g_cp[(btbase + tid) * HN + h];
    __syncthreads();

    const int it = tid >> 4;
    const int jp = tid & 15;
    const int t0 = it << 2;
    const int p0 = jp << 2;

    float acc[4][4];
    #pragma unroll
    for (int i = 0; i < 4; i++)
        #pragma unroll
        for (int j = 0; j < 4; j++) acc[i][j] = 0.f;
    for (int n = 0; n < 64; n++) {
        const float4 hv = *(const float4*)&H0s[n * SROW + p0];
        const float ha[4] = {hv.x, hv.y, hv.z, hv.w};
        #pragma unroll
        for (int i = 0; i < 4; i++) {
            const float c = Ctf[(t0 + i) * SROW + n];
            #pragma unroll
            for (int j = 0; j < 4; j++)
                acc[i][j] = fmaf(c, ha[j], acc[i][j]);
        }
    }

    const float Dh = __ldg(Dp + h);
    #pragma unroll
    for (int i = 0; i < 4; i++) {
        const int bt = btbase + t0 + i;
        const size_t yoff = (size_t)bt * DI + h * HP + p0;
        float4 yl = *(float4*)&g_y[yoff];
        const float4 xv = *(const float4*)&g_xh[(size_t)bt * DI + h * HP + p0];
        const float4 zv = *(const float4*)&g_zx[(size_t)bt * DIP + h * HP + p0];
        const float cu = cumf[t0 + i];
        float y0 = yl.x + cu * acc[i][0] + Dh * xv.x;
        float y1 = yl.y + cu * acc[i][1] + Dh * xv.y;
        float y2 = yl.z + cu * acc[i][2] + Dh * xv.z;
        float y3 = yl.w + cu * acc[i][3] + Dh * xv.w;
        y0 *= zv.x / (1.f + expf(-zv.x));
        y1 *= zv.y / (1.f + expf(-zv.y));
        y2 *= zv.z / (1.f + expf(-zv.z));
        y3 *= zv.w / (1.f + expf(-zv.w));
        *(float4*)&g_y[yoff] = make_float4(y0, y1, y2, y3);
    }
}

// ---------------- RMS norm + folded (out_proj ∘ classifier) ----------------
__global__ __launch_bounds__(256)
void rmsnorm_cls_kernel(const float* __restrict__ norm_w,
                        const float* __restrict__ cls_b, float* __restrict__ out)
{
    const int bt = blockIdx.x;
    const float* row = g_y + (size_t)bt * DI;
    float v[16];
    float ss = 0.f;
    #pragma unroll
    for (int i = 0; i < 16; i++) {
        v[i] = row[threadIdx.x + i * 256];
        ss = fmaf(v[i], v[i], ss);
    }
    #pragma unroll
    for (int o = 16; o > 0; o >>= 1) ss += __shfl_xor_sync(0xffffffffu, ss, o);
    __shared__ float sred[8];
    const int lane = threadIdx.x & 31, warp = threadIdx.x >> 5;
    if (lane == 0) sred[warp] = ss;
    __syncthreads();
    float tot = 0.f;
    #pragma unroll
    for (int w = 0; w < 8; w++) tot += sred[w];
    const float scale = rsqrtf(tot * (1.f / DI) + 1e-5f);

    float a0 = 0.f, a1 = 0.f, a2 = 0.f, a3 = 0.f;
    #pragma unroll
    for (int i = 0; i < 16; i++) {
        const int c = threadIdx.x + i * 256;
        const float yn = v[i] * scale * __ldg(norm_w + c);
        a0 = fmaf(yn, __ldg(&g_M[c]),          a0);
        a1 = fmaf(yn, __ldg(&g_M[DI + c]),     a1);
        a2 = fmaf(yn, __ldg(&g_M[2 * DI + c]), a2);
        a3 = fmaf(yn, __ldg(&g_M[3 * DI + c]), a3);
    }
    #pragma unroll
    for (int o = 16; o > 0; o >>= 1) {
        a0 += __shfl_xor_sync(0xffffffffu, a0, o);
        a1 += __shfl_xor_sync(0xffffffffu, a1, o);
        a2 += __shfl_xor_sync(0xffffffffu, a2, o);
        a3 += __shfl_xor_sync(0xffffffffu, a3, o);
    }
    __shared__ float s4[8][4];
    if (lane == 0) { s4[warp][0] = a0; s4[warp][1] = a1; s4[warp][2] = a2; s4[warp][3] = a3; }
    __syncthreads();
    if (threadIdx.x < 4) {
        float s = __ldg(cls_b + threadIdx.x);
        #pragma unroll
        for (int w = 0; w < 8; w++) s += s4[w][threadIdx.x];
        out[bt * NCLS + threadIdx.x] = s;
    }
}

// ---------------- launcher ----------------
extern "C" void kernel_launch(void* const* d_in, const int* in_sizes, int n_in,
                              void* d_out, int out_size)
{
    (void)in_sizes; (void)n_in; (void)out_size;
    const float* x          = (const float*)d_in[0];
    const float* in_proj_w  = (const float*)d_in[1];
    const float* conv_w     = (const float*)d_in[2];
    const float* conv_b     = (const float*)d_in[3];
    const float* dt_bias    = (const float*)d_in[4];
    const float* A_log      = (const float*)d_in[5];
    const float* Dp         = (const float*)d_in[6];
    const float* norm_w     = (const float*)d_in[7];
    const float* out_proj_w = (const float*)d_in[8];
    const float* cls_w      = (const float*)d_in[9];
    const float* cls_b      = (const float*)d_in[10];
    float* out = (float*)d_out;

    float* zx;
    __half *x16, *w1h;
    cudaGetSymbolAddress((void**)&zx,  g_zx);
    cudaGetSymbolAddress((void**)&x16, g_x16);
    cudaGetSymbolAddress((void**)&w1h, g_w1h);

    cudaFuncSetAttribute(gemm_h256, cudaFuncAttributeMaxDynamicSharedMemorySize, SMEM_BYTES);
    cudaFuncSetAttribute(seg_ssd_kernel, cudaFuncAttributeMaxDynamicSharedMemorySize, SSD_SMEM);

    // 1-2) convert gemm1 operands to fp16
    cvt_f16_kernel<<<2048, 256>>>(x,         x16, BL * DM / 4);
    cvt_f16_kernel<<<2048, 256>>>(in_proj_w, w1h, DIP * DM / 4);
    // 3) build folded M
    mbuild_kernel<<<DI / 256, 256>>>(out_proj_w, cls_w);
    // 4) in_proj GEMM (ncu capture target slot)
    {
        dim3 grid(NOUT / 128, BL / 256);
        gemm_h256<<<grid, 256, SMEM_BYTES>>>(x16, w1h, zx, BL, DM, DIP);
    }
    // 5) exact fp32 dt path (+ log-dA)
    dt_exact_kernel<<<BL / 32, 256>>>(x, in_proj_w, dt_bias, A_log);
    // 6) conv + silu
    conv_prep_kernel<<<BL, 256>>>(conv_w, conv_b);
    // 7-9) SSD chunked scan
    seg_ssd_kernel<<<B_ * HN * NSEG, 256, SSD_SMEM>>>();
    scan_combine_kernel<<<B_ * HN, 256>>>();
    scan_fix_kernel<<<B_ * HN * NSEG, 256>>>(Dp);
    // 10) RMS norm fused with folded out_proj+classifier
    rmsnorm_cls_kernel<<<BL, 256>>>(norm_w, cls_b, out);
}

// round 13
// speedup vs baseline: 4.2560x; 1.0264x over previous
#include <cuda_runtime.h>
#include <cuda_fp16.h>
#include <math.h>
#include <stdint.h>

#define B_    4
#define L_    2048
#define DM    2048
#define DI    4096
#define DST   64
#define HN    64
#define HP    64
#define CONVD 4224
#define DIP   8448
#define NOUT  8320
#define BL    (B_*L_)
#define NCLS  4
#define TC    64
#define NSEG  (L_/TC)
#define SROW  76

__device__ float  g_zx[BL * DIP];
__device__ float  g_xh[BL * DI];
__device__ float  g_Bm[BL * DST];
__device__ float  g_Cm[BL * DST];
__device__ float  g_dt[BL * HN];
__device__ float  g_a [BL * HN];
__device__ float  g_y [BL * DI];
__device__ float  g_M [NCLS * DI];
__device__ float  g_cp[BL * HN];
__device__ float  g_hend[(size_t)B_ * HN * NSEG * HP * DST];
__device__ float  g_h0  [(size_t)B_ * HN * NSEG * HP * DST];
__device__ __half g_x16[BL * DM];
__device__ __half g_w1h[DIP * DM];

__device__ __forceinline__ uint32_t smem_u32(const void* p) {
    uint32_t a;
    asm("{ .reg .u64 t; cvta.to.shared.u64 t, %1; cvt.u32.u64 %0, t; }" : "=r"(a) : "l"(p));
    return a;
}
__device__ __forceinline__ void cp16(uint32_t saddr, const void* gptr) {
    asm volatile("cp.async.ca.shared.global [%0], [%1], 16;" :: "r"(saddr), "l"(gptr) : "memory");
}
__device__ __forceinline__ void cp_commit() {
    asm volatile("cp.async.commit_group;" ::: "memory");
}
__device__ __forceinline__ void cp_wait2() {
    asm volatile("cp.async.wait_group 2;" ::: "memory");
}
__device__ __forceinline__ void ldsm4(unsigned& r0, unsigned& r1, unsigned& r2, unsigned& r3,
                                      uint32_t addr) {
    asm volatile("ldmatrix.sync.aligned.m8n8.x4.shared.b16 {%0,%1,%2,%3}, [%4];"
                 : "=r"(r0), "=r"(r1), "=r"(r2), "=r"(r3) : "r"(addr));
}
__device__ __forceinline__ void mma_f16(float c[4], const unsigned a[4], const unsigned b[2]) {
    asm volatile(
        "mma.sync.aligned.m16n8k16.row.col.f32.f16.f16.f32 "
        "{%0,%1,%2,%3}, {%4,%5,%6,%7}, {%8,%9}, {%0,%1,%2,%3};"
        : "+f"(c[0]), "+f"(c[1]), "+f"(c[2]), "+f"(c[3])
        : "r"(a[0]), "r"(a[1]), "r"(a[2]), "r"(a[3]),
          "r"(b[0]), "r"(b[1]));
}
__device__ __forceinline__ float silu_fast(float x) {
    float th;
    asm("tanh.approx.f32 %0, %1;" : "=f"(th) : "f"(0.5f * x));
    return 0.5f * x * (1.f + th);
}

#define STAGE_BYTES 24576
#define STAGE_BOFF  16384
#define SMEM_BYTES  (4 * STAGE_BYTES)
#define SSD_SMEM    (4 * 64 * SROW * 4 + 4 * 64 * 4)

__global__ __launch_bounds__(256, 1)
void gemm_h256(const __half* __restrict__ A, const __half* __restrict__ W,
               float* __restrict__ C, int M, int K, int ldc)
{
    extern __shared__ __align__(16) char smem[];
    const uint32_t sb = smem_u32(smem);

    const int tid  = threadIdx.x;
    const int warp = tid >> 5;
    const int lane = tid & 31;
    const int wm = warp >> 1;
    const int wn = warp & 1;
    const int g  = lane >> 2;
    const int t  = lane & 3;
    const int bm = blockIdx.y << 8;
    const int bn = blockIdx.x << 7;

    uint32_t pOff[6];
    const __half* Gp[6];
    #pragma unroll
    for (int j = 0; j < 6; j++) {
        const int c = tid + (j << 8);
        if (c < 1024) {
            const int pr = c >> 2, k8 = c & 3;
            pOff[j] = (uint32_t)(pr * 64 + ((k8 ^ ((pr >> 1) & 3)) << 4));
            Gp[j]   = A + (size_t)(bm + pr) * K + k8 * 8;
        } else {
            const int cb = c - 1024;
            const int pr = cb >> 2, k8 = cb & 3;
            pOff[j] = (uint32_t)(STAGE_BOFF + pr * 64 + ((k8 ^ ((pr >> 1) & 3)) << 4));
            Gp[j]   = W + (size_t)(bn + pr) * K + k8 * 8;
        }
    }

    uint32_t offA[4], swA[4];
    #pragma unroll
    for (int mt = 0; mt < 4; mt++) {
        const int r = wm * 64 + mt * 16 + (lane & 7) + ((lane >> 3) & 1) * 8;
        offA[mt] = (uint32_t)(r * 64);
        swA[mt]  = (uint32_t)((r >> 1) & 3);
    }
    uint32_t offB[4], swB[4];
    #pragma unroll
    for (int h = 0; h < 4; h++) {
        const int r = wn * 64 + h * 16 + (lane & 7) + ((lane >> 4) & 1) * 8;
        offB[h] = (uint32_t)(STAGE_BOFF + r * 64);
        swB[h]  = (uint32_t)((r >> 1) & 3);
    }
    const uint32_t cA = (uint32_t)(lane >> 4);
    const uint32_t cB = (uint32_t)((lane >> 3) & 1);

    float acc[4][8][4];
    #pragma unroll
    for (int i = 0; i < 4; i++)
        #pragma unroll
        for (int j = 0; j < 8; j++)
            #pragma unroll
            for (int c = 0; c < 4; c++) acc[i][j][c] = 0.f;

    const int KT = K >> 5;

    auto issue_stage = [&](int kt, int s) {
        const uint32_t base = sb + s * STAGE_BYTES;
        #pragma unroll
        for (int j = 0; j < 6; j++)
            cp16(base + pOff[j], Gp[j] + kt * 32);
    };

    issue_stage(0, 0); cp_commit();
    issue_stage(1, 1); cp_commit();
    issue_stage(2, 2); cp_commit();
    cp_wait2();
    __syncthreads();

    for (int kt = 0; kt < KT; kt++) {
        const int s = kt & 3;
        const uint32_t base = sb + s * STAGE_BYTES;

        #pragma unroll
        for (int kk = 0; kk < 2; kk++) {
            unsigned a[4][4], b[8][2];
            #pragma unroll
            for (int mt = 0; mt < 4; mt++) {
                const uint32_t ch = (uint32_t)(2 * kk) + cA;
                ldsm4(a[mt][0], a[mt][1], a[mt][2], a[mt][3],
                      base + offA[mt] + ((ch ^ swA[mt]) << 4));
            }
            #pragma unroll
            for (int h = 0; h < 4; h++) {
                const uint32_t ch = (uint32_t)(2 * kk) + cB;
                ldsm4(b[2*h][0], b[2*h][1], b[2*h+1][0], b[2*h+1][1],
                      base + offB[h] + ((ch ^ swB[h]) << 4));
            }
            #pragma unroll
            for (int mt = 0; mt < 4; mt++)
                #pragma unroll
                for (int nt = 0; nt < 8; nt++)
                    mma_f16(acc[mt][nt], a[mt], b[nt]);
        }

        if (kt + 3 < KT) issue_stage(kt + 3, (kt + 3) & 3);
        cp_commit();
        if (kt + 1 < KT) {
            cp_wait2();
            __syncthreads();
        }
    }

    #pragma unroll
    for (int mt = 0; mt < 4; mt++) {
        #pragma unroll
        for (int nt = 0; nt < 8; nt++) {
            const int rr = bm + wm * 64 + mt * 16 + g;
            const int c0 = bn + wn * 64 + nt * 8 + 2 * t;
            *(float2*)&C[(size_t)rr * ldc + c0]       = make_float2(acc[mt][nt][0], acc[mt][nt][1]);
            *(float2*)&C[(size_t)(rr + 8) * ldc + c0] = make_float2(acc[mt][nt][2], acc[mt][nt][3]);
        }
    }
}

__global__ __launch_bounds__(256)
void cvt_f16_kernel(const float* __restrict__ src, __half* __restrict__ dst, int n4)
{
    int i = blockIdx.x * 256 + threadIdx.x;
    const int stride = gridDim.x * 256;
    for (; i < n4; i += stride) {
        float4 v = *(const float4*)(src + (size_t)i * 4);
        *(__half2*)(dst + (size_t)i * 4)     = __floats2half2_rn(v.x, v.y);
        *(__half2*)(dst + (size_t)i * 4 + 2) = __floats2half2_rn(v.z, v.w);
    }
}

__global__ __launch_bounds__(256)
void mbuild_kernel(const float* __restrict__ out_proj_w, const float* __restrict__ cls_w)
{
    const int e = blockIdx.x * 256 + threadIdx.x;
    float a0 = 0.f, a1 = 0.f, a2 = 0.f, a3 = 0.f;
    for (int d = 0; d < DM; d++) {
        const float w = __ldg(out_proj_w + (size_t)d * DI + e);
        a0 = fmaf(w, __ldg(cls_w + d),          a0);
        a1 = fmaf(w, __ldg(cls_w + DM + d),     a1);
        a2 = fmaf(w, __ldg(cls_w + 2 * DM + d), a2);
        a3 = fmaf(w, __ldg(cls_w + 3 * DM + d), a3);
    }
    g_M[e]          = a0;
    g_M[DI + e]     = a1;
    g_M[2 * DI + e] = a2;
    g_M[3 * DI + e] = a3;
}

// dt v3: 64 rows x 64 cols per block, grid 128, LDS.128 fragments, fma-bound.
__global__ __launch_bounds__(256)
void dt_exact_kernel(const float* __restrict__ x, const float* __restrict__ in_proj_w,
                     const float* __restrict__ dt_bias, const float* __restrict__ A_log)
{
    __shared__ float As[64][20];
    __shared__ float Ws[64][20];
    const int tid = threadIdx.x;
    const int bt0 = blockIdx.x << 6;
    const int tm = tid >> 3;
    const int tn = tid & 7;
    const float* Wdt = in_proj_w + (size_t)(DI + CONVD) * DM;

    const int lr = tid >> 2;
    const int lc = (tid & 3) << 2;

    float acc[2][8];
    #pragma unroll
    for (int i = 0; i < 2; i++)
        #pragma unroll
        for (int j = 0; j < 8; j++) acc[i][j] = 0.f;

    for (int k0 = 0; k0 < DM; k0 += 16) {
        *(float4*)&As[lr][lc] = *(const float4*)(x   + (size_t)(bt0 + lr) * DM + k0 + lc);
        *(float4*)&Ws[lr][lc] = *(const float4*)(Wdt + (size_t)lr         * DM + k0 + lc);
        __syncthreads();
        #pragma unroll
        for (int kk = 0; kk < 16; kk += 4) {
            float4 b4[8];
            #pragma unroll
            for (int j = 0; j < 8; j++) b4[j] = *(const float4*)&Ws[tn + 8 * j][kk];
            #pragma unroll
            for (int i = 0; i < 2; i++) {
                const float4 a4 = *(const float4*)&As[tm + 32 * i][kk];
                #pragma unroll
                for (int j = 0; j < 8; j++) {
                    acc[i][j] = fmaf(a4.x, b4[j].x, acc[i][j]);
                    acc[i][j] = fmaf(a4.y, b4[j].y, acc[i][j]);
                    acc[i][j] = fmaf(a4.z, b4[j].z, acc[i][j]);
                    acc[i][j] = fmaf(a4.w, b4[j].w, acc[i][j]);
                }
            }
        }
        __syncthreads();
    }
    #pragma unroll
    for (int i = 0; i < 2; i++) {
        #pragma unroll
        for (int j = 0; j < 8; j++) {
            const int bt = bt0 + tm + i * 32;
            const int h  = tn + j * 8;
            float dtr = acc[i][j] + __ldg(dt_bias + h);
            float dts = (dtr > 20.f) ? dtr : log1pf(expf(dtr));
            g_dt[bt * HN + h] = dts;
            g_a [bt * HN + h] = -expf(__ldg(A_log + h)) * dts;
        }
    }
}

__global__ void conv_prep_kernel(const float* __restrict__ conv_w,
                                 const float* __restrict__ conv_b)
{
    const int bt = blockIdx.x;
    const int b  = bt / L_;
    const int t  = bt % L_;

    for (int c = threadIdx.x; c < CONVD; c += blockDim.x) {
        float4 wv = *(const float4*)(conv_w + c * 4);
        float s = conv_b[c];
        const float wk[4] = {wv.x, wv.y, wv.z, wv.w};
        #pragma unroll
        for (int k = 0; k < 4; k++) {
            int tt = t - 3 + k;
            float xv = (tt >= 0) ? g_zx[(size_t)(b * L_ + tt) * DIP + DI + c] : 0.f;
            s = fmaf(xv, wk[k], s);
        }
        float sil = silu_fast(s);
        if (c < DI)            g_xh[(size_t)bt * DI + c]       = sil;
        else if (c < DI + DST) g_Bm[bt * DST + (c - DI)]        = sil;
        else                   g_Cm[bt * DST + (c - DI - DST)]  = sil;
    }
}

__global__ __launch_bounds__(256)
void seg_ssd_kernel()
{
    extern __shared__ __align__(16) float sm[];
    float* Ct  = sm;
    float* Bsm = sm + 64 * SROW;
    float* Xs  = sm + 2 * 64 * SROW;
    float* Ms  = sm + 3 * 64 * SROW;
    float* Acs = sm + 4 * 64 * SROW;
    float* dtss = Acs + 64;
    float* cums = Acs + 128;
    float* wss  = Acs + 192;

    const int tid = threadIdx.x;
    const int seg = blockIdx.x & (NSEG - 1);
    const int bh  = blockIdx.x >> 5;
    const int b = bh >> 6, h = bh & 63;
    const int btbase = b * L_ + seg * TC;

    {
        const int lr = tid >> 2;
        const int lc = (tid & 3) << 4;
        const float* gB = g_Bm + (size_t)(btbase + lr) * DST + lc;
        const float* gC = g_Cm + (size_t)(btbase + lr) * DST + lc;
        const float* gX = g_xh + (size_t)(btbase + lr) * DI + h * HP + lc;
        #pragma unroll
        for (int q = 0; q < 4; q++) {
            *(float4*)&Bsm[lr * SROW + lc + q * 4] = *(const float4*)(gB + q * 4);
            *(float4*)&Ct [lr * SROW + lc + q * 4] = *(const float4*)(gC + q * 4);
            *(float4*)&Xs [lr * SROW + lc + q * 4] = *(const float4*)(gX + q * 4);
        }
    }
    if (tid < 64) {
        dtss[tid] = g_dt[(btbase + tid) * HN + h];
        Acs[tid]  = g_a [(btbase + tid) * HN + h];
    }
    __syncthreads();
    #pragma unroll
    for (int off = 1; off < 64; off <<= 1) {
        float v = 0.f;
        if (tid < 64 && tid >= off) v = Acs[tid - off];
        __syncthreads();
        if (tid < 64) Acs[tid] += v;
        __syncthreads();
    }
    if (tid < 64) {
        cums[tid] = __expf(Acs[tid]);
        wss[tid]  = __expf(Acs[63] - Acs[tid]) * dtss[tid];
        g_cp[(btbase + tid) * HN + h] = cums[tid];
    }
    __syncthreads();

    const int it = tid >> 4;
    const int jp = tid & 15;
    const int t0 = it << 2;
    const int j0 = jp << 2;

    float S[4][4];
    #pragma unroll
    for (int i = 0; i < 4; i++)
        #pragma unroll
        for (int j = 0; j < 4; j++) S[i][j] = 0.f;
    if (j0 <= t0 + 3) {
        for (int n = 0; n < 64; n += 4) {
            float4 cv[4], bv[4];
            #pragma unroll
            for (int i = 0; i < 4; i++) cv[i] = *(const float4*)&Ct[(t0 + i) * SROW + n];
            #pragma unroll
            for (int j = 0; j < 4; j++) bv[j] = *(const float4*)&Bsm[(j0 + j) * SROW + n];
            #pragma unroll
            for (int i = 0; i < 4; i++)
                #pragma unroll
                for (int j = 0; j < 4; j++)
                    S[i][j] += cv[i].x * bv[j].x + cv[i].y * bv[j].y
                             + cv[i].z * bv[j].z + cv[i].w * bv[j].w;
        }
    }
    #pragma unroll
    for (int i = 0; i < 4; i++)
        #pragma unroll
        for (int j = 0; j < 4; j++) {
            const int t = t0 + i, s = j0 + j;
            const float m = (s <= t) ? __expf(Acs[t] - Acs[s]) * dtss[s] : 0.f;
            Ms[s * SROW + t] = S[i][j] * m;
        }
    __syncthreads();

    float Y[4][4], Hn[4][4];
    #pragma unroll
    for (int i = 0; i < 4; i++)
        #pragma unroll
        for (int j = 0; j < 4; j++) { Y[i][j] = 0.f; Hn[i][j] = 0.f; }
    for (int s = 0; s < 64; s++) {
        const float4 xv = *(const float4*)&Xs[s * SROW + j0];
        const float4 mv = *(const float4*)&Ms[s * SROW + t0];
        const float4 bv = *(const float4*)&Bsm[s * SROW + t0];
        const float w = wss[s];
        const float xa[4] = {xv.x, xv.y, xv.z, xv.w};
        const float wx[4] = {xv.x * w, xv.y * w, xv.z * w, xv.w * w};
        const float ma[4] = {mv.x, mv.y, mv.z, mv.w};
        const float ba[4] = {bv.x, bv.y, bv.z, bv.w};
        #pragma unroll
        for (int i = 0; i < 4; i++)
            #pragma unroll
            for (int j = 0; j < 4; j++) {
                Y[i][j]  = fmaf(ma[i], xa[j], Y[i][j]);
                Hn[i][j] = fmaf(ba[i], wx[j], Hn[i][j]);
            }
    }
    #pragma unroll
    for (int i = 0; i < 4; i++)
        *(float4*)&g_y[(size_t)(btbase + t0 + i) * DI + h * HP + j0] =
            make_float4(Y[i][0], Y[i][1], Y[i][2], Y[i][3]);
    const size_t hb = ((size_t)bh * NSEG + seg) * (DST * HP);
    #pragma unroll
    for (int i = 0; i < 4; i++)
        *(float4*)&g_hend[hb + (size_t)(t0 + i) * HP + j0] =
            make_float4(Hn[i][0], Hn[i][1], Hn[i][2], Hn[i][3]);
}

__global__ __launch_bounds__(256)
void scan_combine_kernel()
{
    const int bh  = blockIdx.x;
    const int tid = threadIdx.x;
    const int b = bh >> 6, h = bh & 63;
    float4 st[4];
    #pragma unroll
    for (int q = 0; q < 4; q++) st[q] = make_float4(0.f, 0.f, 0.f, 0.f);
    const size_t base0 = (size_t)bh * NSEG * (DST * HP);
    for (int k = 0; k < NSEG; k++) {
        const size_t off = base0 + (size_t)k * (DST * HP) + (size_t)tid * 16;
        #pragma unroll
        for (int q = 0; q < 4; q++) *(float4*)&g_h0[off + q * 4] = st[q];
        const float Pend = __ldg(&g_cp[(b * L_ + k * TC + TC - 1) * HN + h]);
        #pragma unroll
        for (int q = 0; q < 4; q++) {
            float4 e = __ldg((const float4*)&g_hend[off + q * 4]);
            st[q].x = fmaf(st[q].x, Pend, e.x);
            st[q].y = fmaf(st[q].y, Pend, e.y);
            st[q].z = fmaf(st[q].z, Pend, e.z);
            st[q].w = fmaf(st[q].w, Pend, e.w);
        }
    }
}

__global__ __launch_bounds__(256)
void scan_fix_kernel(const float* __restrict__ Dp)
{
    __shared__ float Ctf[64 * SROW];
    __shared__ float H0s[64 * SROW];
    __shared__ float cumf[64];

    const int tid = threadIdx.x;
    const int seg = blockIdx.x & (NSEG - 1);
    const int bh  = blockIdx.x >> 5;
    const int b = bh >> 6, h = bh & 63;
    const int btbase = b * L_ + seg * TC;

    {
        const int lr = tid >> 2;
        const int lc = (tid & 3) << 4;
        const float* gC = g_Cm + (size_t)(btbase + lr) * DST + lc;
        const size_t hb = ((size_t)bh * NSEG + seg) * (DST * HP);
        const float* gH = g_h0 + hb + (size_t)lr * HP + lc;
        #pragma unroll
        for (int q = 0; q < 4; q++) {
            *(float4*)&Ctf[lr * SROW + lc + q * 4] = *(const float4*)(gC + q * 4);
            *(float4*)&H0s[lr * SROW + lc + q * 4] = *(const float4*)(gH + q * 4);
        }
    }
    if (tid < 64) cumf[tid] = g_cp[(btbase + tid) * HN + h];
    __syncthreads();

    const int it = tid >> 4;
    const int jp = tid & 15;
    const int t0 = it << 2;
    const int p0 = jp << 2;

    float acc[4][4];
    #pragma unroll
    for (int i = 0; i < 4; i++)
        #pragma unroll
        for (int j = 0; j < 4; j++) acc[i][j] = 0.f;
    for (int n = 0; n < 64; n++) {
        const float4 hv = *(const float4*)&H0s[n * SROW + p0];
        const float ha[4] = {hv.x, hv.y, hv.z, hv.w};
        #pragma unroll
        for (int i = 0; i < 4; i++) {
            const float c = Ctf[(t0 + i) * SROW + n];
            #pragma unroll
            for (int j = 0; j < 4; j++)
                acc[i][j] = fmaf(c, ha[j], acc[i][j]);
        }
    }

    const float Dh = __ldg(Dp + h);
    #pragma unroll
    for (int i = 0; i < 4; i++) {
        const int bt = btbase + t0 + i;
        const size_t yoff = (size_t)bt * DI + h * HP + p0;
        float4 yl = *(float4*)&g_y[yoff];
        const float4 xv = *(const float4*)&g_xh[(size_t)bt * DI + h * HP + p0];
        const float4 zv = *(const float4*)&g_zx[(size_t)bt * DIP + h * HP + p0];
        const float cu = cumf[t0 + i];
        const float y0 = (yl.x + cu * acc[i][0] + Dh * xv.x) * silu_fast(zv.x);
        const float y1 = (yl.y + cu * acc[i][1] + Dh * xv.y) * silu_fast(zv.y);
        const float y2 = (yl.z + cu * acc[i][2] + Dh * xv.z) * silu_fast(zv.z);
        const float y3 = (yl.w + cu * acc[i][3] + Dh * xv.w) * silu_fast(zv.w);
        *(float4*)&g_y[yoff] = make_float4(y0, y1, y2, y3);
    }
}

__global__ __launch_bounds__(256)
void rmsnorm_cls_kernel(const float* __restrict__ norm_w,
                        const float* __restrict__ cls_b, float* __restrict__ out)
{
    const int bt = blockIdx.x;
    const float* row = g_y + (size_t)bt * DI;
    float v[16];
    float ss = 0.f;
    #pragma unroll
    for (int i = 0; i < 16; i++) {
        v[i] = row[threadIdx.x + i * 256];
        ss = fmaf(v[i], v[i], ss);
    }
    #pragma unroll
    for (int o = 16; o > 0; o >>= 1) ss += __shfl_xor_sync(0xffffffffu, ss, o);
    __shared__ float sred[8];
    const int lane = threadIdx.x & 31, warp = threadIdx.x >> 5;
    if (lane == 0) sred[warp] = ss;
    __syncthreads();
    float tot = 0.f;
    #pragma unroll
    for (int w = 0; w < 8; w++) tot += sred[w];
    const float scale = rsqrtf(tot * (1.f / DI) + 1e-5f);

    float a0 = 0.f, a1 = 0.f, a2 = 0.f, a3 = 0.f;
    #pragma unroll
    for (int i = 0; i < 16; i++) {
        const int c = threadIdx.x + i * 256;
        const float yn = v[i] * scale * __ldg(norm_w + c);
        a0 = fmaf(yn, __ldg(&g_M[c]),          a0);
        a1 = fmaf(yn, __ldg(&g_M[DI + c]),     a1);
        a2 = fmaf(yn, __ldg(&g_M[2 * DI + c]), a2);
        a3 = fmaf(yn, __ldg(&g_M[3 * DI + c]), a3);
    }
    #pragma unroll
    for (int o = 16; o > 0; o >>= 1) {
        a0 += __shfl_xor_sync(0xffffffffu, a0, o);
        a1 += __shfl_xor_sync(0xffffffffu, a1, o);
        a2 += __shfl_xor_sync(0xffffffffu, a2, o);
        a3 += __shfl_xor_sync(0xffffffffu, a3, o);
    }
    __shared__ float s4[8][4];
    if (lane == 0) { s4[warp][0] = a0; s4[warp][1] = a1; s4[warp][2] = a2; s4[warp][3] = a3; }
    __syncthreads();
    if (threadIdx.x < 4) {
        float s = __ldg(cls_b + threadIdx.x);
        #pragma unroll
        for (int w = 0; w < 8; w++) s += s4[w][threadIdx.x];
        out[bt * NCLS + threadIdx.x] = s;
    }
}

extern "C" void kernel_launch(void* const* d_in, const int* in_sizes, int n_in,
                              void* d_out, int out_size)
{
    (void)in_sizes; (void)n_in; (void)out_size;
    const float* x          = (const float*)d_in[0];
    const float* in_proj_w  = (const float*)d_in[1];
    const float* conv_w     = (const float*)d_in[2];
    const float* conv_b     = (const float*)d_in[3];
    const float* dt_bias    = (const float*)d_in[4];
    const float* A_log      = (const float*)d_in[5];
    const float* Dp         = (const float*)d_in[6];
    const float* norm_w     = (const float*)d_in[7];
    const float* out_proj_w = (const float*)d_in[8];
    const float* cls_w      = (const float*)d_in[9];
    const float* cls_b      = (const float*)d_in[10];
    float* out = (float*)d_out;

    float* zx;
    __half *x16, *w1h;
    cudaGetSymbolAddress((void**)&zx,  g_zx);
    cudaGetSymbolAddress((void**)&x16, g_x16);
    cudaGetSymbolAddress((void**)&w1h, g_w1h);

    cudaFuncSetAttribute(gemm_h256, cudaFuncAttributeMaxDynamicSharedMemorySize, SMEM_BYTES);
    cudaFuncSetAttribute(seg_ssd_kernel, cudaFuncAttributeMaxDynamicSharedMemorySize, SSD_SMEM);

    cvt_f16_kernel<<<2048, 256>>>(x,         x16, BL * DM / 4);
    cvt_f16_kernel<<<2048, 256>>>(in_proj_w, w1h, DIP * DM / 4);
    mbuild_kernel<<<DI / 256, 256>>>(out_proj_w, cls_w);
    {
        dim3 grid(NOUT / 128, BL / 256);
        gemm_h256<<<grid, 256, SMEM_BYTES>>>(x16, w1h, zx, BL, DM, DIP);
    }
    dt_exact_kernel<<<BL / 64, 256>>>(x, in_proj_w, dt_bias, A_log);
    conv_prep_kernel<<<BL, 256>>>(conv_w, conv_b);
    seg_ssd_kernel<<<B_ * HN * NSEG, 256, SSD_SMEM>>>();
    scan_combine_kernel<<<B_ * HN, 256>>>();
    scan_fix_kernel<<<B_ * HN * NSEG, 256>>>(Dp);
    rmsnorm_cls_kernel<<<BL, 256>>>(norm_w, cls_b, out);
}

// round 14
// speedup vs baseline: 4.9697x; 1.1677x over previous
#include <cuda_runtime.h>
#include <cuda_fp16.h>
#include <math.h>
#include <stdint.h>

#define B_    4
#define L_    2048
#define DM    2048
#define DI    4096
#define DST   64
#define HN    64
#define HP    64
#define CONVD 4224
#define DIP   8448
#define NOUT  8320
#define BL    (B_*L_)
#define NCLS  4
#define TC    64
#define NSEG  (L_/TC)
#define HROW  72              // fp16 tile row stride (halfs); 144 B -> conflict-free ldsm

__device__ float  g_zx[BL * DIP];
__device__ float  g_xh[BL * DI];
__device__ float  g_Bm[BL * DST];
__device__ float  g_Cm[BL * DST];
__device__ float  g_dt[BL * HN];
__device__ float  g_a [BL * HN];
__device__ float  g_y [BL * DI];
__device__ float  g_M [NCLS * DI];
__device__ float  g_cp[BL * HN];
__device__ float  g_hend[(size_t)B_ * HN * NSEG * HP * DST];
__device__ float  g_h0  [(size_t)B_ * HN * NSEG * HP * DST];
__device__ __half g_x16[BL * DM];
__device__ __half g_w1h[DIP * DM];

__device__ __forceinline__ uint32_t smem_u32(const void* p) {
    uint32_t a;
    asm("{ .reg .u64 t; cvta.to.shared.u64 t, %1; cvt.u32.u64 %0, t; }" : "=r"(a) : "l"(p));
    return a;
}
__device__ __forceinline__ void cp16(uint32_t saddr, const void* gptr) {
    asm volatile("cp.async.ca.shared.global [%0], [%1], 16;" :: "r"(saddr), "l"(gptr) : "memory");
}
__device__ __forceinline__ void cp_commit() {
    asm volatile("cp.async.commit_group;" ::: "memory");
}
__device__ __forceinline__ void cp_wait2() {
    asm volatile("cp.async.wait_group 2;" ::: "memory");
}
__device__ __forceinline__ void ldsm4(unsigned& r0, unsigned& r1, unsigned& r2, unsigned& r3,
                                      uint32_t addr) {
    asm volatile("ldmatrix.sync.aligned.m8n8.x4.shared.b16 {%0,%1,%2,%3}, [%4];"
                 : "=r"(r0), "=r"(r1), "=r"(r2), "=r"(r3) : "r"(addr));
}
__device__ __forceinline__ void ldsm4t(unsigned& r0, unsigned& r1, unsigned& r2, unsigned& r3,
                                       uint32_t addr) {
    asm volatile("ldmatrix.sync.aligned.m8n8.x4.trans.shared.b16 {%0,%1,%2,%3}, [%4];"
                 : "=r"(r0), "=r"(r1), "=r"(r2), "=r"(r3) : "r"(addr));
}
__device__ __forceinline__ void mma_f16(float c[4], const unsigned a[4], const unsigned b[2]) {
    asm volatile(
        "mma.sync.aligned.m16n8k16.row.col.f32.f16.f16.f32 "
        "{%0,%1,%2,%3}, {%4,%5,%6,%7}, {%8,%9}, {%0,%1,%2,%3};"
        : "+f"(c[0]), "+f"(c[1]), "+f"(c[2]), "+f"(c[3])
        : "r"(a[0]), "r"(a[1]), "r"(a[2]), "r"(a[3]),
          "r"(b[0]), "r"(b[1]));
}
__device__ __forceinline__ float silu_fast(float x) {
    float th;
    asm("tanh.approx.f32 %0, %1;" : "=f"(th) : "f"(0.5f * x));
    return 0.5f * x * (1.f + th);
}

// ---- ldmatrix address helpers for 64x64 fp16 tiles, row stride HROW halfs (144B) ----
// A-operand (logical [m][k], storage row-major [m][HROW]); m0 = warp m base, ks = k/16 step
__device__ __forceinline__ uint32_t addrA(uint32_t base, int m0, int ks, int lane) {
    const int row = m0 + (lane & 7) + ((lane >> 3) & 1) * 8;
    const int ch  = 2 * ks + (lane >> 4);
    return base + (uint32_t)(row * (HROW * 2) + ch * 16);
}
// A-operand TRANS (logical [m][k], storage [k][HROW]); m0, ks
__device__ __forceinline__ uint32_t addrAT(uint32_t base, int m0, int ks, int lane) {
    const int row = ks * 16 + ((lane >> 4) & 1) * 8 + (lane & 7);
    const int ch  = (m0 >> 3) + ((lane >> 3) & 1);
    return base + (uint32_t)(row * (HROW * 2) + ch * 16);
}
// B-operand (logical [n][k], storage row-major [n][HROW]); n0, ks
__device__ __forceinline__ uint32_t addrB(uint32_t base, int n0, int ks, int lane) {
    const int row = n0 + (lane & 7) + ((lane >> 4) & 1) * 8;
    const int ch  = 2 * ks + ((lane >> 3) & 1);
    return base + (uint32_t)(row * (HROW * 2) + ch * 16);
}
// B-operand TRANS (logical [n][k], storage [k][HROW]); n0, ks
__device__ __forceinline__ uint32_t addrBT(uint32_t base, int n0, int ks, int lane) {
    const int row = ks * 16 + ((lane >> 3) & 1) * 8 + (lane & 7);
    const int ch  = (n0 >> 3) + ((lane >> 4) & 1);
    return base + (uint32_t)(row * (HROW * 2) + ch * 16);
}

#define STAGE_BYTES 24576
#define STAGE_BOFF  16384
#define SMEM_BYTES  (4 * STAGE_BYTES)
// seg smem: 5 tiles x 64*HROW halfs + 4 x 64 floats
#define TILE_H   (64 * HROW)                  // 4608 halfs = 9216 B
#define SEG_SMEM (5 * TILE_H * 2 + 4 * 64 * 4)

// ---------------- FP16-operand GEMM, 256x128 CTA tile (proven, unchanged) ----------
__global__ __launch_bounds__(256, 1)
void gemm_h256(const __half* __restrict__ A, const __half* __restrict__ W,
               float* __restrict__ C, int M, int K, int ldc)
{
    extern __shared__ __align__(16) char smem[];
    const uint32_t sb = smem_u32(smem);

    const int tid  = threadIdx.x;
    const int warp = tid >> 5;
    const int lane = tid & 31;
    const int wm = warp >> 1;
    const int wn = warp & 1;
    const int g  = lane >> 2;
    const int t  = lane & 3;
    const int bm = blockIdx.y << 8;
    const int bn = blockIdx.x << 7;

    uint32_t pOff[6];
    const __half* Gp[6];
    #pragma unroll
    for (int j = 0; j < 6; j++) {
        const int c = tid + (j << 8);
        if (c < 1024) {
            const int pr = c >> 2, k8 = c & 3;
            pOff[j] = (uint32_t)(pr * 64 + ((k8 ^ ((pr >> 1) & 3)) << 4));
            Gp[j]   = A + (size_t)(bm + pr) * K + k8 * 8;
        } else {
            const int cb = c - 1024;
            const int pr = cb >> 2, k8 = cb & 3;
            pOff[j] = (uint32_t)(STAGE_BOFF + pr * 64 + ((k8 ^ ((pr >> 1) & 3)) << 4));
            Gp[j]   = W + (size_t)(bn + pr) * K + k8 * 8;
        }
    }

    uint32_t offA[4], swA[4];
    #pragma unroll
    for (int mt = 0; mt < 4; mt++) {
        const int r = wm * 64 + mt * 16 + (lane & 7) + ((lane >> 3) & 1) * 8;
        offA[mt] = (uint32_t)(r * 64);
        swA[mt]  = (uint32_t)((r >> 1) & 3);
    }
    uint32_t offB[4], swB[4];
    #pragma unroll
    for (int h = 0; h < 4; h++) {
        const int r = wn * 64 + h * 16 + (lane & 7) + ((lane >> 4) & 1) * 8;
        offB[h] = (uint32_t)(STAGE_BOFF + r * 64);
        swB[h]  = (uint32_t)((r >> 1) & 3);
    }
    const uint32_t cA = (uint32_t)(lane >> 4);
    const uint32_t cB = (uint32_t)((lane >> 3) & 1);

    float acc[4][8][4];
    #pragma unroll
    for (int i = 0; i < 4; i++)
        #pragma unroll
        for (int j = 0; j < 8; j++)
            #pragma unroll
            for (int c = 0; c < 4; c++) acc[i][j][c] = 0.f;

    const int KT = K >> 5;

    auto issue_stage = [&](int kt, int s) {
        const uint32_t base = sb + s * STAGE_BYTES;
        #pragma unroll
        for (int j = 0; j < 6; j++)
            cp16(base + pOff[j], Gp[j] + kt * 32);
    };

    issue_stage(0, 0); cp_commit();
    issue_stage(1, 1); cp_commit();
    issue_stage(2, 2); cp_commit();
    cp_wait2();
    __syncthreads();

    for (int kt = 0; kt < KT; kt++) {
        const int s = kt & 3;
        const uint32_t base = sb + s * STAGE_BYTES;

        #pragma unroll
        for (int kk = 0; kk < 2; kk++) {
            unsigned a[4][4], b[8][2];
            #pragma unroll
            for (int mt = 0; mt < 4; mt++) {
                const uint32_t ch = (uint32_t)(2 * kk) + cA;
                ldsm4(a[mt][0], a[mt][1], a[mt][2], a[mt][3],
                      base + offA[mt] + ((ch ^ swA[mt]) << 4));
            }
            #pragma unroll
            for (int h = 0; h < 4; h++) {
                const uint32_t ch = (uint32_t)(2 * kk) + cB;
                ldsm4(b[2*h][0], b[2*h][1], b[2*h+1][0], b[2*h+1][1],
                      base + offB[h] + ((ch ^ swB[h]) << 4));
            }
            #pragma unroll
            for (int mt = 0; mt < 4; mt++)
                #pragma unroll
                for (int nt = 0; nt < 8; nt++)
                    mma_f16(acc[mt][nt], a[mt], b[nt]);
        }

        if (kt + 3 < KT) issue_stage(kt + 3, (kt + 3) & 3);
        cp_commit();
        if (kt + 1 < KT) {
            cp_wait2();
            __syncthreads();
        }
    }

    #pragma unroll
    for (int mt = 0; mt < 4; mt++) {
        #pragma unroll
        for (int nt = 0; nt < 8; nt++) {
            const int rr = bm + wm * 64 + mt * 16 + g;
            const int c0 = bn + wn * 64 + nt * 8 + 2 * t;
            *(float2*)&C[(size_t)rr * ldc + c0]       = make_float2(acc[mt][nt][0], acc[mt][nt][1]);
            *(float2*)&C[(size_t)(rr + 8) * ldc + c0] = make_float2(acc[mt][nt][2], acc[mt][nt][3]);
        }
    }
}

__global__ __launch_bounds__(256)
void cvt_f16_kernel(const float* __restrict__ src, __half* __restrict__ dst, int n4)
{
    int i = blockIdx.x * 256 + threadIdx.x;
    const int stride = gridDim.x * 256;
    for (; i < n4; i += stride) {
        float4 v = *(const float4*)(src + (size_t)i * 4);
        *(__half2*)(dst + (size_t)i * 4)     = __floats2half2_rn(v.x, v.y);
        *(__half2*)(dst + (size_t)i * 4 + 2) = __floats2half2_rn(v.z, v.w);
    }
}

__global__ __launch_bounds__(256)
void mbuild_kernel(const float* __restrict__ out_proj_w, const float* __restrict__ cls_w)
{
    const int e = blockIdx.x * 256 + threadIdx.x;
    float a0 = 0.f, a1 = 0.f, a2 = 0.f, a3 = 0.f;
    for (int d = 0; d < DM; d++) {
        const float w = __ldg(out_proj_w + (size_t)d * DI + e);
        a0 = fmaf(w, __ldg(cls_w + d),          a0);
        a1 = fmaf(w, __ldg(cls_w + DM + d),     a1);
        a2 = fmaf(w, __ldg(cls_w + 2 * DM + d), a2);
        a3 = fmaf(w, __ldg(cls_w + 3 * DM + d), a3);
    }
    g_M[e]          = a0;
    g_M[DI + e]     = a1;
    g_M[2 * DI + e] = a2;
    g_M[3 * DI + e] = a3;
}

__global__ __launch_bounds__(256)
void dt_exact_kernel(const float* __restrict__ x, const float* __restrict__ in_proj_w,
                     const float* __restrict__ dt_bias, const float* __restrict__ A_log)
{
    __shared__ float As[64][20];
    __shared__ float Ws[64][20];
    const int tid = threadIdx.x;
    const int bt0 = blockIdx.x << 6;
    const int tm = tid >> 3;
    const int tn = tid & 7;
    const float* Wdt = in_proj_w + (size_t)(DI + CONVD) * DM;

    const int lr = tid >> 2;
    const int lc = (tid & 3) << 2;

    float acc[2][8];
    #pragma unroll
    for (int i = 0; i < 2; i++)
        #pragma unroll
        for (int j = 0; j < 8; j++) acc[i][j] = 0.f;

    for (int k0 = 0; k0 < DM; k0 += 16) {
        *(float4*)&As[lr][lc] = *(const float4*)(x   + (size_t)(bt0 + lr) * DM + k0 + lc);
        *(float4*)&Ws[lr][lc] = *(const float4*)(Wdt + (size_t)lr         * DM + k0 + lc);
        __syncthreads();
        #pragma unroll
        for (int kk = 0; kk < 16; kk += 4) {
            float4 b4[8];
            #pragma unroll
            for (int j = 0; j < 8; j++) b4[j] = *(const float4*)&Ws[tn + 8 * j][kk];
            #pragma unroll
            for (int i = 0; i < 2; i++) {
                const float4 a4 = *(const float4*)&As[tm + 32 * i][kk];
                #pragma unroll
                for (int j = 0; j < 8; j++) {
                    acc[i][j] = fmaf(a4.x, b4[j].x, acc[i][j]);
                    acc[i][j] = fmaf(a4.y, b4[j].y, acc[i][j]);
                    acc[i][j] = fmaf(a4.z, b4[j].z, acc[i][j]);
                    acc[i][j] = fmaf(a4.w, b4[j].w, acc[i][j]);
                }
            }
        }
        __syncthreads();
    }
    #pragma unroll
    for (int i = 0; i < 2; i++) {
        #pragma unroll
        for (int j = 0; j < 8; j++) {
            const int bt = bt0 + tm + i * 32;
            const int h  = tn + j * 8;
            float dtr = acc[i][j] + __ldg(dt_bias + h);
            float dts = (dtr > 20.f) ? dtr : log1pf(expf(dtr));
            g_dt[bt * HN + h] = dts;
            g_a [bt * HN + h] = -expf(__ldg(A_log + h)) * dts;
        }
    }
}

__global__ void conv_prep_kernel(const float* __restrict__ conv_w,
                                 const float* __restrict__ conv_b)
{
    const int bt = blockIdx.x;
    const int b  = bt / L_;
    const int t  = bt % L_;

    for (int c = threadIdx.x; c < CONVD; c += blockDim.x) {
        float4 wv = *(const float4*)(conv_w + c * 4);
        float s = conv_b[c];
        const float wk[4] = {wv.x, wv.y, wv.z, wv.w};
        #pragma unroll
        for (int k = 0; k < 4; k++) {
            int tt = t - 3 + k;
            float xv = (tt >= 0) ? g_zx[(size_t)(b * L_ + tt) * DIP + DI + c] : 0.f;
            s = fmaf(xv, wk[k], s);
        }
        float sil = silu_fast(s);
        if (c < DI)            g_xh[(size_t)bt * DI + c]       = sil;
        else if (c < DI + DST) g_Bm[bt * DST + (c - DI)]        = sil;
        else                   g_Cm[bt * DST + (c - DI - DST)]  = sil;
    }
}

// ---------------- SSD segment kernel, tensor cores ----------------
// block per (b,h,seg), 256 threads (8 warps: wr=warp>>2 m-half, wc=warp&3 n-quarter).
__global__ __launch_bounds__(256)
void seg_ssd_tc()
{
    extern __shared__ __align__(16) char smraw[];
    __half* Cs  = (__half*)smraw;                 // [t][n]
    __half* Bs  = Cs  + TILE_H;                   // [s][n]
    __half* Bws = Bs  + TILE_H;                   // [s][n] * w_s
    __half* Xs  = Bws + TILE_H;                   // [s][p]
    __half* Msm = Xs  + TILE_H;                   // [t][s]
    float* Acs = (float*)(Msm + TILE_H);
    float* dts = Acs + 64;
    float* wss = Acs + 128;
    float* cums = Acs + 192;

    const uint32_t uCs  = smem_u32(Cs);
    const uint32_t uBs  = smem_u32(Bs);
    const uint32_t uBws = smem_u32(Bws);
    const uint32_t uXs  = smem_u32(Xs);
    const uint32_t uMs  = smem_u32(Msm);

    const int tid  = threadIdx.x;
    const int warp = tid >> 5;
    const int lane = tid & 31;
    const int wr = warp >> 2;
    const int wc = warp & 3;
    const int g  = lane >> 2;
    const int t4 = lane & 3;

    const int seg = blockIdx.x & (NSEG - 1);
    const int bh  = blockIdx.x >> 5;
    const int b = bh >> 6, h = bh & 63;
    const int btbase = b * L_ + seg * TC;

    // cooperative tile loads fp32 -> fp16
    {
        const int lr = tid >> 2;
        const int lc = (tid & 3) << 4;
        const float* gB = g_Bm + (size_t)(btbase + lr) * DST + lc;
        const float* gC = g_Cm + (size_t)(btbase + lr) * DST + lc;
        const float* gX = g_xh + (size_t)(btbase + lr) * DI + h * HP + lc;
        #pragma unroll
        for (int q = 0; q < 4; q++) {
            float4 vb = *(const float4*)(gB + q * 4);
            float4 vc = *(const float4*)(gC + q * 4);
            float4 vx = *(const float4*)(gX + q * 4);
            *(__half2*)&Bs[lr * HROW + lc + q * 4]     = __floats2half2_rn(vb.x, vb.y);
            *(__half2*)&Bs[lr * HROW + lc + q * 4 + 2] = __floats2half2_rn(vb.z, vb.w);
            *(__half2*)&Cs[lr * HROW + lc + q * 4]     = __floats2half2_rn(vc.x, vc.y);
            *(__half2*)&Cs[lr * HROW + lc + q * 4 + 2] = __floats2half2_rn(vc.z, vc.w);
            *(__half2*)&Xs[lr * HROW + lc + q * 4]     = __floats2half2_rn(vx.x, vx.y);
            *(__half2*)&Xs[lr * HROW + lc + q * 4 + 2] = __floats2half2_rn(vx.z, vx.w);
        }
    }
    if (tid < 64) {
        dts[tid] = g_dt[(btbase + tid) * HN + h];
        Acs[tid] = g_a [(btbase + tid) * HN + h];
    }
    __syncthreads();
    #pragma unroll
    for (int off = 1; off < 64; off <<= 1) {
        float v = 0.f;
        if (tid < 64 && tid >= off) v = Acs[tid - off];
        __syncthreads();
        if (tid < 64) Acs[tid] += v;
        __syncthreads();
    }
    if (tid < 64) {
        cums[tid] = __expf(Acs[tid]);
        wss[tid]  = __expf(Acs[63] - Acs[tid]) * dts[tid];
        g_cp[(btbase + tid) * HN + h] = cums[tid];
    }
    __syncthreads();
    // Bws = Bs * w_s (row-scaled)
    {
        const int lr = tid >> 2;
        const int lc = (tid & 3) << 4;
        const __half2 wh = __floats2half2_rn(wss[lr], wss[lr]);
        #pragma unroll
        for (int q = 0; q < 8; q++) {
            __half2 v = *(__half2*)&Bs[lr * HROW + lc + q * 2];
            *(__half2*)&Bws[lr * HROW + lc + q * 2] = __hmul2(v, wh);
        }
    }
    __syncthreads();

    const int m0t = wr * 32;          // t-rows / n-rows base for this warp
    const int n0s = wc * 16;          // s-cols / p-cols base

    // ---- GEMM1: S[t][s] = C · B^T ----
    float S[2][2][4];
    #pragma unroll
    for (int i = 0; i < 2; i++)
        #pragma unroll
        for (int j = 0; j < 2; j++)
            #pragma unroll
            for (int c = 0; c < 4; c++) S[i][j][c] = 0.f;
    bool live[2][2];
    #pragma unroll
    for (int mt = 0; mt < 2; mt++)
        #pragma unroll
        for (int nt = 0; nt < 2; nt++)
            live[mt][nt] = (n0s + nt * 8) <= (m0t + mt * 16 + 15);

    #pragma unroll
    for (int ks = 0; ks < 4; ks++) {
        unsigned a[2][4], bb[2][2];
        #pragma unroll
        for (int mt = 0; mt < 2; mt++)
            ldsm4(a[mt][0], a[mt][1], a[mt][2], a[mt][3],
                  addrA(uCs, m0t + mt * 16, ks, lane));
        ldsm4(bb[0][0], bb[0][1], bb[1][0], bb[1][1], addrB(uBs, n0s, ks, lane));
        #pragma unroll
        for (int mt = 0; mt < 2; mt++)
            #pragma unroll
            for (int nt = 0; nt < 2; nt++)
                if (live[mt][nt]) mma_f16(S[mt][nt], a[mt], bb[nt]);
    }
    // mask + decay, store M[t][s] fp16
    #pragma unroll
    for (int mt = 0; mt < 2; mt++) {
        #pragma unroll
        for (int nt = 0; nt < 2; nt++) {
            const int s0 = n0s + nt * 8 + 2 * t4;
            #pragma unroll
            for (int half = 0; half < 2; half++) {
                const int t = m0t + mt * 16 + g + half * 8;
                float v0 = 0.f, v1 = 0.f;
                if (live[mt][nt]) {
                    const float m0v = (s0     <= t) ? __expf(Acs[t] - Acs[s0])     * dts[s0]     : 0.f;
                    const float m1v = (s0 + 1 <= t) ? __expf(Acs[t] - Acs[s0 + 1]) * dts[s0 + 1] : 0.f;
                    v0 = S[mt][nt][half * 2]     * m0v;
                    v1 = S[mt][nt][half * 2 + 1] * m1v;
                }
                *(__half2*)&Msm[t * HROW + s0] = __floats2half2_rn(v0, v1);
            }
        }
    }
    __syncthreads();

    // ---- GEMM2: Y[t][p] = M·X ;  GEMM3: Hend[n][p] = Bw^T·X ----
    float Y[2][2][4], Hh[2][2][4];
    #pragma unroll
    for (int i = 0; i < 2; i++)
        #pragma unroll
        for (int j = 0; j < 2; j++)
            #pragma unroll
            for (int c = 0; c < 4; c++) { Y[i][j][c] = 0.f; Hh[i][j][c] = 0.f; }

    #pragma unroll
    for (int ks = 0; ks < 4; ks++) {
        unsigned aM[2][4], aB[2][4], bX[2][2];
        #pragma unroll
        for (int mt = 0; mt < 2; mt++) {
            ldsm4 (aM[mt][0], aM[mt][1], aM[mt][2], aM[mt][3],
                   addrA (uMs,  m0t + mt * 16, ks, lane));
            ldsm4t(aB[mt][0], aB[mt][1], aB[mt][2], aB[mt][3],
                   addrAT(uBws, m0t + mt * 16, ks, lane));
        }
        ldsm4t(bX[0][0], bX[0][1], bX[1][0], bX[1][1], addrBT(uXs, n0s, ks, lane));
        #pragma unroll
        for (int mt = 0; mt < 2; mt++)
            #pragma unroll
            for (int nt = 0; nt < 2; nt++) {
                mma_f16(Y [mt][nt], aM[mt], bX[nt]);
                mma_f16(Hh[mt][nt], aB[mt], bX[nt]);
            }
    }
    // store Y (fp32) and Hend (fp32)
    const size_t hb = ((size_t)bh * NSEG + seg) * (DST * HP);
    #pragma unroll
    for (int mt = 0; mt < 2; mt++) {
        #pragma unroll
        for (int nt = 0; nt < 2; nt++) {
            const int p0 = n0s + nt * 8 + 2 * t4;
            #pragma unroll
            for (int half = 0; half < 2; half++) {
                const int tr = m0t + mt * 16 + g + half * 8;
                *(float2*)&g_y[(size_t)(btbase + tr) * DI + h * HP + p0] =
                    make_float2(Y[mt][nt][half * 2], Y[mt][nt][half * 2 + 1]);
                *(float2*)&g_hend[hb + (size_t)tr * HP + p0] =
                    make_float2(Hh[mt][nt][half * 2], Hh[mt][nt][half * 2 + 1]);
            }
        }
    }
}

__global__ __launch_bounds__(256)
void scan_combine_kernel()
{
    const int bh  = blockIdx.x;
    const int tid = threadIdx.x;
    const int b = bh >> 6, h = bh & 63;
    float4 st[4];
    #pragma unroll
    for (int q = 0; q < 4; q++) st[q] = make_float4(0.f, 0.f, 0.f, 0.f);
    const size_t base0 = (size_t)bh * NSEG * (DST * HP);
    for (int k = 0; k < NSEG; k++) {
        const size_t off = base0 + (size_t)k * (DST * HP) + (size_t)tid * 16;
        #pragma unroll
        for (int q = 0; q < 4; q++) *(float4*)&g_h0[off + q * 4] = st[q];
        const float Pend = __ldg(&g_cp[(b * L_ + k * TC + TC - 1) * HN + h]);
        #pragma unroll
        for (int q = 0; q < 4; q++) {
            float4 e = __ldg((const float4*)&g_hend[off + q * 4]);
            st[q].x = fmaf(st[q].x, Pend, e.x);
            st[q].y = fmaf(st[q].y, Pend, e.y);
            st[q].z = fmaf(st[q].z, Pend, e.z);
            st[q].w = fmaf(st[q].w, Pend, e.w);
        }
    }
}

// ---------------- fix pass, tensor cores: y += cum_t*(C·h0) + D*x, gate ----------------
__global__ __launch_bounds__(256)
void scan_fix_tc(const float* __restrict__ Dp)
{
    __shared__ __align__(16) __half Cs[TILE_H];    // [t][n]
    __shared__ __align__(16) __half H0s[TILE_H];   // [n][p]
    __shared__ float cumf[64];

    const uint32_t uCs = smem_u32(Cs);
    const uint32_t uH  = smem_u32(H0s);

    const int tid  = threadIdx.x;
    const int warp = tid >> 5;
    const int lane = tid & 31;
    const int wr = warp >> 2;
    const int wc = warp & 3;
    const int g  = lane >> 2;
    const int t4 = lane & 3;

    const int seg = blockIdx.x & (NSEG - 1);
    const int bh  = blockIdx.x >> 5;
    const int b = bh >> 6, h = bh & 63;
    const int btbase = b * L_ + seg * TC;

    {
        const int lr = tid >> 2;
        const int lc = (tid & 3) << 4;
        const float* gC = g_Cm + (size_t)(btbase + lr) * DST + lc;
        const size_t hb = ((size_t)bh * NSEG + seg) * (DST * HP);
        const float* gH = g_h0 + hb + (size_t)lr * HP + lc;
        #pragma unroll
        for (int q = 0; q < 4; q++) {
            float4 vc = *(const float4*)(gC + q * 4);
            float4 vh = *(const float4*)(gH + q * 4);
            *(__half2*)&Cs[lr * HROW + lc + q * 4]      = __floats2half2_rn(vc.x, vc.y);
            *(__half2*)&Cs[lr * HROW + lc + q * 4 + 2]  = __floats2half2_rn(vc.z, vc.w);
            *(__half2*)&H0s[lr * HROW + lc + q * 4]     = __floats2half2_rn(vh.x, vh.y);
            *(__half2*)&H0s[lr * HROW + lc + q * 4 + 2] = __floats2half2_rn(vh.z, vh.w);
        }
    }
    if (tid < 64) cumf[tid] = g_cp[(btbase + tid) * HN + h];
    __syncthreads();

    const int m0t = wr * 32;
    const int n0p = wc * 16;

    float acc[2][2][4];
    #pragma unroll
    for (int i = 0; i < 2; i++)
        #pragma unroll
        for (int j = 0; j < 2; j++)
            #pragma unroll
            for (int c = 0; c < 4; c++) acc[i][j][c] = 0.f;

    #pragma unroll
    for (int ks = 0; ks < 4; ks++) {
        unsigned a[2][4], bb[2][2];
        #pragma unroll
        for (int mt = 0; mt < 2; mt++)
            ldsm4(a[mt][0], a[mt][1], a[mt][2], a[mt][3],
                  addrA(uCs, m0t + mt * 16, ks, lane));
        ldsm4t(bb[0][0], bb[0][1], bb[1][0], bb[1][1], addrBT(uH, n0p, ks, lane));
        #pragma unroll
        for (int mt = 0; mt < 2; mt++)
            #pragma unroll
            for (int nt = 0; nt < 2; nt++)
                mma_f16(acc[mt][nt], a[mt], bb[nt]);
    }

    const float Dh = __ldg(Dp + h);
    #pragma unroll
    for (int mt = 0; mt < 2; mt++) {
        #pragma unroll
        for (int nt = 0; nt < 2; nt++) {
            const int p0 = n0p + nt * 8 + 2 * t4;
            #pragma unroll
            for (int half = 0; half < 2; half++) {
                const int tr = m0t + mt * 16 + g + half * 8;
                const int bt = btbase + tr;
                const size_t yoff = (size_t)bt * DI + h * HP + p0;
                float2 yl = *(float2*)&g_y[yoff];
                const float2 xv = *(const float2*)&g_xh[(size_t)bt * DI + h * HP + p0];
                const float2 zv = *(const float2*)&g_zx[(size_t)bt * DIP + h * HP + p0];
                const float cu = cumf[tr];
                const float y0 = (yl.x + cu * acc[mt][nt][half * 2]     + Dh * xv.x) * silu_fast(zv.x);
                const float y1 = (yl.y + cu * acc[mt][nt][half * 2 + 1] + Dh * xv.y) * silu_fast(zv.y);
                *(float2*)&g_y[yoff] = make_float2(y0, y1);
            }
        }
    }
}

__global__ __launch_bounds__(256)
void rmsnorm_cls_kernel(const float* __restrict__ norm_w,
                        const float* __restrict__ cls_b, float* __restrict__ out)
{
    const int bt = blockIdx.x;
    const float* row = g_y + (size_t)bt * DI;
    float v[16];
    float ss = 0.f;
    #pragma unroll
    for (int i = 0; i < 16; i++) {
        v[i] = row[threadIdx.x + i * 256];
        ss = fmaf(v[i], v[i], ss);
    }
    #pragma unroll
    for (int o = 16; o > 0; o >>= 1) ss += __shfl_xor_sync(0xffffffffu, ss, o);
    __shared__ float sred[8];
    const int lane = threadIdx.x & 31, warp = threadIdx.x >> 5;
    if (lane == 0) sred[warp] = ss;
    __syncthreads();
    float tot = 0.f;
    #pragma unroll
    for (int w = 0; w < 8; w++) tot += sred[w];
    const float scale = rsqrtf(tot * (1.f / DI) + 1e-5f);

    float a0 = 0.f, a1 = 0.f, a2 = 0.f, a3 = 0.f;
    #pragma unroll
    for (int i = 0; i < 16; i++) {
        const int c = threadIdx.x + i * 256;
        const float yn = v[i] * scale * __ldg(norm_w + c);
        a0 = fmaf(yn, __ldg(&g_M[c]),          a0);
        a1 = fmaf(yn, __ldg(&g_M[DI + c]),     a1);
        a2 = fmaf(yn, __ldg(&g_M[2 * DI + c]), a2);
        a3 = fmaf(yn, __ldg(&g_M[3 * DI + c]), a3);
    }
    #pragma unroll
    for (int o = 16; o > 0; o >>= 1) {
        a0 += __shfl_xor_sync(0xffffffffu, a0, o);
        a1 += __shfl_xor_sync(0xffffffffu, a1, o);
        a2 += __shfl_xor_sync(0xffffffffu, a2, o);
        a3 += __shfl_xor_sync(0xffffffffu, a3, o);
    }
    __shared__ float s4[8][4];
    if (lane == 0) { s4[warp][0] = a0; s4[warp][1] = a1; s4[warp][2] = a2; s4[warp][3] = a3; }
    __syncthreads();
    if (threadIdx.x < 4) {
        float s = __ldg(cls_b + threadIdx.x);
        #pragma unroll
        for (int w = 0; w < 8; w++) s += s4[w][threadIdx.x];
        out[bt * NCLS + threadIdx.x] = s;
    }
}

extern "C" void kernel_launch(void* const* d_in, const int* in_sizes, int n_in,
                              void* d_out, int out_size)
{
    (void)in_sizes; (void)n_in; (void)out_size;
    const float* x          = (const float*)d_in[0];
    const float* in_proj_w  = (const float*)d_in[1];
    const float* conv_w     = (const float*)d_in[2];
    const float* conv_b     = (const float*)d_in[3];
    const float* dt_bias    = (const float*)d_in[4];
    const float* A_log      = (const float*)d_in[5];
    const float* Dp         = (const float*)d_in[6];
    const float* norm_w     = (const float*)d_in[7];
    const float* out_proj_w = (const float*)d_in[8];
    const float* cls_w      = (const float*)d_in[9];
    const float* cls_b      = (const float*)d_in[10];
    float* out = (float*)d_out;

    float* zx;
    __half *x16, *w1h;
    cudaGetSymbolAddress((void**)&zx,  g_zx);
    cudaGetSymbolAddress((void**)&x16, g_x16);
    cudaGetSymbolAddress((void**)&w1h, g_w1h);

    cudaFuncSetAttribute(gemm_h256, cudaFuncAttributeMaxDynamicSharedMemorySize, SMEM_BYTES);
    cudaFuncSetAttribute(seg_ssd_tc, cudaFuncAttributeMaxDynamicSharedMemorySize, SEG_SMEM);

    cvt_f16_kernel<<<2048, 256>>>(x,         x16, BL * DM / 4);
    cvt_f16_kernel<<<2048, 256>>>(in_proj_w, w1h, DIP * DM / 4);
    mbuild_kernel<<<DI / 256, 256>>>(out_proj_w, cls_w);
    {
        dim3 grid(NOUT / 128, BL / 256);
        gemm_h256<<<grid, 256, SMEM_BYTES>>>(x16, w1h, zx, BL, DM, DIP);
    }
    dt_exact_kernel<<<BL / 64, 256>>>(x, in_proj_w, dt_bias, A_log);
    conv_prep_kernel<<<BL, 256>>>(conv_w, conv_b);
    seg_ssd_tc<<<B_ * HN * NSEG, 256, SEG_SMEM>>>();
    scan_combine_kernel<<<B_ * HN, 256>>>();
    scan_fix_tc<<<B_ * HN * NSEG, 256>>>(Dp);
    rmsnorm_cls_kernel<<<BL, 256>>>(norm_w, cls_b, out);
}

// round 15
// speedup vs baseline: 5.5063x; 1.1080x over previous
#include <cuda_runtime.h>
#include <cuda_fp16.h>
#include <math.h>
#include <stdint.h>

#define B_    4
#define L_    2048
#define DM    2048
#define DI    4096
#define DST   64
#define HN    64
#define HP    64
#define CONVD 4224
#define DIP   8448
#define NOUT  8320
#define BL    (B_*L_)
#define NCLS  4
#define TC    64
#define NSEG  (L_/TC)
#define HROW  72              // fp16 tile row stride (halfs); 144 B -> conflict-free ldsm

__device__ float  g_zx[BL * DIP];
__device__ float  g_xh[BL * DI];
__device__ float  g_Bm[BL * DST];
__device__ float  g_Cm[BL * DST];
__device__ float  g_dt[BL * HN];
__device__ float  g_a [BL * HN];
__device__ float  g_y [BL * DI];
__device__ float  g_M [NCLS * DI];
__device__ float  g_cp[BL * HN];
__device__ float  g_hend[(size_t)B_ * HN * NSEG * HP * DST];
__device__ float  g_h0  [(size_t)B_ * HN * NSEG * HP * DST];
__device__ __half g_x16[BL * DM];
__device__ __half g_w1h[DIP * DM];

__device__ __forceinline__ uint32_t smem_u32(const void* p) {
    uint32_t a;
    asm("{ .reg .u64 t; cvta.to.shared.u64 t, %1; cvt.u32.u64 %0, t; }" : "=r"(a) : "l"(p));
    return a;
}
__device__ __forceinline__ void cp16(uint32_t saddr, const void* gptr) {
    asm volatile("cp.async.ca.shared.global [%0], [%1], 16;" :: "r"(saddr), "l"(gptr) : "memory");
}
__device__ __forceinline__ void cp_commit() {
    asm volatile("cp.async.commit_group;" ::: "memory");
}
__device__ __forceinline__ void cp_wait2() {
    asm volatile("cp.async.wait_group 2;" ::: "memory");
}
__device__ __forceinline__ void ldsm4(unsigned& r0, unsigned& r1, unsigned& r2, unsigned& r3,
                                      uint32_t addr) {
    asm volatile("ldmatrix.sync.aligned.m8n8.x4.shared.b16 {%0,%1,%2,%3}, [%4];"
                 : "=r"(r0), "=r"(r1), "=r"(r2), "=r"(r3) : "r"(addr));
}
__device__ __forceinline__ void ldsm4t(unsigned& r0, unsigned& r1, unsigned& r2, unsigned& r3,
                                       uint32_t addr) {
    asm volatile("ldmatrix.sync.aligned.m8n8.x4.trans.shared.b16 {%0,%1,%2,%3}, [%4];"
                 : "=r"(r0), "=r"(r1), "=r"(r2), "=r"(r3) : "r"(addr));
}
__device__ __forceinline__ void mma_f16(float c[4], const unsigned a[4], const unsigned b[2]) {
    asm volatile(
        "mma.sync.aligned.m16n8k16.row.col.f32.f16.f16.f32 "
        "{%0,%1,%2,%3}, {%4,%5,%6,%7}, {%8,%9}, {%0,%1,%2,%3};"
        : "+f"(c[0]), "+f"(c[1]), "+f"(c[2]), "+f"(c[3])
        : "r"(a[0]), "r"(a[1]), "r"(a[2]), "r"(a[3]),
          "r"(b[0]), "r"(b[1]));
}
__device__ __forceinline__ float silu_fast(float x) {
    float th;
    asm("tanh.approx.f32 %0, %1;" : "=f"(th) : "f"(0.5f * x));
    return 0.5f * x * (1.f + th);
}

// ---- ldmatrix address helpers for 64x64 fp16 tiles, row stride HROW halfs (144B) ----
__device__ __forceinline__ uint32_t addrA(uint32_t base, int m0, int ks, int lane) {
    const int row = m0 + (lane & 7) + ((lane >> 3) & 1) * 8;
    const int ch  = 2 * ks + (lane >> 4);
    return base + (uint32_t)(row * (HROW * 2) + ch * 16);
}
__device__ __forceinline__ uint32_t addrAT(uint32_t base, int m0, int ks, int lane) {
    const int row = ks * 16 + ((lane >> 4) & 1) * 8 + (lane & 7);
    const int ch  = (m0 >> 3) + ((lane >> 3) & 1);
    return base + (uint32_t)(row * (HROW * 2) + ch * 16);
}
__device__ __forceinline__ uint32_t addrB(uint32_t base, int n0, int ks, int lane) {
    const int row = n0 + (lane & 7) + ((lane >> 4) & 1) * 8;
    const int ch  = 2 * ks + ((lane >> 3) & 1);
    return base + (uint32_t)(row * (HROW * 2) + ch * 16);
}
__device__ __forceinline__ uint32_t addrBT(uint32_t base, int n0, int ks, int lane) {
    const int row = ks * 16 + ((lane >> 3) & 1) * 8 + (lane & 7);
    const int ch  = (n0 >> 3) + ((lane >> 4) & 1);
    return base + (uint32_t)(row * (HROW * 2) + ch * 16);
}

#define STAGE_BYTES 24576
#define STAGE_BOFF  16384
#define SMEM_BYTES  (4 * STAGE_BYTES)
#define TILE_H   (64 * HROW)
#define SEG_SMEM (5 * TILE_H * 2 + 4 * 64 * 4)

// ---------------- FP16-operand GEMM, 256x128 CTA tile (proven, unchanged) ----------
__global__ __launch_bounds__(256, 1)
void gemm_h256(const __half* __restrict__ A, const __half* __restrict__ W,
               float* __restrict__ C, int M, int K, int ldc)
{
    extern __shared__ __align__(16) char smem[];
    const uint32_t sb = smem_u32(smem);

    const int tid  = threadIdx.x;
    const int warp = tid >> 5;
    const int lane = tid & 31;
    const int wm = warp >> 1;
    const int wn = warp & 1;
    const int g  = lane >> 2;
    const int t  = lane & 3;
    const int bm = blockIdx.y << 8;
    const int bn = blockIdx.x << 7;

    uint32_t pOff[6];
    const __half* Gp[6];
    #pragma unroll
    for (int j = 0; j < 6; j++) {
        const int c = tid + (j << 8);
        if (c < 1024) {
            const int pr = c >> 2, k8 = c & 3;
            pOff[j] = (uint32_t)(pr * 64 + ((k8 ^ ((pr >> 1) & 3)) << 4));
            Gp[j]   = A + (size_t)(bm + pr) * K + k8 * 8;
        } else {
            const int cb = c - 1024;
            const int pr = cb >> 2, k8 = cb & 3;
            pOff[j] = (uint32_t)(STAGE_BOFF + pr * 64 + ((k8 ^ ((pr >> 1) & 3)) << 4));
            Gp[j]   = W + (size_t)(bn + pr) * K + k8 * 8;
        }
    }

    uint32_t offA[4], swA[4];
    #pragma unroll
    for (int mt = 0; mt < 4; mt++) {
        const int r = wm * 64 + mt * 16 + (lane & 7) + ((lane >> 3) & 1) * 8;
        offA[mt] = (uint32_t)(r * 64);
        swA[mt]  = (uint32_t)((r >> 1) & 3);
    }
    uint32_t offB[4], swB[4];
    #pragma unroll
    for (int h = 0; h < 4; h++) {
        const int r = wn * 64 + h * 16 + (lane & 7) + ((lane >> 4) & 1) * 8;
        offB[h] = (uint32_t)(STAGE_BOFF + r * 64);
        swB[h]  = (uint32_t)((r >> 1) & 3);
    }
    const uint32_t cA = (uint32_t)(lane >> 4);
    const uint32_t cB = (uint32_t)((lane >> 3) & 1);

    float acc[4][8][4];
    #pragma unroll
    for (int i = 0; i < 4; i++)
        #pragma unroll
        for (int j = 0; j < 8; j++)
            #pragma unroll
            for (int c = 0; c < 4; c++) acc[i][j][c] = 0.f;

    const int KT = K >> 5;

    auto issue_stage = [&](int kt, int s) {
        const uint32_t base = sb + s * STAGE_BYTES;
        #pragma unroll
        for (int j = 0; j < 6; j++)
            cp16(base + pOff[j], Gp[j] + kt * 32);
    };

    issue_stage(0, 0); cp_commit();
    issue_stage(1, 1); cp_commit();
    issue_stage(2, 2); cp_commit();
    cp_wait2();
    __syncthreads();

    for (int kt = 0; kt < KT; kt++) {
        const int s = kt & 3;
        const uint32_t base = sb + s * STAGE_BYTES;

        #pragma unroll
        for (int kk = 0; kk < 2; kk++) {
            unsigned a[4][4], b[8][2];
            #pragma unroll
            for (int mt = 0; mt < 4; mt++) {
                const uint32_t ch = (uint32_t)(2 * kk) + cA;
                ldsm4(a[mt][0], a[mt][1], a[mt][2], a[mt][3],
                      base + offA[mt] + ((ch ^ swA[mt]) << 4));
            }
            #pragma unroll
            for (int h = 0; h < 4; h++) {
                const uint32_t ch = (uint32_t)(2 * kk) + cB;
                ldsm4(b[2*h][0], b[2*h][1], b[2*h+1][0], b[2*h+1][1],
                      base + offB[h] + ((ch ^ swB[h]) << 4));
            }
            #pragma unroll
            for (int mt = 0; mt < 4; mt++)
                #pragma unroll
                for (int nt = 0; nt < 8; nt++)
                    mma_f16(acc[mt][nt], a[mt], b[nt]);
        }

        if (kt + 3 < KT) issue_stage(kt + 3, (kt + 3) & 3);
        cp_commit();
        if (kt + 1 < KT) {
            cp_wait2();
            __syncthreads();
        }
    }

    #pragma unroll
    for (int mt = 0; mt < 4; mt++) {
        #pragma unroll
        for (int nt = 0; nt < 8; nt++) {
            const int rr = bm + wm * 64 + mt * 16 + g;
            const int c0 = bn + wn * 64 + nt * 8 + 2 * t;
            *(float2*)&C[(size_t)rr * ldc + c0]       = make_float2(acc[mt][nt][0], acc[mt][nt][1]);
            *(float2*)&C[(size_t)(rr + 8) * ldc + c0] = make_float2(acc[mt][nt][2], acc[mt][nt][3]);
        }
    }
}

__global__ __launch_bounds__(256)
void cvt_f16_kernel(const float* __restrict__ src, __half* __restrict__ dst, int n4)
{
    int i = blockIdx.x * 256 + threadIdx.x;
    const int stride = gridDim.x * 256;
    for (; i < n4; i += stride) {
        float4 v = *(const float4*)(src + (size_t)i * 4);
        *(__half2*)(dst + (size_t)i * 4)     = __floats2half2_rn(v.x, v.y);
        *(__half2*)(dst + (size_t)i * 4 + 2) = __floats2half2_rn(v.z, v.w);
    }
}

__global__ __launch_bounds__(256)
void mbuild_kernel(const float* __restrict__ out_proj_w, const float* __restrict__ cls_w)
{
    const int e = blockIdx.x * 256 + threadIdx.x;
    float a0 = 0.f, a1 = 0.f, a2 = 0.f, a3 = 0.f;
    for (int d = 0; d < DM; d++) {
        const float w = __ldg(out_proj_w + (size_t)d * DI + e);
        a0 = fmaf(w, __ldg(cls_w + d),          a0);
        a1 = fmaf(w, __ldg(cls_w + DM + d),     a1);
        a2 = fmaf(w, __ldg(cls_w + 2 * DM + d), a2);
        a3 = fmaf(w, __ldg(cls_w + 3 * DM + d), a3);
    }
    g_M[e]          = a0;
    g_M[DI + e]     = a1;
    g_M[2 * DI + e] = a2;
    g_M[3 * DI + e] = a3;
}

__global__ __launch_bounds__(256)
void dt_exact_kernel(const float* __restrict__ x, const float* __restrict__ in_proj_w,
                     const float* __restrict__ dt_bias, const float* __restrict__ A_log)
{
    __shared__ float As[64][20];
    __shared__ float Ws[64][20];
    const int tid = threadIdx.x;
    const int bt0 = blockIdx.x << 6;
    const int tm = tid >> 3;
    const int tn = tid & 7;
    const float* Wdt = in_proj_w + (size_t)(DI + CONVD) * DM;

    const int lr = tid >> 2;
    const int lc = (tid & 3) << 2;

    float acc[2][8];
    #pragma unroll
    for (int i = 0; i < 2; i++)
        #pragma unroll
        for (int j = 0; j < 8; j++) acc[i][j] = 0.f;

    for (int k0 = 0; k0 < DM; k0 += 16) {
        *(float4*)&As[lr][lc] = *(const float4*)(x   + (size_t)(bt0 + lr) * DM + k0 + lc);
        *(float4*)&Ws[lr][lc] = *(const float4*)(Wdt + (size_t)lr         * DM + k0 + lc);
        __syncthreads();
        #pragma unroll
        for (int kk = 0; kk < 16; kk += 4) {
            float4 b4[8];
            #pragma unroll
            for (int j = 0; j < 8; j++) b4[j] = *(const float4*)&Ws[tn + 8 * j][kk];
            #pragma unroll
            for (int i = 0; i < 2; i++) {
                const float4 a4 = *(const float4*)&As[tm + 32 * i][kk];
                #pragma unroll
                for (int j = 0; j < 8; j++) {
                    acc[i][j] = fmaf(a4.x, b4[j].x, acc[i][j]);
                    acc[i][j] = fmaf(a4.y, b4[j].y, acc[i][j]);
                    acc[i][j] = fmaf(a4.z, b4[j].z, acc[i][j]);
                    acc[i][j] = fmaf(a4.w, b4[j].w, acc[i][j]);
                }
            }
        }
        __syncthreads();
    }
    #pragma unroll
    for (int i = 0; i < 2; i++) {
        #pragma unroll
        for (int j = 0; j < 8; j++) {
            const int bt = bt0 + tm + i * 32;
            const int h  = tn + j * 8;
            float dtr = acc[i][j] + __ldg(dt_bias + h);
            float dts = (dtr > 20.f) ? dtr : log1pf(expf(dtr));
            g_dt[bt * HN + h] = dts;
            g_a [bt * HN + h] = -expf(__ldg(A_log + h)) * dts;
        }
    }
}

__global__ void conv_prep_kernel(const float* __restrict__ conv_w,
                                 const float* __restrict__ conv_b)
{
    const int bt = blockIdx.x;
    const int b  = bt / L_;
    const int t  = bt % L_;

    for (int c = threadIdx.x; c < CONVD; c += blockDim.x) {
        float4 wv = *(const float4*)(conv_w + c * 4);
        float s = conv_b[c];
        const float wk[4] = {wv.x, wv.y, wv.z, wv.w};
        #pragma unroll
        for (int k = 0; k < 4; k++) {
            int tt = t - 3 + k;
            float xv = (tt >= 0) ? g_zx[(size_t)(b * L_ + tt) * DIP + DI + c] : 0.f;
            s = fmaf(xv, wk[k], s);
        }
        float sil = silu_fast(s);
        if (c < DI)            g_xh[(size_t)bt * DI + c]       = sil;
        else if (c < DI + DST) g_Bm[bt * DST + (c - DI)]        = sil;
        else                   g_Cm[bt * DST + (c - DI - DST)]  = sil;
    }
}

// ---------------- SSD segment kernel, tensor cores ----------------
__global__ __launch_bounds__(256)
void seg_ssd_tc()
{
    extern __shared__ __align__(16) char smraw[];
    __half* Cs  = (__half*)smraw;
    __half* Bs  = Cs  + TILE_H;
    __half* Bws = Bs  + TILE_H;
    __half* Xs  = Bws + TILE_H;
    __half* Msm = Xs  + TILE_H;
    float* Acs = (float*)(Msm + TILE_H);
    float* dts = Acs + 64;
    float* wss = Acs + 128;
    float* cums = Acs + 192;

    const uint32_t uCs  = smem_u32(Cs);
    const uint32_t uBs  = smem_u32(Bs);
    const uint32_t uBws = smem_u32(Bws);
    const uint32_t uXs  = smem_u32(Xs);
    const uint32_t uMs  = smem_u32(Msm);

    const int tid  = threadIdx.x;
    const int warp = tid >> 5;
    const int lane = tid & 31;
    const int wr = warp >> 2;
    const int wc = warp & 3;
    const int g  = lane >> 2;
    const int t4 = lane & 3;

    const int seg = blockIdx.x & (NSEG - 1);
    const int bh  = blockIdx.x >> 5;
    const int b = bh >> 6, h = bh & 63;
    const int btbase = b * L_ + seg * TC;

    {
        const int lr = tid >> 2;
        const int lc = (tid & 3) << 4;
        const float* gB = g_Bm + (size_t)(btbase + lr) * DST + lc;
        const float* gC = g_Cm + (size_t)(btbase + lr) * DST + lc;
        const float* gX = g_xh + (size_t)(btbase + lr) * DI + h * HP + lc;
        #pragma unroll
        for (int q = 0; q < 4; q++) {
            float4 vb = *(const float4*)(gB + q * 4);
            float4 vc = *(const float4*)(gC + q * 4);
            float4 vx = *(const float4*)(gX + q * 4);
            *(__half2*)&Bs[lr * HROW + lc + q * 4]     = __floats2half2_rn(vb.x, vb.y);
            *(__half2*)&Bs[lr * HROW + lc + q * 4 + 2] = __floats2half2_rn(vb.z, vb.w);
            *(__half2*)&Cs[lr * HROW + lc + q * 4]     = __floats2half2_rn(vc.x, vc.y);
            *(__half2*)&Cs[lr * HROW + lc + q * 4 + 2] = __floats2half2_rn(vc.z, vc.w);
            *(__half2*)&Xs[lr * HROW + lc + q * 4]     = __floats2half2_rn(vx.x, vx.y);
            *(__half2*)&Xs[lr * HROW + lc + q * 4 + 2] = __floats2half2_rn(vx.z, vx.w);
        }
    }
    if (tid < 64) {
        dts[tid] = g_dt[(btbase + tid) * HN + h];
        Acs[tid] = g_a [(btbase + tid) * HN + h];
    }
    __syncthreads();
    // warp-shuffle inclusive cumsum over 64 elems (warp 0, 2 per lane)
    if (warp == 0) {
        float a0 = Acs[2 * lane];
        float a1 = Acs[2 * lane + 1];
        float ps = a0 + a1;
        float sc = ps;
        #pragma unroll
        for (int o = 1; o < 32; o <<= 1) {
            float v = __shfl_up_sync(0xffffffffu, sc, o);
            if (lane >= o) sc += v;
        }
        const float excl = sc - ps;
        Acs[2 * lane]     = excl + a0;
        Acs[2 * lane + 1] = excl + a0 + a1;
    }
    __syncthreads();
    if (tid < 64) {
        cums[tid] = __expf(Acs[tid]);
        wss[tid]  = __expf(Acs[63] - Acs[tid]) * dts[tid];
        g_cp[(btbase + tid) * HN + h] = cums[tid];
    }
    __syncthreads();
    {
        const int lr = tid >> 2;
        const int lc = (tid & 3) << 4;
        const __half2 wh = __floats2half2_rn(wss[lr], wss[lr]);
        #pragma unroll
        for (int q = 0; q < 8; q++) {
            __half2 v = *(__half2*)&Bs[lr * HROW + lc + q * 2];
            *(__half2*)&Bws[lr * HROW + lc + q * 2] = __hmul2(v, wh);
        }
    }
    __syncthreads();

    const int m0t = wr * 32;
    const int n0s = wc * 16;

    float S[2][2][4];
    #pragma unroll
    for (int i = 0; i < 2; i++)
        #pragma unroll
        for (int j = 0; j < 2; j++)
            #pragma unroll
            for (int c = 0; c < 4; c++) S[i][j][c] = 0.f;
    bool live[2][2];
    #pragma unroll
    for (int mt = 0; mt < 2; mt++)
        #pragma unroll
        for (int nt = 0; nt < 2; nt++)
            live[mt][nt] = (n0s + nt * 8) <= (m0t + mt * 16 + 15);

    #pragma unroll
    for (int ks = 0; ks < 4; ks++) {
        unsigned a[2][4], bb[2][2];
        #pragma unroll
        for (int mt = 0; mt < 2; mt++)
            ldsm4(a[mt][0], a[mt][1], a[mt][2], a[mt][3],
                  addrA(uCs, m0t + mt * 16, ks, lane));
        ldsm4(bb[0][0], bb[0][1], bb[1][0], bb[1][1], addrB(uBs, n0s, ks, lane));
        #pragma unroll
        for (int mt = 0; mt < 2; mt++)
            #pragma unroll
            for (int nt = 0; nt < 2; nt++)
                if (live[mt][nt]) mma_f16(S[mt][nt], a[mt], bb[nt]);
    }
    #pragma unroll
    for (int mt = 0; mt < 2; mt++) {
        #pragma unroll
        for (int nt = 0; nt < 2; nt++) {
            const int s0 = n0s + nt * 8 + 2 * t4;
            #pragma unroll
            for (int half = 0; half < 2; half++) {
                const int t = m0t + mt * 16 + g + half * 8;
                float v0 = 0.f, v1 = 0.f;
                if (live[mt][nt]) {
                    const float m0v = (s0     <= t) ? __expf(Acs[t] - Acs[s0])     * dts[s0]     : 0.f;
                    const float m1v = (s0 + 1 <= t) ? __expf(Acs[t] - Acs[s0 + 1]) * dts[s0 + 1] : 0.f;
                    v0 = S[mt][nt][half * 2]     * m0v;
                    v1 = S[mt][nt][half * 2 + 1] * m1v;
                }
                *(__half2*)&Msm[t * HROW + s0] = __floats2half2_rn(v0, v1);
            }
        }
    }
    __syncthreads();

    float Y[2][2][4], Hh[2][2][4];
    #pragma unroll
    for (int i = 0; i < 2; i++)
        #pragma unroll
        for (int j = 0; j < 2; j++)
            #pragma unroll
            for (int c = 0; c < 4; c++) { Y[i][j][c] = 0.f; Hh[i][j][c] = 0.f; }

    #pragma unroll
    for (int ks = 0; ks < 4; ks++) {
        unsigned aM[2][4], aB[2][4], bX[2][2];
        #pragma unroll
        for (int mt = 0; mt < 2; mt++) {
            ldsm4 (aM[mt][0], aM[mt][1], aM[mt][2], aM[mt][3],
                   addrA (uMs,  m0t + mt * 16, ks, lane));
            ldsm4t(aB[mt][0], aB[mt][1], aB[mt][2], aB[mt][3],
                   addrAT(uBws, m0t + mt * 16, ks, lane));
        }
        ldsm4t(bX[0][0], bX[0][1], bX[1][0], bX[1][1], addrBT(uXs, n0s, ks, lane));
        #pragma unroll
        for (int mt = 0; mt < 2; mt++)
            #pragma unroll
            for (int nt = 0; nt < 2; nt++) {
                mma_f16(Y [mt][nt], aM[mt], bX[nt]);
                mma_f16(Hh[mt][nt], aB[mt], bX[nt]);
            }
    }
    const size_t hb = ((size_t)bh * NSEG + seg) * (DST * HP);
    #pragma unroll
    for (int mt = 0; mt < 2; mt++) {
        #pragma unroll
        for (int nt = 0; nt < 2; nt++) {
            const int p0 = n0s + nt * 8 + 2 * t4;
            #pragma unroll
            for (int half = 0; half < 2; half++) {
                const int tr = m0t + mt * 16 + g + half * 8;
                *(float2*)&g_y[(size_t)(btbase + tr) * DI + h * HP + p0] =
                    make_float2(Y[mt][nt][half * 2], Y[mt][nt][half * 2 + 1]);
                *(float2*)&g_hend[hb + (size_t)tr * HP + p0] =
                    make_float2(Hh[mt][nt][half * 2], Hh[mt][nt][half * 2 + 1]);
            }
        }
    }
}

__global__ __launch_bounds__(256)
void scan_combine_kernel()
{
    const int bh  = blockIdx.x;
    const int tid = threadIdx.x;
    const int b = bh >> 6, h = bh & 63;
    float4 st[4];
    #pragma unroll
    for (int q = 0; q < 4; q++) st[q] = make_float4(0.f, 0.f, 0.f, 0.f);
    const size_t base0 = (size_t)bh * NSEG * (DST * HP);
    for (int k = 0; k < NSEG; k++) {
        const size_t off = base0 + (size_t)k * (DST * HP) + (size_t)tid * 16;
        #pragma unroll
        for (int q = 0; q < 4; q++) *(float4*)&g_h0[off + q * 4] = st[q];
        const float Pend = __ldg(&g_cp[(b * L_ + k * TC + TC - 1) * HN + h]);
        #pragma unroll
        for (int q = 0; q < 4; q++) {
            float4 e = __ldg((const float4*)&g_hend[off + q * 4]);
            st[q].x = fmaf(st[q].x, Pend, e.x);
            st[q].y = fmaf(st[q].y, Pend, e.y);
            st[q].z = fmaf(st[q].z, Pend, e.z);
            st[q].w = fmaf(st[q].w, Pend, e.w);
        }
    }
}

__global__ __launch_bounds__(256)
void scan_fix_tc(const float* __restrict__ Dp)
{
    __shared__ __align__(16) __half Cs[TILE_H];
    __shared__ __align__(16) __half H0s[TILE_H];
    __shared__ float cumf[64];

    const uint32_t uCs = smem_u32(Cs);
    const uint32_t uH  = smem_u32(H0s);

    const int tid  = threadIdx.x;
    const int warp = tid >> 5;
    const int lane = tid & 31;
    const int wr = warp >> 2;
    const int wc = warp & 3;
    const int g  = lane >> 2;
    const int t4 = lane & 3;

    const int seg = blockIdx.x & (NSEG - 1);
    const int bh  = blockIdx.x >> 5;
    const int b = bh >> 6, h = bh & 63;
    const int btbase = b * L_ + seg * TC;

    {
        const int lr = tid >> 2;
        const int lc = (tid & 3) << 4;
        const float* gC = g_Cm + (size_t)(btbase + lr) * DST + lc;
        const size_t hb = ((size_t)bh * NSEG + seg) * (DST * HP);
        const float* gH = g_h0 + hb + (size_t)lr * HP + lc;
        #pragma unroll
        for (int q = 0; q < 4; q++) {
            float4 vc = *(const float4*)(gC + q * 4);
            float4 vh = *(const float4*)(gH + q * 4);
            *(__half2*)&Cs[lr * HROW + lc + q * 4]      = __floats2half2_rn(vc.x, vc.y);
            *(__half2*)&Cs[lr * HROW + lc + q * 4 + 2]  = __floats2half2_rn(vc.z, vc.w);
            *(__half2*)&H0s[lr * HROW + lc + q * 4]     = __floats2half2_rn(vh.x, vh.y);
            *(__half2*)&H0s[lr * HROW + lc + q * 4 + 2] = __floats2half2_rn(vh.z, vh.w);
        }
    }
    if (tid < 64) cumf[tid] = g_cp[(btbase + tid) * HN + h];
    __syncthreads();

    const int m0t = wr * 32;
    const int n0p = wc * 16;

    float acc[2][2][4];
    #pragma unroll
    for (int i = 0; i < 2; i++)
        #pragma unroll
        for (int j = 0; j < 2; j++)
            #pragma unroll
            for (int c = 0; c < 4; c++) acc[i][j][c] = 0.f;

    #pragma unroll
    for (int ks = 0; ks < 4; ks++) {
        unsigned a[2][4], bb[2][2];
        #pragma unroll
        for (int mt = 0; mt < 2; mt++)
            ldsm4(a[mt][0], a[mt][1], a[mt][2], a[mt][3],
                  addrA(uCs, m0t + mt * 16, ks, lane));
        ldsm4t(bb[0][0], bb[0][1], bb[1][0], bb[1][1], addrBT(uH, n0p, ks, lane));
        #pragma unroll
        for (int mt = 0; mt < 2; mt++)
            #pragma unroll
            for (int nt = 0; nt < 2; nt++)
                mma_f16(acc[mt][nt], a[mt], bb[nt]);
    }

    const float Dh = __ldg(Dp + h);
    #pragma unroll
    for (int mt = 0; mt < 2; mt++) {
        #pragma unroll
        for (int nt = 0; nt < 2; nt++) {
            const int p0 = n0p + nt * 8 + 2 * t4;
            #pragma unroll
            for (int half = 0; half < 2; half++) {
                const int tr = m0t + mt * 16 + g + half * 8;
                const int bt = btbase + tr;
                const size_t yoff = (size_t)bt * DI + h * HP + p0;
                float2 yl = *(float2*)&g_y[yoff];
                const float2 xv = *(const float2*)&g_xh[(size_t)bt * DI + h * HP + p0];
                const float2 zv = *(const float2*)&g_zx[(size_t)bt * DIP + h * HP + p0];
                const float cu = cumf[tr];
                const float y0 = (yl.x + cu * acc[mt][nt][half * 2]     + Dh * xv.x) * silu_fast(zv.x);
                const float y1 = (yl.y + cu * acc[mt][nt][half * 2 + 1] + Dh * xv.y) * silu_fast(zv.y);
                *(float2*)&g_y[yoff] = make_float2(y0, y1);
            }
        }
    }
}

__global__ __launch_bounds__(256)
void rmsnorm_cls_kernel(const float* __restrict__ norm_w,
                        const float* __restrict__ cls_b, float* __restrict__ out)
{
    const int bt = blockIdx.x;
    const float* row = g_y + (size_t)bt * DI;
    float v[16];
    float ss = 0.f;
    #pragma unroll
    for (int i = 0; i < 16; i++) {
        v[i] = row[threadIdx.x + i * 256];
        ss = fmaf(v[i], v[i], ss);
    }
    #pragma unroll
    for (int o = 16; o > 0; o >>= 1) ss += __shfl_xor_sync(0xffffffffu, ss, o);
    __shared__ float sred[8];
    const int lane = threadIdx.x & 31, warp = threadIdx.x >> 5;
    if (lane == 0) sred[warp] = ss;
    __syncthreads();
    float tot = 0.f;
    #pragma unroll
    for (int w = 0; w < 8; w++) tot += sred[w];
    const float scale = rsqrtf(tot * (1.f / DI) + 1e-5f);

    float a0 = 0.f, a1 = 0.f, a2 = 0.f, a3 = 0.f;
    #pragma unroll
    for (int i = 0; i < 16; i++) {
        const int c = threadIdx.x + i * 256;
        const float yn = v[i] * scale * __ldg(norm_w + c);
        a0 = fmaf(yn, __ldg(&g_M[c]),          a0);
        a1 = fmaf(yn, __ldg(&g_M[DI + c]),     a1);
        a2 = fmaf(yn, __ldg(&g_M[2 * DI + c]), a2);
        a3 = fmaf(yn, __ldg(&g_M[3 * DI + c]), a3);
    }
    #pragma unroll
    for (int o = 16; o > 0; o >>= 1) {
        a0 += __shfl_xor_sync(0xffffffffu, a0, o);
        a1 += __shfl_xor_sync(0xffffffffu, a1, o);
        a2 += __shfl_xor_sync(0xffffffffu, a2, o);
        a3 += __shfl_xor_sync(0xffffffffu, a3, o);
    }
    __shared__ float s4[8][4];
    if (lane == 0) { s4[warp][0] = a0; s4[warp][1] = a1; s4[warp][2] = a2; s4[warp][3] = a3; }
    __syncthreads();
    if (threadIdx.x < 4) {
        float s = __ldg(cls_b + threadIdx.x);
        #pragma unroll
        for (int w = 0; w < 8; w++) s += s4[w][threadIdx.x];
        out[bt * NCLS + threadIdx.x] = s;
    }
}

// ---------------- launcher: fork/join side stream for independent kernels ----------
extern "C" void kernel_launch(void* const* d_in, const int* in_sizes, int n_in,
                              void* d_out, int out_size)
{
    (void)in_sizes; (void)n_in; (void)out_size;
    const float* x          = (const float*)d_in[0];
    const float* in_proj_w  = (const float*)d_in[1];
    const float* conv_w     = (const float*)d_in[2];
    const float* conv_b     = (const float*)d_in[3];
    const float* dt_bias    = (const float*)d_in[4];
    const float* A_log      = (const float*)d_in[5];
    const float* Dp         = (const float*)d_in[6];
    const float* norm_w     = (const float*)d_in[7];
    const float* out_proj_w = (const float*)d_in[8];
    const float* cls_w      = (const float*)d_in[9];
    const float* cls_b      = (const float*)d_in[10];
    float* out = (float*)d_out;

    float* zx;
    __half *x16, *w1h;
    cudaGetSymbolAddress((void**)&zx,  g_zx);
    cudaGetSymbolAddress((void**)&x16, g_x16);
    cudaGetSymbolAddress((void**)&w1h, g_w1h);

    // one-time setup on the uncaptured correctness call
    static cudaStream_t s_side = nullptr;
    static cudaEvent_t ev_fork = nullptr, ev_join = nullptr;
    static bool attrs_set = false;
    if (!s_side) {
        cudaStreamCreateWithFlags(&s_side, cudaStreamNonBlocking);
        cudaEventCreateWithFlags(&ev_fork, cudaEventDisableTiming);
        cudaEventCreateWithFlags(&ev_join, cudaEventDisableTiming);
    }
    if (!attrs_set) {
        cudaFuncSetAttribute(gemm_h256, cudaFuncAttributeMaxDynamicSharedMemorySize, SMEM_BYTES);
        cudaFuncSetAttribute(seg_ssd_tc, cudaFuncAttributeMaxDynamicSharedMemorySize, SEG_SMEM);
        attrs_set = true;
    }

    // fork: side stream runs dt_exact + mbuild (independent of gemm1 chain)
    cudaEventRecord(ev_fork, 0);
    cudaStreamWaitEvent(s_side, ev_fork, 0);
    dt_exact_kernel<<<BL / 64, 256, 0, s_side>>>(x, in_proj_w, dt_bias, A_log);
    mbuild_kernel<<<DI / 256, 256, 0, s_side>>>(out_proj_w, cls_w);
    cudaEventRecord(ev_join, s_side);

    // main chain
    cvt_f16_kernel<<<2048, 256>>>(x,         x16, BL * DM / 4);
    cvt_f16_kernel<<<2048, 256>>>(in_proj_w, w1h, DIP * DM / 4);
    {
        dim3 grid(NOUT / 128, BL / 256);
        gemm_h256<<<grid, 256, SMEM_BYTES>>>(x16, w1h, zx, BL, DM, DIP);
    }
    conv_prep_kernel<<<BL, 256>>>(conv_w, conv_b);

    // join before seg (needs g_dt/g_a) — also covers mbuild for rmsnorm
    cudaStreamWaitEvent(0, ev_join, 0);

    seg_ssd_tc<<<B_ * HN * NSEG, 256, SEG_SMEM>>>();
    scan_combine_kernel<<<B_ * HN, 256>>>();
    scan_fix_tc<<<B_ * HN * NSEG, 256>>>(Dp);
    rmsnorm_cls_kernel<<<BL, 256>>>(norm_w, cls_b, out);
}

// round 17
// speedup vs baseline: 6.5694x; 1.1931x over previous
#include <cuda_runtime.h>
#include <cuda_fp16.h>
#include <math.h>
#include <stdint.h>

#define B_    4
#define L_    2048
#define DM    2048
#define DI    4096
#define DST   64
#define HN    64
#define HP    64
#define CONVD 4224
#define DIP   8448
#define NOUT  8320
#define BL    (B_*L_)
#define NCLS  4
#define TC    64
#define NSEG  (L_/TC)
#define HROW  72              // fp16 tile row stride (halfs); 144 B -> conflict-free ldsm

__device__ float  g_zx[BL * DIP];
__device__ float  g_xh[BL * DI];
__device__ float  g_Bm[BL * DST];
__device__ float  g_Cm[BL * DST];
__device__ float  g_dt[BL * HN];
__device__ float  g_a [BL * HN];
__device__ float  g_y [BL * DI];
__device__ float  g_M [NCLS * DI];
__device__ float  g_cp[BL * HN];
__device__ float  g_hend[(size_t)B_ * HN * NSEG * HP * DST];
__device__ float  g_h0  [(size_t)B_ * HN * NSEG * HP * DST];
__device__ __half g_x16[BL * DM];
__device__ __half g_w1h[DIP * DM];

__device__ __forceinline__ uint32_t smem_u32(const void* p) {
    uint32_t a;
    asm("{ .reg .u64 t; cvta.to.shared.u64 t, %1; cvt.u32.u64 %0, t; }" : "=r"(a) : "l"(p));
    return a;
}
__device__ __forceinline__ void cp16(uint32_t saddr, const void* gptr) {
    asm volatile("cp.async.ca.shared.global [%0], [%1], 16;" :: "r"(saddr), "l"(gptr) : "memory");
}
__device__ __forceinline__ void cp_commit() {
    asm volatile("cp.async.commit_group;" ::: "memory");
}
__device__ __forceinline__ void cp_wait2() {
    asm volatile("cp.async.wait_group 2;" ::: "memory");
}
__device__ __forceinline__ void ldsm4(unsigned& r0, unsigned& r1, unsigned& r2, unsigned& r3,
                                      uint32_t addr) {
    asm volatile("ldmatrix.sync.aligned.m8n8.x4.shared.b16 {%0,%1,%2,%3}, [%4];"
                 : "=r"(r0), "=r"(r1), "=r"(r2), "=r"(r3) : "r"(addr));
}
__device__ __forceinline__ void ldsm4t(unsigned& r0, unsigned& r1, unsigned& r2, unsigned& r3,
                                       uint32_t addr) {
    asm volatile("ldmatrix.sync.aligned.m8n8.x4.trans.shared.b16 {%0,%1,%2,%3}, [%4];"
                 : "=r"(r0), "=r"(r1), "=r"(r2), "=r"(r3) : "r"(addr));
}
__device__ __forceinline__ void mma_f16(float c[4], const unsigned a[4], const unsigned b[2]) {
    asm volatile(
        "mma.sync.aligned.m16n8k16.row.col.f32.f16.f16.f32 "
        "{%0,%1,%2,%3}, {%4,%5,%6,%7}, {%8,%9}, {%0,%1,%2,%3};"
        : "+f"(c[0]), "+f"(c[1]), "+f"(c[2]), "+f"(c[3])
        : "r"(a[0]), "r"(a[1]), "r"(a[2]), "r"(a[3]),
          "r"(b[0]), "r"(b[1]));
}
__device__ __forceinline__ float silu_fast(float x) {
    float th;
    asm("tanh.approx.f32 %0, %1;" : "=f"(th) : "f"(0.5f * x));
    return 0.5f * x * (1.f + th);
}

// ---- ldmatrix address helpers for 64x64 fp16 tiles, row stride HROW halfs (144B) ----
__device__ __forceinline__ uint32_t addrA(uint32_t base, int m0, int ks, int lane) {
    const int row = m0 + (lane & 7) + ((lane >> 3) & 1) * 8;
    const int ch  = 2 * ks + (lane >> 4);
    return base + (uint32_t)(row * (HROW * 2) + ch * 16);
}
__device__ __forceinline__ uint32_t addrAT(uint32_t base, int m0, int ks, int lane) {
    const int row = ks * 16 + ((lane >> 4) & 1) * 8 + (lane & 7);
    const int ch  = (m0 >> 3) + ((lane >> 3) & 1);
    return base + (uint32_t)(row * (HROW * 2) + ch * 16);
}
__device__ __forceinline__ uint32_t addrB(uint32_t base, int n0, int ks, int lane) {
    const int row = n0 + (lane & 7) + ((lane >> 4) & 1) * 8;
    const int ch  = 2 * ks + ((lane >> 3) & 1);
    return base + (uint32_t)(row * (HROW * 2) + ch * 16);
}
__device__ __forceinline__ uint32_t addrBT(uint32_t base, int n0, int ks, int lane) {
    const int row = ks * 16 + ((lane >> 3) & 1) * 8 + (lane & 7);
    const int ch  = (n0 >> 3) + ((lane >> 4) & 1);
    return base + (uint32_t)(row * (HROW * 2) + ch * 16);
}

#define STAGE_BYTES 24576
#define STAGE_BOFF  16384
#define SMEM_BYTES  (4 * STAGE_BYTES)
#define TILE_H   (64 * HROW)
#define SEG_SMEM (5 * TILE_H * 2 + 4 * 64 * 4)

// ---------------- FP16-operand GEMM, 256x128 CTA tile (proven, unchanged) ----------
__global__ __launch_bounds__(256, 1)
void gemm_h256(const __half* __restrict__ A, const __half* __restrict__ W,
               float* __restrict__ C, int M, int K, int ldc)
{
    extern __shared__ __align__(16) char smem[];
    const uint32_t sb = smem_u32(smem);

    const int tid  = threadIdx.x;
    const int warp = tid >> 5;
    const int lane = tid & 31;
    const int wm = warp >> 1;
    const int wn = warp & 1;
    const int g  = lane >> 2;
    const int t  = lane & 3;
    const int bm = blockIdx.y << 8;
    const int bn = blockIdx.x << 7;

    uint32_t pOff[6];
    const __half* Gp[6];
    #pragma unroll
    for (int j = 0; j < 6; j++) {
        const int c = tid + (j << 8);
        if (c < 1024) {
            const int pr = c >> 2, k8 = c & 3;
            pOff[j] = (uint32_t)(pr * 64 + ((k8 ^ ((pr >> 1) & 3)) << 4));
            Gp[j]   = A + (size_t)(bm + pr) * K + k8 * 8;
        } else {
            const int cb = c - 1024;
            const int pr = cb >> 2, k8 = cb & 3;
            pOff[j] = (uint32_t)(STAGE_BOFF + pr * 64 + ((k8 ^ ((pr >> 1) & 3)) << 4));
            Gp[j]   = W + (size_t)(bn + pr) * K + k8 * 8;
        }
    }

    uint32_t offA[4], swA[4];
    #pragma unroll
    for (int mt = 0; mt < 4; mt++) {
        const int r = wm * 64 + mt * 16 + (lane & 7) + ((lane >> 3) & 1) * 8;
        offA[mt] = (uint32_t)(r * 64);
        swA[mt]  = (uint32_t)((r >> 1) & 3);
    }
    uint32_t offB[4], swB[4];
    #pragma unroll
    for (int h = 0; h < 4; h++) {
        const int r = wn * 64 + h * 16 + (lane & 7) + ((lane >> 4) & 1) * 8;
        offB[h] = (uint32_t)(STAGE_BOFF + r * 64);
        swB[h]  = (uint32_t)((r >> 1) & 3);
    }
    const uint32_t cA = (uint32_t)(lane >> 4);
    const uint32_t cB = (uint32_t)((lane >> 3) & 1);

    float acc[4][8][4];
    #pragma unroll
    for (int i = 0; i < 4; i++)
        #pragma unroll
        for (int j = 0; j < 8; j++)
            #pragma unroll
            for (int c = 0; c < 4; c++) acc[i][j][c] = 0.f;

    const int KT = K >> 5;

    auto issue_stage = [&](int kt, int s) {
        const uint32_t base = sb + s * STAGE_BYTES;
        #pragma unroll
        for (int j = 0; j < 6; j++)
            cp16(base + pOff[j], Gp[j] + kt * 32);
    };

    issue_stage(0, 0); cp_commit();
    issue_stage(1, 1); cp_commit();
    issue_stage(2, 2); cp_commit();
    cp_wait2();
    __syncthreads();

    for (int kt = 0; kt < KT; kt++) {
        const int s = kt & 3;
        const uint32_t base = sb + s * STAGE_BYTES;

        #pragma unroll
        for (int kk = 0; kk < 2; kk++) {
            unsigned a[4][4], b[8][2];
            #pragma unroll
            for (int mt = 0; mt < 4; mt++) {
                const uint32_t ch = (uint32_t)(2 * kk) + cA;
                ldsm4(a[mt][0], a[mt][1], a[mt][2], a[mt][3],
                      base + offA[mt] + ((ch ^ swA[mt]) << 4));
            }
            #pragma unroll
            for (int h = 0; h < 4; h++) {
                const uint32_t ch = (uint32_t)(2 * kk) + cB;
                ldsm4(b[2*h][0], b[2*h][1], b[2*h+1][0], b[2*h+1][1],
                      base + offB[h] + ((ch ^ swB[h]) << 4));
            }
            #pragma unroll
            for (int mt = 0; mt < 4; mt++)
                #pragma unroll
                for (int nt = 0; nt < 8; nt++)
                    mma_f16(acc[mt][nt], a[mt], b[nt]);
        }

        if (kt + 3 < KT) issue_stage(kt + 3, (kt + 3) & 3);
        cp_commit();
        if (kt + 1 < KT) {
            cp_wait2();
            __syncthreads();
        }
    }

    #pragma unroll
    for (int mt = 0; mt < 4; mt++) {
        #pragma unroll
        for (int nt = 0; nt < 8; nt++) {
            const int rr = bm + wm * 64 + mt * 16 + g;
            const int c0 = bn + wn * 64 + nt * 8 + 2 * t;
            *(float2*)&C[(size_t)rr * ldc + c0]       = make_float2(acc[mt][nt][0], acc[mt][nt][1]);
            *(float2*)&C[(size_t)(rr + 8) * ldc + c0] = make_float2(acc[mt][nt][2], acc[mt][nt][3]);
        }
    }
}

__global__ __launch_bounds__(256)
void cvt_f16_kernel(const float* __restrict__ src, __half* __restrict__ dst, int n4)
{
    int i = blockIdx.x * 256 + threadIdx.x;
    const int stride = gridDim.x * 256;
    for (; i < n4; i += stride) {
        float4 v = *(const float4*)(src + (size_t)i * 4);
        *(__half2*)(dst + (size_t)i * 4)     = __floats2half2_rn(v.x, v.y);
        *(__half2*)(dst + (size_t)i * 4 + 2) = __floats2half2_rn(v.z, v.w);
    }
}

__global__ __launch_bounds__(256)
void mbuild_kernel(const float* __restrict__ out_proj_w, const float* __restrict__ cls_w)
{
    const int e = blockIdx.x * 256 + threadIdx.x;
    float a0 = 0.f, a1 = 0.f, a2 = 0.f, a3 = 0.f;
    for (int d = 0; d < DM; d++) {
        const float w = __ldg(out_proj_w + (size_t)d * DI + e);
        a0 = fmaf(w, __ldg(cls_w + d),          a0);
        a1 = fmaf(w, __ldg(cls_w + DM + d),     a1);
        a2 = fmaf(w, __ldg(cls_w + 2 * DM + d), a2);
        a3 = fmaf(w, __ldg(cls_w + 3 * DM + d), a3);
    }
    g_M[e]          = a0;
    g_M[DI + e]     = a1;
    g_M[2 * DI + e] = a2;
    g_M[3 * DI + e] = a3;
}

__global__ __launch_bounds__(256)
void dt_exact_kernel(const float* __restrict__ x, const float* __restrict__ in_proj_w,
                     const float* __restrict__ dt_bias, const float* __restrict__ A_log)
{
    __shared__ float As[64][20];
    __shared__ float Ws[64][20];
    const int tid = threadIdx.x;
    const int bt0 = blockIdx.x << 6;
    const int tm = tid >> 3;
    const int tn = tid & 7;
    const float* Wdt = in_proj_w + (size_t)(DI + CONVD) * DM;

    const int lr = tid >> 2;
    const int lc = (tid & 3) << 2;

    float acc[2][8];
    #pragma unroll
    for (int i = 0; i < 2; i++)
        #pragma unroll
        for (int j = 0; j < 8; j++) acc[i][j] = 0.f;

    for (int k0 = 0; k0 < DM; k0 += 16) {
        *(float4*)&As[lr][lc] = *(const float4*)(x   + (size_t)(bt0 + lr) * DM + k0 + lc);
        *(float4*)&Ws[lr][lc] = *(const float4*)(Wdt + (size_t)lr         * DM + k0 + lc);
        __syncthreads();
        #pragma unroll
        for (int kk = 0; kk < 16; kk += 4) {
            float4 b4[8];
            #pragma unroll
            for (int j = 0; j < 8; j++) b4[j] = *(const float4*)&Ws[tn + 8 * j][kk];
            #pragma unroll
            for (int i = 0; i < 2; i++) {
                const float4 a4 = *(const float4*)&As[tm + 32 * i][kk];
                #pragma unroll
                for (int j = 0; j < 8; j++) {
                    acc[i][j] = fmaf(a4.x, b4[j].x, acc[i][j]);
                    acc[i][j] = fmaf(a4.y, b4[j].y, acc[i][j]);
                    acc[i][j] = fmaf(a4.z, b4[j].z, acc[i][j]);
                    acc[i][j] = fmaf(a4.w, b4[j].w, acc[i][j]);
                }
            }
        }
        __syncthreads();
    }
    #pragma unroll
    for (int i = 0; i < 2; i++) {
        #pragma unroll
        for (int j = 0; j < 8; j++) {
            const int bt = bt0 + tm + i * 32;
            const int h  = tn + j * 8;
            float dtr = acc[i][j] + __ldg(dt_bias + h);
            float dts = (dtr > 20.f) ? dtr : log1pf(expf(dtr));
            g_dt[bt * HN + h] = dts;
            g_a [bt * HN + h] = -expf(__ldg(A_log + h)) * dts;
        }
    }
}

__global__ void conv_prep_kernel(const float* __restrict__ conv_w,
                                 const float* __restrict__ conv_b)
{
    const int bt = blockIdx.x;
    const int b  = bt / L_;
    const int t  = bt % L_;

    for (int c = threadIdx.x; c < CONVD; c += blockDim.x) {
        float4 wv = *(const float4*)(conv_w + c * 4);
        float s = conv_b[c];
        const float wk[4] = {wv.x, wv.y, wv.z, wv.w};
        #pragma unroll
        for (int k = 0; k < 4; k++) {
            int tt = t - 3 + k;
            float xv = (tt >= 0) ? g_zx[(size_t)(b * L_ + tt) * DIP + DI + c] : 0.f;
            s = fmaf(xv, wk[k], s);
        }
        float sil = silu_fast(s);
        if (c < DI)            g_xh[(size_t)bt * DI + c]       = sil;
        else if (c < DI + DST) g_Bm[bt * DST + (c - DI)]        = sil;
        else                   g_Cm[bt * DST + (c - DI - DST)]  = sil;
    }
}

// ---------------- SSD segment kernel, tensor cores (unchanged from R15) ----------
__global__ __launch_bounds__(256)
void seg_ssd_tc()
{
    extern __shared__ __align__(16) char smraw[];
    __half* Cs  = (__half*)smraw;
    __half* Bs  = Cs  + TILE_H;
    __half* Bws = Bs  + TILE_H;
    __half* Xs  = Bws + TILE_H;
    __half* Msm = Xs  + TILE_H;
    float* Acs = (float*)(Msm + TILE_H);
    float* dts = Acs + 64;
    float* wss = Acs + 128;
    float* cums = Acs + 192;

    const uint32_t uCs  = smem_u32(Cs);
    const uint32_t uBs  = smem_u32(Bs);
    const uint32_t uBws = smem_u32(Bws);
    const uint32_t uXs  = smem_u32(Xs);
    const uint32_t uMs  = smem_u32(Msm);

    const int tid  = threadIdx.x;
    const int warp = tid >> 5;
    const int lane = tid & 31;
    const int wr = warp >> 2;
    const int wc = warp & 3;
    const int g  = lane >> 2;
    const int t4 = lane & 3;

    const int seg = blockIdx.x & (NSEG - 1);
    const int bh  = blockIdx.x >> 5;
    const int b = bh >> 6, h = bh & 63;
    const int btbase = b * L_ + seg * TC;

    {
        const int lr = tid >> 2;
        const int lc = (tid & 3) << 4;
        const float* gB = g_Bm + (size_t)(btbase + lr) * DST + lc;
        const float* gC = g_Cm + (size_t)(btbase + lr) * DST + lc;
        const float* gX = g_xh + (size_t)(btbase + lr) * DI + h * HP + lc;
        #pragma unroll
        for (int q = 0; q < 4; q++) {
            float4 vb = *(const float4*)(gB + q * 4);
            float4 vc = *(const float4*)(gC + q * 4);
            float4 vx = *(const float4*)(gX + q * 4);
            *(__half2*)&Bs[lr * HROW + lc + q * 4]     = __floats2half2_rn(vb.x, vb.y);
            *(__half2*)&Bs[lr * HROW + lc + q * 4 + 2] = __floats2half2_rn(vb.z, vb.w);
            *(__half2*)&Cs[lr * HROW + lc + q * 4]     = __floats2half2_rn(vc.x, vc.y);
            *(__half2*)&Cs[lr * HROW + lc + q * 4 + 2] = __floats2half2_rn(vc.z, vc.w);
            *(__half2*)&Xs[lr * HROW + lc + q * 4]     = __floats2half2_rn(vx.x, vx.y);
            *(__half2*)&Xs[lr * HROW + lc + q * 4 + 2] = __floats2half2_rn(vx.z, vx.w);
        }
    }
    if (tid < 64) {
        dts[tid] = g_dt[(btbase + tid) * HN + h];
        Acs[tid] = g_a [(btbase + tid) * HN + h];
    }
    __syncthreads();
    if (warp == 0) {
        float a0 = Acs[2 * lane];
        float a1 = Acs[2 * lane + 1];
        float ps = a0 + a1;
        float sc = ps;
        #pragma unroll
        for (int o = 1; o < 32; o <<= 1) {
            float v = __shfl_up_sync(0xffffffffu, sc, o);
            if (lane >= o) sc += v;
        }
        const float excl = sc - ps;
        Acs[2 * lane]     = excl + a0;
        Acs[2 * lane + 1] = excl + a0 + a1;
    }
    __syncthreads();
    if (tid < 64) {
        cums[tid] = __expf(Acs[tid]);
        wss[tid]  = __expf(Acs[63] - Acs[tid]) * dts[tid];
        g_cp[(btbase + tid) * HN + h] = cums[tid];
    }
    __syncthreads();
    {
        const int lr = tid >> 2;
        const int lc = (tid & 3) << 4;
        const __half2 wh = __floats2half2_rn(wss[lr], wss[lr]);
        #pragma unroll
        for (int q = 0; q < 8; q++) {
            __half2 v = *(__half2*)&Bs[lr * HROW + lc + q * 2];
            *(__half2*)&Bws[lr * HROW + lc + q * 2] = __hmul2(v, wh);
        }
    }
    __syncthreads();

    const int m0t = wr * 32;
    const int n0s = wc * 16;

    float S[2][2][4];
    #pragma unroll
    for (int i = 0; i < 2; i++)
        #pragma unroll
        for (int j = 0; j < 2; j++)
            #pragma unroll
            for (int c = 0; c < 4; c++) S[i][j][c] = 0.f;
    bool live[2][2];
    #pragma unroll
    for (int mt = 0; mt < 2; mt++)
        #pragma unroll
        for (int nt = 0; nt < 2; nt++)
            live[mt][nt] = (n0s + nt * 8) <= (m0t + mt * 16 + 15);

    #pragma unroll
    for (int ks = 0; ks < 4; ks++) {
        unsigned a[2][4], bb[2][2];
        #pragma unroll
        for (int mt = 0; mt < 2; mt++)
            ldsm4(a[mt][0], a[mt][1], a[mt][2], a[mt][3],
                  addrA(uCs, m0t + mt * 16, ks, lane));
        ldsm4(bb[0][0], bb[0][1], bb[1][0], bb[1][1], addrB(uBs, n0s, ks, lane));
        #pragma unroll
        for (int mt = 0; mt < 2; mt++)
            #pragma unroll
            for (int nt = 0; nt < 2; nt++)
                if (live[mt][nt]) mma_f16(S[mt][nt], a[mt], bb[nt]);
    }
    #pragma unroll
    for (int mt = 0; mt < 2; mt++) {
        #pragma unroll
        for (int nt = 0; nt < 2; nt++) {
            const int s0 = n0s + nt * 8 + 2 * t4;
            #pragma unroll
            for (int half = 0; half < 2; half++) {
                const int t = m0t + mt * 16 + g + half * 8;
                float v0 = 0.f, v1 = 0.f;
                if (live[mt][nt]) {
                    const float m0v = (s0     <= t) ? __expf(Acs[t] - Acs[s0])     * dts[s0]     : 0.f;
                    const float m1v = (s0 + 1 <= t) ? __expf(Acs[t] - Acs[s0 + 1]) * dts[s0 + 1] : 0.f;
                    v0 = S[mt][nt][half * 2]     * m0v;
                    v1 = S[mt][nt][half * 2 + 1] * m1v;
                }
                *(__half2*)&Msm[t * HROW + s0] = __floats2half2_rn(v0, v1);
            }
        }
    }
    __syncthreads();

    float Y[2][2][4], Hh[2][2][4];
    #pragma unroll
    for (int i = 0; i < 2; i++)
        #pragma unroll
        for (int j = 0; j < 2; j++)
            #pragma unroll
            for (int c = 0; c < 4; c++) { Y[i][j][c] = 0.f; Hh[i][j][c] = 0.f; }

    #pragma unroll
    for (int ks = 0; ks < 4; ks++) {
        unsigned aM[2][4], aB[2][4], bX[2][2];
        #pragma unroll
        for (int mt = 0; mt < 2; mt++) {
            ldsm4 (aM[mt][0], aM[mt][1], aM[mt][2], aM[mt][3],
                   addrA (uMs,  m0t + mt * 16, ks, lane));
            ldsm4t(aB[mt][0], aB[mt][1], aB[mt][2], aB[mt][3],
                   addrAT(uBws, m0t + mt * 16, ks, lane));
        }
        ldsm4t(bX[0][0], bX[0][1], bX[1][0], bX[1][1], addrBT(uXs, n0s, ks, lane));
        #pragma unroll
        for (int mt = 0; mt < 2; mt++)
            #pragma unroll
            for (int nt = 0; nt < 2; nt++) {
                mma_f16(Y [mt][nt], aM[mt], bX[nt]);
                mma_f16(Hh[mt][nt], aB[mt], bX[nt]);
            }
    }
    const size_t hb = ((size_t)bh * NSEG + seg) * (DST * HP);
    #pragma unroll
    for (int mt = 0; mt < 2; mt++) {
        #pragma unroll
        for (int nt = 0; nt < 2; nt++) {
            const int p0 = n0s + nt * 8 + 2 * t4;
            #pragma unroll
            for (int half = 0; half < 2; half++) {
                const int tr = m0t + mt * 16 + g + half * 8;
                *(float2*)&g_y[(size_t)(btbase + tr) * DI + h * HP + p0] =
                    make_float2(Y[mt][nt][half * 2], Y[mt][nt][half * 2 + 1]);
                *(float2*)&g_hend[hb + (size_t)tr * HP + p0] =
                    make_float2(Hh[mt][nt][half * 2], Hh[mt][nt][half * 2 + 1]);
            }
        }
    }
}

__global__ __launch_bounds__(256)
void scan_combine_kernel()
{
    const int bh  = blockIdx.x;
    const int tid = threadIdx.x;
    const int b = bh >> 6, h = bh & 63;
    float4 st[4];
    #pragma unroll
    for (int q = 0; q < 4; q++) st[q] = make_float4(0.f, 0.f, 0.f, 0.f);
    const size_t base0 = (size_t)bh * NSEG * (DST * HP);
    for (int k = 0; k < NSEG; k++) {
        const size_t off = base0 + (size_t)k * (DST * HP) + (size_t)tid * 16;
        #pragma unroll
        for (int q = 0; q < 4; q++) *(float4*)&g_h0[off + q * 4] = st[q];
        const float Pend = __ldg(&g_cp[(b * L_ + k * TC + TC - 1) * HN + h]);
        #pragma unroll
        for (int q = 0; q < 4; q++) {
            float4 e = __ldg((const float4*)&g_hend[off + q * 4]);
            st[q].x = fmaf(st[q].x, Pend, e.x);
            st[q].y = fmaf(st[q].y, Pend, e.y);
            st[q].z = fmaf(st[q].z, Pend, e.z);
            st[q].w = fmaf(st[q].w, Pend, e.w);
        }
    }
}

__global__ __launch_bounds__(256)
void scan_fix_tc(const float* __restrict__ Dp)
{
    __shared__ __align__(16) __half Cs[TILE_H];
    __shared__ __align__(16) __half H0s[TILE_H];
    __shared__ float cumf[64];

    const uint32_t uCs = smem_u32(Cs);
    const uint32_t uH  = smem_u32(H0s);

    const int tid  = threadIdx.x;
    const int warp = tid >> 5;
    const int lane = tid & 31;
    const int wr = warp >> 2;
    const int wc = warp & 3;
    const int g  = lane >> 2;
    const int t4 = lane & 3;

    const int seg = blockIdx.x & (NSEG - 1);
    const int bh  = blockIdx.x >> 5;
    const int b = bh >> 6, h = bh & 63;
    const int btbase = b * L_ + seg * TC;

    {
        const int lr = tid >> 2;
        const int lc = (tid & 3) << 4;
        const float* gC = g_Cm + (size_t)(btbase + lr) * DST + lc;
        const size_t hb = ((size_t)bh * NSEG + seg) * (DST * HP);
        const float* gH = g_h0 + hb + (size_t)lr * HP + lc;
        #pragma unroll
        for (int q = 0; q < 4; q++) {
            float4 vc = *(const float4*)(gC + q * 4);
            float4 vh = *(const float4*)(gH + q * 4);
            *(__half2*)&Cs[lr * HROW + lc + q * 4]      = __floats2half2_rn(vc.x, vc.y);
            *(__half2*)&Cs[lr * HROW + lc + q * 4 + 2]  = __floats2half2_rn(vc.z, vc.w);
            *(__half2*)&H0s[lr * HROW + lc + q * 4]     = __floats2half2_rn(vh.x, vh.y);
            *(__half2*)&H0s[lr * HROW + lc + q * 4 + 2] = __floats2half2_rn(vh.z, vh.w);
        }
    }
    if (tid < 64) cumf[tid] = g_cp[(btbase + tid) * HN + h];
    __syncthreads();

    const int m0t = wr * 32;
    const int n0p = wc * 16;

    float acc[2][2][4];
    #pragma unroll
    for (int i = 0; i < 2; i++)
        #pragma unroll
        for (int j = 0; j < 2; j++)
            #pragma unroll
            for (int c = 0; c < 4; c++) acc[i][j][c] = 0.f;

    #pragma unroll
    for (int ks = 0; ks < 4; ks++) {
        unsigned a[2][4], bb[2][2];
        #pragma unroll
        for (int mt = 0; mt < 2; mt++)
            ldsm4(a[mt][0], a[mt][1], a[mt][2], a[mt][3],
                  addrA(uCs, m0t + mt * 16, ks, lane));
        ldsm4t(bb[0][0], bb[0][1], bb[1][0], bb[1][1], addrBT(uH, n0p, ks, lane));
        #pragma unroll
        for (int mt = 0; mt < 2; mt++)
            #pragma unroll
            for (int nt = 0; nt < 2; nt++)
                mma_f16(acc[mt][nt], a[mt], bb[nt]);
    }

    const float Dh = __ldg(Dp + h);
    #pragma unroll
    for (int mt = 0; mt < 2; mt++) {
        #pragma unroll
        for (int nt = 0; nt < 2; nt++) {
            const int p0 = n0p + nt * 8 + 2 * t4;
            #pragma unroll
            for (int half = 0; half < 2; half++) {
                const int tr = m0t + mt * 16 + g + half * 8;
                const int bt = btbase + tr;
                const size_t yoff = (size_t)bt * DI + h * HP + p0;
                float2 yl = *(float2*)&g_y[yoff];
                const float2 xv = *(const float2*)&g_xh[(size_t)bt * DI + h * HP + p0];
                const float2 zv = *(const float2*)&g_zx[(size_t)bt * DIP + h * HP + p0];
                const float cu = cumf[tr];
                const float y0 = (yl.x + cu * acc[mt][nt][half * 2]     + Dh * xv.x) * silu_fast(zv.x);
                const float y1 = (yl.y + cu * acc[mt][nt][half * 2 + 1] + Dh * xv.y) * silu_fast(zv.y);
                *(float2*)&g_y[yoff] = make_float2(y0, y1);
            }
        }
    }
}

__global__ __launch_bounds__(256)
void rmsnorm_cls_kernel(const float* __restrict__ norm_w,
                        const float* __restrict__ cls_b, float* __restrict__ out)
{
    const int bt = blockIdx.x;
    const float* row = g_y + (size_t)bt * DI;
    float v[16];
    float ss = 0.f;
    #pragma unroll
    for (int i = 0; i < 16; i++) {
        v[i] = row[threadIdx.x + i * 256];
        ss = fmaf(v[i], v[i], ss);
    }
    #pragma unroll
    for (int o = 16; o > 0; o >>= 1) ss += __shfl_xor_sync(0xffffffffu, ss, o);
    __shared__ float sred[8];
    const int lane = threadIdx.x & 31, warp = threadIdx.x >> 5;
    if (lane == 0) sred[warp] = ss;
    __syncthreads();
    float tot = 0.f;
    #pragma unroll
    for (int w = 0; w < 8; w++) tot += sred[w];
    const float scale = rsqrtf(tot * (1.f / DI) + 1e-5f);

    float a0 = 0.f, a1 = 0.f, a2 = 0.f, a3 = 0.f;
    #pragma unroll
    for (int i = 0; i < 16; i++) {
        const int c = threadIdx.x + i * 256;
        const float yn = v[i] * scale * __ldg(norm_w + c);
        a0 = fmaf(yn, __ldg(&g_M[c]),          a0);
        a1 = fmaf(yn, __ldg(&g_M[DI + c]),     a1);
        a2 = fmaf(yn, __ldg(&g_M[2 * DI + c]), a2);
        a3 = fmaf(yn, __ldg(&g_M[3 * DI + c]), a3);
    }
    #pragma unroll
    for (int o = 16; o > 0; o >>= 1) {
        a0 += __shfl_xor_sync(0xffffffffu, a0, o);
        a1 += __shfl_xor_sync(0xffffffffu, a1, o);
        a2 += __shfl_xor_sync(0xffffffffu, a2, o);
        a3 += __shfl_xor_sync(0xffffffffu, a3, o);
    }
    __shared__ float s4[8][4];
    if (lane == 0) { s4[warp][0] = a0; s4[warp][1] = a1; s4[warp][2] = a2; s4[warp][3] = a3; }
    __syncthreads();
    if (threadIdx.x < 4) {
        float s = __ldg(cls_b + threadIdx.x);
        #pragma unroll
        for (int w = 0; w < 8; w++) s += s4[w][threadIdx.x];
        out[bt * NCLS + threadIdx.x] = s;
    }
}

// ---------------- launcher: column-split gemm1 + two side streams ----------------
extern "C" void kernel_launch(void* const* d_in, const int* in_sizes, int n_in,
                              void* d_out, int out_size)
{
    (void)in_sizes; (void)n_in; (void)out_size;
    const float* x          = (const float*)d_in[0];
    const float* in_proj_w  = (const float*)d_in[1];
    const float* conv_w     = (const float*)d_in[2];
    const float* conv_b     = (const float*)d_in[3];
    const float* dt_bias    = (const float*)d_in[4];
    const float* A_log      = (const float*)d_in[5];
    const float* Dp         = (const float*)d_in[6];
    const float* norm_w     = (const float*)d_in[7];
    const float* out_proj_w = (const float*)d_in[8];
    const float* cls_w      = (const float*)d_in[9];
    const float* cls_b      = (const float*)d_in[10];
    float* out = (float*)d_out;

    float* zx;
    __half *x16, *w1h;
    cudaGetSymbolAddress((void**)&zx,  g_zx);
    cudaGetSymbolAddress((void**)&x16, g_x16);
    cudaGetSymbolAddress((void**)&w1h, g_w1h);

    // one-time setup on the uncaptured correctness call
    static cudaStream_t s_dt = nullptr, s_z = nullptr;
    static cudaEvent_t ev_fork = nullptr, ev_dt_done = nullptr;
    static cudaEvent_t ev_p1 = nullptr, ev_z_done = nullptr;
    static bool attrs_set = false;
    if (!s_dt) {
        cudaStreamCreateWithFlags(&s_dt, cudaStreamNonBlocking);
        cudaStreamCreateWithFlags(&s_z,  cudaStreamNonBlocking);
        cudaEventCreateWithFlags(&ev_fork,    cudaEventDisableTiming);
        cudaEventCreateWithFlags(&ev_dt_done, cudaEventDisableTiming);
        cudaEventCreateWithFlags(&ev_p1,      cudaEventDisableTiming);
        cudaEventCreateWithFlags(&ev_z_done,  cudaEventDisableTiming);
    }
    if (!attrs_set) {
        cudaFuncSetAttribute(gemm_h256, cudaFuncAttributeMaxDynamicSharedMemorySize, SMEM_BYTES);
        cudaFuncSetAttribute(seg_ssd_tc, cudaFuncAttributeMaxDynamicSharedMemorySize, SEG_SMEM);
        attrs_set = true;
    }

    // fork A: dt_exact + mbuild (fully independent)
    cudaEventRecord(ev_fork, 0);
    cudaStreamWaitEvent(s_dt, ev_fork, 0);
    dt_exact_kernel<<<BL / 64, 256, 0, s_dt>>>(x, in_proj_w, dt_bias, A_log);
    mbuild_kernel<<<DI / 256, 256, 0, s_dt>>>(out_proj_w, cls_w);
    cudaEventRecord(ev_dt_done, s_dt);

    // main chain: convert operands, then xBC-column GEMM slice
    cvt_f16_kernel<<<2048, 256>>>(x,         x16, BL * DM / 4);
    cvt_f16_kernel<<<2048, 256>>>(in_proj_w, w1h, DIP * DM / 4);
    {
        // gemm_p1: columns DI..DI+CONVD (xBC) -> feeds conv/seg immediately
        dim3 grid(CONVD / 128, BL / 256);
        gemm_h256<<<grid, 256, SMEM_BYTES>>>(x16, w1h + (size_t)DI * DM, zx + DI, BL, DM, DIP);
    }
    // fork B: z-column GEMM slice runs concurrent with conv/seg/combine
    cudaEventRecord(ev_p1, 0);
    cudaStreamWaitEvent(s_z, ev_p1, 0);
    {
        dim3 grid(DI / 128, BL / 256);
        gemm_h256<<<grid, 256, SMEM_BYTES, s_z>>>(x16, w1h, zx, BL, DM, DIP);
    }
    cudaEventRecord(ev_z_done, s_z);

    // main chain continues on xBC output
    conv_prep_kernel<<<BL, 256>>>(conv_w, conv_b);

    // join dt before seg (needs g_dt/g_a; also covers mbuild for rmsnorm)
    cudaStreamWaitEvent(0, ev_dt_done, 0);

    seg_ssd_tc<<<B_ * HN * NSEG, 256, SEG_SMEM>>>();
    scan_combine_kernel<<<B_ * HN, 256>>>();

    // join z-columns before fix (gate reads g_zx[:, 0..DI))
    cudaStreamWaitEvent(0, ev_z_done, 0);

    scan_fix_tc<<<B_ * HN * NSEG, 256>>>(Dp);
    rmsnorm_cls_kernel<<<BL, 256>>>(norm_w, cls_b, out);
}